// round 1
// baseline (speedup 1.0000x reference)
#include <cuda_runtime.h>
#include <math.h>

#define BATCH 256
#define NNODE 512
#define FDIM  128
#define HDIM  32
#define CDIM  16
#define KSEL1 256
#define KSEL2 128

// ---------------- scratch (device globals: no allocation allowed) ----------
__device__ float g_z1[BATCH * NNODE * HDIM];
__device__ float g_u1[BATCH * NNODE * HDIM];
__device__ float g_h1[BATCH * NNODE * HDIM];
__device__ float g_gate1[BATCH * NNODE];
__device__ int   g_idx1[BATCH * KSEL1];
__device__ float g_z2[BATCH * NNODE * HDIM];
__device__ float g_u2[BATCH * NNODE * HDIM];
__device__ float g_h2[BATCH * NNODE * HDIM];
__device__ float g_gate2[BATCH * NNODE];
__device__ int   g_idx2[BATCH * KSEL2];
__device__ float g_z3[BATCH * NNODE * HDIM];
__device__ float g_u3[BATCH * NNODE * HDIM];
__device__ float g_h3[BATCH * KSEL2 * HDIM];

// ---------------------------------------------------------------------------
// G1: z = x @ w1, u = x @ w2 + bias.  x:[B*N, 128], w:[128,32] each.
// Block: 256 threads, 64-row tile, N=64 combined output (z | u).
// ---------------------------------------------------------------------------
__global__ __launch_bounds__(256) void k_xw(
    const float* __restrict__ x, const float* __restrict__ w1,
    const float* __restrict__ w2, const float* __restrict__ bias,
    float* __restrict__ zout, float* __restrict__ uout)
{
    __shared__ float ws[FDIM][68];   // cols 0..31 = w1, 32..63 = w2
    __shared__ float xt[64][36];
    const int tid = threadIdx.x;
    const int m0  = blockIdx.x * 64;

    // load both weight matrices (128x32 each = 1024 float4 each)
#pragma unroll
    for (int i = 0; i < 4; i++) {
        int e  = tid + 256 * i;          // 0..1023
        int k  = e >> 3, c4 = e & 7;
        *(float4*)&ws[k][c4 * 4]      = *(const float4*)&w1[k * HDIM + c4 * 4];
        *(float4*)&ws[k][32 + c4 * 4] = *(const float4*)&w2[k * HDIM + c4 * 4];
    }

    float acc[4][4];
#pragma unroll
    for (int i = 0; i < 4; i++)
#pragma unroll
        for (int j = 0; j < 4; j++) acc[i][j] = 0.f;

    const int tx = tid & 15, ty = tid >> 4;   // 16 x 16 thread grid, 4x4 tiles

    for (int k0 = 0; k0 < FDIM; k0 += 32) {
        __syncthreads();
#pragma unroll
        for (int i = 0; i < 2; i++) {
            int e = tid + 256 * i;           // 512 float4 (64 rows x 8)
            int r = e >> 3, c4 = e & 7;
            *(float4*)&xt[r][c4 * 4] =
                *(const float4*)&x[(size_t)(m0 + r) * FDIM + k0 + c4 * 4];
        }
        __syncthreads();
#pragma unroll
        for (int kk = 0; kk < 32; kk++) {
            float4 wv = *(float4*)&ws[k0 + kk][tx * 4];
#pragma unroll
            for (int i = 0; i < 4; i++) {
                float xv = xt[ty * 4 + i][kk];
                acc[i][0] += xv * wv.x; acc[i][1] += xv * wv.y;
                acc[i][2] += xv * wv.z; acc[i][3] += xv * wv.w;
            }
        }
    }

    if (tx < 8) {
#pragma unroll
        for (int i = 0; i < 4; i++) {
            int gr = m0 + ty * 4 + i;
            *(float4*)&zout[(size_t)gr * HDIM + tx * 4] =
                make_float4(acc[i][0], acc[i][1], acc[i][2], acc[i][3]);
        }
    } else {
        int c0 = tx * 4 - 32;
        float4 bv = *(const float4*)&bias[c0];
#pragma unroll
        for (int i = 0; i < 4; i++) {
            int gr = m0 + ty * 4 + i;
            *(float4*)&uout[(size_t)gr * HDIM + c0] =
                make_float4(acc[i][0] + bv.x, acc[i][1] + bv.y,
                            acc[i][2] + bv.z, acc[i][3] + bv.w);
        }
    }
}

// ---------------------------------------------------------------------------
// G3/G5: z = (gate*h) @ w1, u = (gate*h) @ w2 + bias.  h:[B*N,32].
// ---------------------------------------------------------------------------
__global__ __launch_bounds__(256) void k_gxw(
    const float* __restrict__ hfeat, const float* __restrict__ gate,
    const float* __restrict__ w1, const float* __restrict__ w2,
    const float* __restrict__ bias,
    float* __restrict__ zout, float* __restrict__ uout)
{
    __shared__ float ws[HDIM][68];
    __shared__ float xt[64][36];
    const int tid = threadIdx.x;
    const int m0  = blockIdx.x * 64;

    {   // 32x32 weights: 256 float4 each — one per thread
        int k = tid >> 3, c4 = tid & 7;
        *(float4*)&ws[k][c4 * 4]      = *(const float4*)&w1[k * HDIM + c4 * 4];
        *(float4*)&ws[k][32 + c4 * 4] = *(const float4*)&w2[k * HDIM + c4 * 4];
    }
#pragma unroll
    for (int i = 0; i < 2; i++) {
        int e = tid + 256 * i;
        int r = e >> 3, c4 = e & 7;
        int gr = m0 + r;
        float g = gate[gr];
        float4 v = *(const float4*)&hfeat[(size_t)gr * HDIM + c4 * 4];
        v.x *= g; v.y *= g; v.z *= g; v.w *= g;
        *(float4*)&xt[r][c4 * 4] = v;
    }
    __syncthreads();

    float acc[4][4];
#pragma unroll
    for (int i = 0; i < 4; i++)
#pragma unroll
        for (int j = 0; j < 4; j++) acc[i][j] = 0.f;

    const int tx = tid & 15, ty = tid >> 4;
#pragma unroll
    for (int kk = 0; kk < HDIM; kk++) {
        float4 wv = *(float4*)&ws[kk][tx * 4];
#pragma unroll
        for (int i = 0; i < 4; i++) {
            float xv = xt[ty * 4 + i][kk];
            acc[i][0] += xv * wv.x; acc[i][1] += xv * wv.y;
            acc[i][2] += xv * wv.z; acc[i][3] += xv * wv.w;
        }
    }

    if (tx < 8) {
#pragma unroll
        for (int i = 0; i < 4; i++) {
            int gr = m0 + ty * 4 + i;
            *(float4*)&zout[(size_t)gr * HDIM + tx * 4] =
                make_float4(acc[i][0], acc[i][1], acc[i][2], acc[i][3]);
        }
    } else {
        int c0 = tx * 4 - 32;
        float4 bv = *(const float4*)&bias[c0];
#pragma unroll
        for (int i = 0; i < 4; i++) {
            int gr = m0 + ty * 4 + i;
            *(float4*)&uout[(size_t)gr * HDIM + c0] =
                make_float4(acc[i][0] + bv.x, acc[i][1] + bv.y,
                            acc[i][2] + bv.z, acc[i][3] + bv.w);
        }
    }
}

// ---------------------------------------------------------------------------
// G2/G4/G6: out[rows] = relu( a[b, gidx(row), :] @ zfull[b] + u[b, gidx(row)] )
// zfull is full-N layout (zeros at dropped nodes). ridx==nullptr -> identity.
// out_compact: write at (b, m0+local) instead of (b, gidx).
// ---------------------------------------------------------------------------
__global__ __launch_bounds__(256) void k_aZ(
    const float* __restrict__ a, const float* __restrict__ z,
    const float* __restrict__ u, float* __restrict__ out,
    const int* __restrict__ ridx, int rows_out, int out_compact)
{
    __shared__ float at[128][36];
    __shared__ float zt[32][36];
    __shared__ int gidx[128];
    const int tid = threadIdx.x;
    const int b   = blockIdx.y;
    const int m0  = blockIdx.x * 128;

    if (tid < 128)
        gidx[tid] = ridx ? ridx[b * rows_out + m0 + tid] : (m0 + tid);
    __syncthreads();

    const float* ab = a + (size_t)b * NNODE * NNODE;
    const float* zb = z + (size_t)b * NNODE * HDIM;

    float acc[4][4];
#pragma unroll
    for (int i = 0; i < 4; i++)
#pragma unroll
        for (int j = 0; j < 4; j++) acc[i][j] = 0.f;

    const int tx = tid & 7, ty = tid >> 3;   // 8 x 32 thread grid, 4x4 tiles

    for (int k0 = 0; k0 < NNODE; k0 += 32) {
        __syncthreads();
        {   // z tile: 32x32 = 256 float4, one per thread
            int kk = tid >> 3, c4 = tid & 7;
            *(float4*)&zt[kk][c4 * 4] =
                *(const float4*)&zb[(size_t)(k0 + kk) * HDIM + c4 * 4];
        }
#pragma unroll
        for (int i = 0; i < 4; i++) {        // a tile: 128 rows x 8 float4
            int e = tid + 256 * i;
            int r = e >> 3, c4 = e & 7;
            *(float4*)&at[r][c4 * 4] =
                *(const float4*)&ab[(size_t)gidx[r] * NNODE + k0 + c4 * 4];
        }
        __syncthreads();
#pragma unroll
        for (int kk = 0; kk < 32; kk++) {
            float4 zv = *(float4*)&zt[kk][tx * 4];
#pragma unroll
            for (int i = 0; i < 4; i++) {
                float av = at[ty * 4 + i][kk];
                acc[i][0] += av * zv.x; acc[i][1] += av * zv.y;
                acc[i][2] += av * zv.z; acc[i][3] += av * zv.w;
            }
        }
    }

#pragma unroll
    for (int i = 0; i < 4; i++) {
        int lr = ty * 4 + i;
        int gm = gidx[lr];
        float4 uv = *(const float4*)&u[((size_t)b * NNODE + gm) * HDIM + tx * 4];
        float4 r4;
        r4.x = fmaxf(acc[i][0] + uv.x, 0.f);
        r4.y = fmaxf(acc[i][1] + uv.y, 0.f);
        r4.z = fmaxf(acc[i][2] + uv.z, 0.f);
        r4.w = fmaxf(acc[i][3] + uv.w, 0.f);
        size_t o = out_compact
                 ? ((size_t)b * rows_out + m0 + lr) * HDIM + tx * 4
                 : ((size_t)b * NNODE + gm) * HDIM + tx * 4;
        *(float4*)&out[o] = r4;
    }
}

// ---------------------------------------------------------------------------
// TopK: scores y = h @ p/||p||; exact jax.lax.top_k set semantics via ranks.
// Outputs: full-layout gate (sigmoid(y) if selected else 0) + index list
// (deterministic, prefix-compacted; order is irrelevant downstream).
// ---------------------------------------------------------------------------
__global__ __launch_bounds__(256) void k_topk(
    const float* __restrict__ hfeat, const float* __restrict__ p,
    const float* __restrict__ prevgate, float* __restrict__ gate_out,
    int* __restrict__ idx_out, int k)
{
    __shared__ float ysh[NNODE];
    __shared__ float pn[HDIM];
    __shared__ int sflag[NNODE];
    const int tid = threadIdx.x;
    const int b   = blockIdx.x;

    if (tid == 0) {
        float s = 0.f;
        for (int h = 0; h < HDIM; h++) s += p[h] * p[h];
        s = rsqrtf(s);
        for (int h = 0; h < HDIM; h++) pn[h] = p[h] * s;
    }
    __syncthreads();

    const int lane = tid & 31, w = tid >> 5;
    for (int r = w; r < NNODE; r += 8) {
        float v = hfeat[((size_t)b * NNODE + r) * HDIM + lane] * pn[lane];
#pragma unroll
        for (int s = 16; s > 0; s >>= 1) v += __shfl_xor_sync(0xffffffffu, v, s);
        if (lane == 0) {
            bool valid = (prevgate == nullptr) ||
                         (prevgate[(size_t)b * NNODE + r] > 0.f);
            ysh[r] = valid ? v : -1e30f;
        }
    }
    __syncthreads();

    for (int r = tid; r < NNODE; r += 256) {
        float yv = ysh[r];
        int rank = 0;
        for (int j = 0; j < NNODE; j++) {
            float yj = ysh[j];
            rank += (yj > yv) || (yj == yv && j < r);
        }
        int sel = (rank < k) ? 1 : 0;
        sflag[r] = sel;
        gate_out[(size_t)b * NNODE + r] =
            sel ? (1.f / (1.f + expf(-yv))) : 0.f;
    }
    __syncthreads();

    for (int r = tid; r < NNODE; r += 256) {
        if (sflag[r]) {
            int pos = 0;
            for (int j = 0; j < r; j++) pos += sflag[j];
            idx_out[b * k + pos] = r;
        }
    }
}

// ---------------------------------------------------------------------------
// Final: mean over 128 nodes -> dense [32,16] + bias -> softmax(16).
// ---------------------------------------------------------------------------
__global__ __launch_bounds__(128) void k_final(
    const float* __restrict__ h3, const float* __restrict__ wd,
    const float* __restrict__ bd, float* __restrict__ out)
{
    __shared__ float ps[4][HDIM];
    __shared__ float pooled[HDIM];
    __shared__ float logits[CDIM];
    const int tid = threadIdx.x;
    const int b   = blockIdx.x;
    const int c = tid & 31, seg = tid >> 5;

    float s = 0.f;
    for (int i = seg * 32; i < seg * 32 + 32; i++)
        s += h3[((size_t)b * KSEL2 + i) * HDIM + c];
    ps[seg][c] = s;
    __syncthreads();
    if (tid < HDIM)
        pooled[tid] = (ps[0][tid] + ps[1][tid] + ps[2][tid] + ps[3][tid]) *
                      (1.f / (float)KSEL2);
    __syncthreads();
    if (tid < CDIM) {
        float l = bd[tid];
        for (int h = 0; h < HDIM; h++) l += pooled[h] * wd[h * CDIM + tid];
        logits[tid] = l;
    }
    __syncthreads();
    if (tid < CDIM) {
        float mx = -1e30f;
        for (int j = 0; j < CDIM; j++) mx = fmaxf(mx, logits[j]);
        float den = 0.f;
        for (int j = 0; j < CDIM; j++) den += expf(logits[j] - mx);
        out[b * CDIM + tid] = expf(logits[tid] - mx) / den;
    }
}

// ---------------------------------------------------------------------------
extern "C" void kernel_launch(void* const* d_in, const int* in_sizes, int n_in,
                              void* d_out, int out_size)
{
    (void)in_sizes; (void)n_in; (void)out_size;
    const float* x    = (const float*)d_in[0];
    const float* a    = (const float*)d_in[1];
    const float* w1_1 = (const float*)d_in[2];
    const float* w2_1 = (const float*)d_in[3];
    const float* b1   = (const float*)d_in[4];
    const float* w1_2 = (const float*)d_in[5];
    const float* w2_2 = (const float*)d_in[6];
    const float* b2   = (const float*)d_in[7];
    const float* w1_3 = (const float*)d_in[8];
    const float* w2_3 = (const float*)d_in[9];
    const float* b3   = (const float*)d_in[10];
    const float* pp   = (const float*)d_in[11];
    const float* wd   = (const float*)d_in[12];
    const float* bd   = (const float*)d_in[13];
    float* out = (float*)d_out;

    float *z1, *u1, *h1, *gate1, *z2, *u2, *h2, *gate2, *z3, *u3, *h3;
    int *idx1, *idx2;
    cudaGetSymbolAddress((void**)&z1, g_z1);
    cudaGetSymbolAddress((void**)&u1, g_u1);
    cudaGetSymbolAddress((void**)&h1, g_h1);
    cudaGetSymbolAddress((void**)&gate1, g_gate1);
    cudaGetSymbolAddress((void**)&idx1, g_idx1);
    cudaGetSymbolAddress((void**)&z2, g_z2);
    cudaGetSymbolAddress((void**)&u2, g_u2);
    cudaGetSymbolAddress((void**)&h2, g_h2);
    cudaGetSymbolAddress((void**)&gate2, g_gate2);
    cudaGetSymbolAddress((void**)&idx2, g_idx2);
    cudaGetSymbolAddress((void**)&z3, g_z3);
    cudaGetSymbolAddress((void**)&u3, g_u3);
    cudaGetSymbolAddress((void**)&h3, g_h3);

    // conv1
    k_xw<<<(BATCH * NNODE) / 64, 256>>>(x, w1_1, w2_1, b1, z1, u1);
    k_aZ<<<dim3(NNODE / 128, BATCH), 256>>>(a, z1, u1, h1, nullptr, NNODE, 0);
    // pool1
    k_topk<<<BATCH, 256>>>(h1, pp, nullptr, gate1, idx1, KSEL1);
    // conv2 (scatter-z / gather-rows trick; z2 is zero at dropped nodes
    // because gate1 is zero there)
    k_gxw<<<(BATCH * NNODE) / 64, 256>>>(h1, gate1, w1_2, w2_2, b2, z2, u2);
    k_aZ<<<dim3(KSEL1 / 128, BATCH), 256>>>(a, z2, u2, h2, idx1, KSEL1, 0);
    // pool2 (valid = survivors of pool1)
    k_topk<<<BATCH, 256>>>(h2, pp, gate1, gate2, idx2, KSEL2);
    // conv3
    k_gxw<<<(BATCH * NNODE) / 64, 256>>>(h2, gate2, w1_3, w2_3, b3, z3, u3);
    k_aZ<<<dim3(KSEL2 / 128, BATCH), 256>>>(a, z3, u3, h3, idx2, KSEL2, 1);
    // global mean pool + dense + softmax
    k_final<<<BATCH, 128>>>(h3, wd, bd, out);
}

// round 4
// speedup vs baseline: 1.0439x; 1.0439x over previous
#include <cuda_runtime.h>
#include <cuda_bf16.h>
#include <math.h>
#include <stdint.h>

#define BATCH 256
#define NNODE 512
#define FDIM  128
#define HDIM  32
#define CDIM  16
#define KSEL1 256
#define KSEL2 128

// ---------------- scratch (device globals: no allocation allowed) ----------
__device__ __nv_bfloat16 g_zhi[BATCH * HDIM * NNODE];  // z^T split-hi [B][32][512]
__device__ __nv_bfloat16 g_zlo[BATCH * HDIM * NNODE];  // z^T split-lo
__device__ float g_u1[BATCH * NNODE * HDIM];
__device__ float g_u2[BATCH * NNODE * HDIM];
__device__ float g_u3[BATCH * NNODE * HDIM];
__device__ float g_h1[BATCH * NNODE * HDIM];
__device__ float g_h2[BATCH * NNODE * HDIM];
__device__ float g_h3[BATCH * KSEL2 * HDIM];
__device__ float g_gate1[BATCH * NNODE];
__device__ float g_gate2[BATCH * NNODE];
__device__ int   g_idx1[BATCH * KSEL1];
__device__ int   g_idx2[BATCH * KSEL2];

// ======================= warp-MMA helpers (generic PTX) =====================
__device__ __forceinline__ uint32_t smem_u32(const void* p) {
    uint32_t a;
    asm("{ .reg .u64 t; cvta.to.shared.u64 t, %1; cvt.u32.u64 %0, t; }"
        : "=r"(a) : "l"(p));
    return a;
}
__device__ __forceinline__ void ldsm4(uint32_t* r, uint32_t addr) {
    asm volatile(
        "ldmatrix.sync.aligned.m8n8.x4.shared.b16 {%0,%1,%2,%3}, [%4];"
        : "=r"(r[0]), "=r"(r[1]), "=r"(r[2]), "=r"(r[3]) : "r"(addr));
}
__device__ __forceinline__ void mma16816(float* c, const uint32_t* a,
                                         uint32_t b0, uint32_t b1) {
    asm volatile(
        "mma.sync.aligned.m16n8k16.row.col.f32.bf16.bf16.f32 "
        "{%0,%1,%2,%3}, {%4,%5,%6,%7}, {%8,%9}, {%0,%1,%2,%3};"
        : "+f"(c[0]), "+f"(c[1]), "+f"(c[2]), "+f"(c[3])
        : "r"(a[0]), "r"(a[1]), "r"(a[2]), "r"(a[3]), "r"(b0), "r"(b1));
}
// split fp32 -> bf16 hi/lo
__device__ __forceinline__ void bf16_split(float v, unsigned short& h,
                                           unsigned short& l) {
    __nv_bfloat16 hb = __float2bfloat16(v);
    float hf = __bfloat162float(hb);
    __nv_bfloat16 lb = __float2bfloat16(v - hf);
    h = *(unsigned short*)&hb;
    l = *(unsigned short*)&lb;
}

// ---------------------------------------------------------------------------
// G1: zT_hi/lo = split(x @ w1)^T, u = x @ w2 + bias.  x:[B*N,128].
// ---------------------------------------------------------------------------
__global__ __launch_bounds__(256) void k_xw(
    const float* __restrict__ x, const float* __restrict__ w1,
    const float* __restrict__ w2, const float* __restrict__ bias,
    __nv_bfloat16* __restrict__ zhi, __nv_bfloat16* __restrict__ zlo,
    float* __restrict__ uout)
{
    __shared__ float ws[FDIM][68];
    __shared__ float xt[64][36];
    const int tid = threadIdx.x;
    const int m0  = blockIdx.x * 64;

#pragma unroll
    for (int i = 0; i < 4; i++) {
        int e = tid + 256 * i;
        int k = e >> 3, c4 = e & 7;
        *(float4*)&ws[k][c4 * 4]      = *(const float4*)&w1[k * HDIM + c4 * 4];
        *(float4*)&ws[k][32 + c4 * 4] = *(const float4*)&w2[k * HDIM + c4 * 4];
    }

    float acc[4][4];
#pragma unroll
    for (int i = 0; i < 4; i++)
#pragma unroll
        for (int j = 0; j < 4; j++) acc[i][j] = 0.f;

    const int tx = tid & 15, ty = tid >> 4;

    for (int k0 = 0; k0 < FDIM; k0 += 32) {
        __syncthreads();
#pragma unroll
        for (int i = 0; i < 2; i++) {
            int e = tid + 256 * i;
            int r = e >> 3, c4 = e & 7;
            *(float4*)&xt[r][c4 * 4] =
                *(const float4*)&x[(size_t)(m0 + r) * FDIM + k0 + c4 * 4];
        }
        __syncthreads();
#pragma unroll
        for (int kk = 0; kk < 32; kk++) {
            float4 wv = *(float4*)&ws[k0 + kk][tx * 4];
#pragma unroll
            for (int i = 0; i < 4; i++) {
                float xv = xt[ty * 4 + i][kk];
                acc[i][0] += xv * wv.x; acc[i][1] += xv * wv.y;
                acc[i][2] += xv * wv.z; acc[i][3] += xv * wv.w;
            }
        }
    }

    if (tx < 8) {   // z half -> transposed split-bf16 store
        int gr0 = m0 + ty * 4;
        int b_  = gr0 >> 9;
        int r0  = gr0 & (NNODE - 1);
#pragma unroll
        for (int j = 0; j < 4; j++) {
            int col = tx * 4 + j;
            unsigned short hp[4], lp[4];
#pragma unroll
            for (int i = 0; i < 4; i++) bf16_split(acc[i][j], hp[i], lp[i]);
            size_t base = ((size_t)(b_ * HDIM + col)) * NNODE + r0;
            *(uint2*)&zhi[base] = *(uint2*)hp;
            *(uint2*)&zlo[base] = *(uint2*)lp;
        }
    } else {        // u half
        int c0 = tx * 4 - 32;
        float4 bv = *(const float4*)&bias[c0];
#pragma unroll
        for (int i = 0; i < 4; i++) {
            int gr = m0 + ty * 4 + i;
            *(float4*)&uout[(size_t)gr * HDIM + c0] =
                make_float4(acc[i][0] + bv.x, acc[i][1] + bv.y,
                            acc[i][2] + bv.z, acc[i][3] + bv.w);
        }
    }
}

// ---------------------------------------------------------------------------
// G3/G5: same but input is gate*h, h:[B*N,32].
// ---------------------------------------------------------------------------
__global__ __launch_bounds__(256) void k_gxw(
    const float* __restrict__ hfeat, const float* __restrict__ gate,
    const float* __restrict__ w1, const float* __restrict__ w2,
    const float* __restrict__ bias,
    __nv_bfloat16* __restrict__ zhi, __nv_bfloat16* __restrict__ zlo,
    float* __restrict__ uout)
{
    __shared__ float ws[HDIM][68];
    __shared__ float xt[64][36];
    const int tid = threadIdx.x;
    const int m0  = blockIdx.x * 64;

    {
        int k = tid >> 3, c4 = tid & 7;
        *(float4*)&ws[k][c4 * 4]      = *(const float4*)&w1[k * HDIM + c4 * 4];
        *(float4*)&ws[k][32 + c4 * 4] = *(const float4*)&w2[k * HDIM + c4 * 4];
    }
#pragma unroll
    for (int i = 0; i < 2; i++) {
        int e = tid + 256 * i;
        int r = e >> 3, c4 = e & 7;
        int gr = m0 + r;
        float g = gate[gr];
        float4 v = *(const float4*)&hfeat[(size_t)gr * HDIM + c4 * 4];
        v.x *= g; v.y *= g; v.z *= g; v.w *= g;
        *(float4*)&xt[r][c4 * 4] = v;
    }
    __syncthreads();

    float acc[4][4];
#pragma unroll
    for (int i = 0; i < 4; i++)
#pragma unroll
        for (int j = 0; j < 4; j++) acc[i][j] = 0.f;

    const int tx = tid & 15, ty = tid >> 4;
#pragma unroll
    for (int kk = 0; kk < HDIM; kk++) {
        float4 wv = *(float4*)&ws[kk][tx * 4];
#pragma unroll
        for (int i = 0; i < 4; i++) {
            float xv = xt[ty * 4 + i][kk];
            acc[i][0] += xv * wv.x; acc[i][1] += xv * wv.y;
            acc[i][2] += xv * wv.z; acc[i][3] += xv * wv.w;
        }
    }

    if (tx < 8) {
        int gr0 = m0 + ty * 4;
        int b_  = gr0 >> 9;
        int r0  = gr0 & (NNODE - 1);
#pragma unroll
        for (int j = 0; j < 4; j++) {
            int col = tx * 4 + j;
            unsigned short hp[4], lp[4];
#pragma unroll
            for (int i = 0; i < 4; i++) bf16_split(acc[i][j], hp[i], lp[i]);
            size_t base = ((size_t)(b_ * HDIM + col)) * NNODE + r0;
            *(uint2*)&zhi[base] = *(uint2*)hp;
            *(uint2*)&zlo[base] = *(uint2*)lp;
        }
    } else {
        int c0 = tx * 4 - 32;
        float4 bv = *(const float4*)&bias[c0];
#pragma unroll
        for (int i = 0; i < 4; i++) {
            int gr = m0 + ty * 4 + i;
            *(float4*)&uout[(size_t)gr * HDIM + c0] =
                make_float4(acc[i][0] + bv.x, acc[i][1] + bv.y,
                            acc[i][2] + bv.z, acc[i][3] + bv.w);
        }
    }
}

// ---------------------------------------------------------------------------
// HMMA a@z: out[rows] = relu( a[b,gidx(row),:] @ z[b] + u[b,gidx(row)] )
// Split-bf16 compensated: D = Ah*Bh + Ah*Bl + Al*Bh (fp32 accum).
// 256 threads = 8 warps; warp w owns rows [w*16, w*16+16) x 32 cols.
// K chunked at 64. a converted fp32->bf16 hi/lo on the fly.
// ---------------------------------------------------------------------------
#define ASTR 72   // smem row stride in bf16 (144B = 9*16B: ldmatrix conflict-free)

__global__ __launch_bounds__(256) void k_aZ_mma(
    const float* __restrict__ a, const __nv_bfloat16* __restrict__ zhi,
    const __nv_bfloat16* __restrict__ zlo, const float* __restrict__ u,
    float* __restrict__ out, const int* __restrict__ ridx,
    int rows_out, int out_compact)
{
    __shared__ __nv_bfloat16 sAh[128][ASTR];
    __shared__ __nv_bfloat16 sAl[128][ASTR];
    __shared__ __nv_bfloat16 sZh[32][ASTR];
    __shared__ __nv_bfloat16 sZl[32][ASTR];
    __shared__ int gidx[128];

    const int tid = threadIdx.x, wid = tid >> 5, lane = tid & 31;
    const int b  = blockIdx.y;
    const int m0 = blockIdx.x * 128;

    if (tid < 128)
        gidx[tid] = ridx ? ridx[b * rows_out + m0 + tid] : (m0 + tid);
    __syncthreads();

    const float* ab = a + (size_t)b * NNODE * NNODE;
    const __nv_bfloat16* zhb = zhi + (size_t)b * HDIM * NNODE;
    const __nv_bfloat16* zlb = zlo + (size_t)b * HDIM * NNODE;

    float acc[4][4];
#pragma unroll
    for (int i = 0; i < 4; i++)
#pragma unroll
        for (int j = 0; j < 4; j++) acc[i][j] = 0.f;

    // ldmatrix per-lane base addresses
    const int g8 = lane >> 3, r8 = lane & 7;
    // A x4 groups: g0=(r,klo)->a0, g1=(r+8,klo)->a1, g2=(r,khi)->a2, g3=(r+8,khi)->a3
    const int a_row = wid * 16 + ((g8 & 1) ? 8 : 0) + r8;
    const int a_col = (g8 >= 2) ? 8 : 0;
    const uint32_t ah_base = smem_u32(&sAh[a_row][a_col]);
    const uint32_t al_base = smem_u32(&sAl[a_row][a_col]);
    // B x4 groups (per call, n-base nb): g0=(nb+r,klo), g1=(nb+r,khi),
    //   g2=(nb+8+r,klo), g3=(nb+8+r,khi) -> regs {b0_t0,b1_t0,b0_t1,b1_t1}
    const int b_rowoff = ((g8 >> 1) ? 8 : 0) + r8;
    const int b_col    = (g8 & 1) ? 8 : 0;
    const uint32_t bh0_base = smem_u32(&sZh[b_rowoff][b_col]);
    const uint32_t bh1_base = smem_u32(&sZh[16 + b_rowoff][b_col]);
    const uint32_t bl0_base = smem_u32(&sZl[b_rowoff][b_col]);
    const uint32_t bl1_base = smem_u32(&sZl[16 + b_rowoff][b_col]);

    for (int ch = 0; ch < 8; ch++) {
        const int k0 = ch * 64;
        __syncthreads();
        // ---- A chunk: 128 rows x 64 cols fp32 -> bf16 hi/lo ----
#pragma unroll
        for (int t = 0; t < 8; t++) {
            int e = tid + 256 * t;            // 2048 float4 units
            int row = e >> 4, c4 = (e & 15) * 4;
            float4 v = *(const float4*)&ab[(size_t)gidx[row] * NNODE + k0 + c4];
            unsigned short hp[4], lp[4];
            bf16_split(v.x, hp[0], lp[0]); bf16_split(v.y, hp[1], lp[1]);
            bf16_split(v.z, hp[2], lp[2]); bf16_split(v.w, hp[3], lp[3]);
            *(uint2*)&sAh[row][c4] = *(uint2*)hp;
            *(uint2*)&sAl[row][c4] = *(uint2*)lp;
        }
        // ---- z chunk: zT 32 rows x 64 bf16, straight copy ----
        {
            int row = tid >> 3, c8 = (tid & 7) * 8;
            *(uint4*)&sZh[row][c8] =
                *(const uint4*)&zhb[(size_t)row * NNODE + k0 + c8];
            *(uint4*)&sZl[row][c8] =
                *(const uint4*)&zlb[(size_t)row * NNODE + k0 + c8];
        }
        __syncthreads();

#pragma unroll
        for (int ks = 0; ks < 4; ks++) {
            const uint32_t koff = ks * 32;     // 16 bf16 = 32 bytes
            uint32_t ah[4], al[4], bh[8], bl[8];
            ldsm4(ah, ah_base + koff);
            ldsm4(al, al_base + koff);
            ldsm4(bh,     bh0_base + koff);
            ldsm4(bh + 4, bh1_base + koff);
            ldsm4(bl,     bl0_base + koff);
            ldsm4(bl + 4, bl1_base + koff);
#pragma unroll
            for (int nt = 0; nt < 4; nt++) {
                mma16816(acc[nt], ah, bh[nt * 2], bh[nt * 2 + 1]);
                mma16816(acc[nt], ah, bl[nt * 2], bl[nt * 2 + 1]);
                mma16816(acc[nt], al, bh[nt * 2], bh[nt * 2 + 1]);
            }
        }
    }

    // ---- epilogue: D frag (g,t2),(g,t2+1),(g+8,t2),(g+8,t2+1) ----
    const int g  = lane >> 2, t2 = (lane & 3) * 2;
    const int lr0 = wid * 16 + g, lr1 = lr0 + 8;
    const int gm0 = gidx[lr0], gm1 = gidx[lr1];
    const float* u0 = &u[((size_t)b * NNODE + gm0) * HDIM];
    const float* u1 = &u[((size_t)b * NNODE + gm1) * HDIM];
    float* o0 = out + (out_compact
               ? ((size_t)b * rows_out + m0 + lr0) * HDIM
               : ((size_t)b * NNODE + gm0) * HDIM);
    float* o1 = out + (out_compact
               ? ((size_t)b * rows_out + m0 + lr1) * HDIM
               : ((size_t)b * NNODE + gm1) * HDIM);
#pragma unroll
    for (int nt = 0; nt < 4; nt++) {
        int c = nt * 8 + t2;
        float2 uv0 = *(const float2*)&u0[c];
        float2 uv1 = *(const float2*)&u1[c];
        float2 r0, r1;
        r0.x = fmaxf(acc[nt][0] + uv0.x, 0.f);
        r0.y = fmaxf(acc[nt][1] + uv0.y, 0.f);
        r1.x = fmaxf(acc[nt][2] + uv1.x, 0.f);
        r1.y = fmaxf(acc[nt][3] + uv1.y, 0.f);
        *(float2*)&o0[c] = r0;
        *(float2*)&o1[c] = r1;
    }
}

// ---------------------------------------------------------------------------
// TopK: exact jax.lax.top_k set semantics via rank counting.
// ---------------------------------------------------------------------------
__global__ __launch_bounds__(256) void k_topk(
    const float* __restrict__ hfeat, const float* __restrict__ p,
    const float* __restrict__ prevgate, float* __restrict__ gate_out,
    int* __restrict__ idx_out, int k)
{
    __shared__ float ysh[NNODE];
    __shared__ float pn[HDIM];
    __shared__ int sflag[NNODE];
    const int tid = threadIdx.x;
    const int b   = blockIdx.x;

    if (tid == 0) {
        float s = 0.f;
        for (int h = 0; h < HDIM; h++) s += p[h] * p[h];
        s = rsqrtf(s);
        for (int h = 0; h < HDIM; h++) pn[h] = p[h] * s;
    }
    __syncthreads();

    const int lane = tid & 31, w = tid >> 5;
    for (int r = w; r < NNODE; r += 8) {
        float v = hfeat[((size_t)b * NNODE + r) * HDIM + lane] * pn[lane];
#pragma unroll
        for (int s = 16; s > 0; s >>= 1) v += __shfl_xor_sync(0xffffffffu, v, s);
        if (lane == 0) {
            bool valid = (prevgate == nullptr) ||
                         (prevgate[(size_t)b * NNODE + r] > 0.f);
            ysh[r] = valid ? v : -1e30f;
        }
    }
    __syncthreads();

    for (int r = tid; r < NNODE; r += 256) {
        float yv = ysh[r];
        int rank = 0;
        for (int j = 0; j < NNODE; j++) {
            float yj = ysh[j];
            rank += (yj > yv) || (yj == yv && j < r);
        }
        int sel = (rank < k) ? 1 : 0;
        sflag[r] = sel;
        gate_out[(size_t)b * NNODE + r] =
            sel ? (1.f / (1.f + expf(-yv))) : 0.f;
    }
    __syncthreads();

    for (int r = tid; r < NNODE; r += 256) {
        if (sflag[r]) {
            int pos = 0;
            for (int j = 0; j < r; j++) pos += sflag[j];
            idx_out[b * k + pos] = r;
        }
    }
}

// ---------------------------------------------------------------------------
// Final: mean over 128 nodes -> dense [32,16] + bias -> softmax(16).
// ---------------------------------------------------------------------------
__global__ __launch_bounds__(128) void k_final(
    const float* __restrict__ h3, const float* __restrict__ wd,
    const float* __restrict__ bd, float* __restrict__ out)
{
    __shared__ float ps[4][HDIM];
    __shared__ float pooled[HDIM];
    __shared__ float logits[CDIM];
    const int tid = threadIdx.x;
    const int b   = blockIdx.x;
    const int c = tid & 31, seg = tid >> 5;

    float s = 0.f;
    for (int i = seg * 32; i < seg * 32 + 32; i++)
        s += h3[((size_t)b * KSEL2 + i) * HDIM + c];
    ps[seg][c] = s;
    __syncthreads();
    if (tid < HDIM)
        pooled[tid] = (ps[0][tid] + ps[1][tid] + ps[2][tid] + ps[3][tid]) *
                      (1.f / (float)KSEL2);
    __syncthreads();
    if (tid < CDIM) {
        float l = bd[tid];
        for (int h = 0; h < HDIM; h++) l += pooled[h] * wd[h * CDIM + tid];
        logits[tid] = l;
    }
    __syncthreads();
    if (tid < CDIM) {
        float mx = -1e30f;
        for (int j = 0; j < CDIM; j++) mx = fmaxf(mx, logits[j]);
        float den = 0.f;
        for (int j = 0; j < CDIM; j++) den += expf(logits[j] - mx);
        out[b * CDIM + tid] = expf(logits[tid] - mx) / den;
    }
}

// ---------------------------------------------------------------------------
extern "C" void kernel_launch(void* const* d_in, const int* in_sizes, int n_in,
                              void* d_out, int out_size)
{
    (void)in_sizes; (void)n_in; (void)out_size;
    const float* x    = (const float*)d_in[0];
    const float* a    = (const float*)d_in[1];
    const float* w1_1 = (const float*)d_in[2];
    const float* w2_1 = (const float*)d_in[3];
    const float* b1   = (const float*)d_in[4];
    const float* w1_2 = (const float*)d_in[5];
    const float* w2_2 = (const float*)d_in[6];
    const float* b2   = (const float*)d_in[7];
    const float* w1_3 = (const float*)d_in[8];
    const float* w2_3 = (const float*)d_in[9];
    const float* b3   = (const float*)d_in[10];
    const float* pp   = (const float*)d_in[11];
    const float* wd   = (const float*)d_in[12];
    const float* bd   = (const float*)d_in[13];
    float* out = (float*)d_out;

    __nv_bfloat16 *zhi, *zlo;
    float *u1, *u2, *u3, *h1, *h2, *h3, *gate1, *gate2;
    int *idx1, *idx2;
    cudaGetSymbolAddress((void**)&zhi, g_zhi);
    cudaGetSymbolAddress((void**)&zlo, g_zlo);
    cudaGetSymbolAddress((void**)&u1, g_u1);
    cudaGetSymbolAddress((void**)&u2, g_u2);
    cudaGetSymbolAddress((void**)&u3, g_u3);
    cudaGetSymbolAddress((void**)&h1, g_h1);
    cudaGetSymbolAddress((void**)&h2, g_h2);
    cudaGetSymbolAddress((void**)&h3, g_h3);
    cudaGetSymbolAddress((void**)&gate1, g_gate1);
    cudaGetSymbolAddress((void**)&gate2, g_gate2);
    cudaGetSymbolAddress((void**)&idx1, g_idx1);
    cudaGetSymbolAddress((void**)&idx2, g_idx2);

    // conv1
    k_xw<<<(BATCH * NNODE) / 64, 256>>>(x, w1_1, w2_1, b1, zhi, zlo, u1);
    k_aZ_mma<<<dim3(NNODE / 128, BATCH), 256>>>(
        a, zhi, zlo, u1, h1, nullptr, NNODE, 0);
    // pool1
    k_topk<<<BATCH, 256>>>(h1, pp, nullptr, gate1, idx1, KSEL1);
    // conv2 (scatter-z / gather-rows: z rows are zero at dropped nodes)
    k_gxw<<<(BATCH * NNODE) / 64, 256>>>(h1, gate1, w1_2, w2_2, b2, zhi, zlo, u2);
    k_aZ_mma<<<dim3(KSEL1 / 128, BATCH), 256>>>(
        a, zhi, zlo, u2, h2, idx1, KSEL1, 0);
    // pool2
    k_topk<<<BATCH, 256>>>(h2, pp, gate1, gate2, idx2, KSEL2);
    // conv3
    k_gxw<<<(BATCH * NNODE) / 64, 256>>>(h2, gate2, w1_3, w2_3, b3, zhi, zlo, u3);
    k_aZ_mma<<<dim3(KSEL2 / 128, BATCH), 256>>>(
        a, zhi, zlo, u3, h3, idx2, KSEL2, 1);
    // global mean pool + dense + softmax
    k_final<<<BATCH, 128>>>(h3, wd, bd, out);
}

// round 5
// speedup vs baseline: 1.2004x; 1.1499x over previous
#include <cuda_runtime.h>
#include <cuda_bf16.h>
#include <math.h>
#include <stdint.h>

#define BATCH 256
#define NNODE 512
#define FDIM  128
#define HDIM  32
#define CDIM  16
#define KSEL1 256
#define KSEL2 128

// ---------------- scratch (device globals: no allocation allowed) ----------
__device__ __nv_bfloat16 g_zhi[BATCH * HDIM * NNODE];  // z^T split-hi [B][32][512]
__device__ __nv_bfloat16 g_zlo[BATCH * HDIM * NNODE];  // z^T split-lo
__device__ float g_u1[BATCH * NNODE * HDIM];
__device__ float g_u2[BATCH * NNODE * HDIM];
__device__ float g_u3[BATCH * NNODE * HDIM];
__device__ float g_h1[BATCH * NNODE * HDIM];
__device__ float g_h2[BATCH * NNODE * HDIM];
__device__ float g_h3[BATCH * KSEL2 * HDIM];
__device__ float g_gate1[BATCH * NNODE];
__device__ float g_gate2[BATCH * NNODE];
__device__ int   g_idx1[BATCH * KSEL1];
__device__ int   g_idx2[BATCH * KSEL2];

// ======================= warp-MMA helpers (generic PTX) =====================
__device__ __forceinline__ uint32_t smem_u32(const void* p) {
    uint32_t a;
    asm("{ .reg .u64 t; cvta.to.shared.u64 t, %1; cvt.u32.u64 %0, t; }"
        : "=r"(a) : "l"(p));
    return a;
}
__device__ __forceinline__ void ldsm4(uint32_t* r, uint32_t addr) {
    asm volatile(
        "ldmatrix.sync.aligned.m8n8.x4.shared.b16 {%0,%1,%2,%3}, [%4];"
        : "=r"(r[0]), "=r"(r[1]), "=r"(r[2]), "=r"(r[3]) : "r"(addr));
}
__device__ __forceinline__ void mma16816(float* c, const uint32_t* a,
                                         uint32_t b0, uint32_t b1) {
    asm volatile(
        "mma.sync.aligned.m16n8k16.row.col.f32.bf16.bf16.f32 "
        "{%0,%1,%2,%3}, {%4,%5,%6,%7}, {%8,%9}, {%0,%1,%2,%3};"
        : "+f"(c[0]), "+f"(c[1]), "+f"(c[2]), "+f"(c[3])
        : "r"(a[0]), "r"(a[1]), "r"(a[2]), "r"(a[3]), "r"(b0), "r"(b1));
}
#define CP16(dst, src) \
    asm volatile("cp.async.cg.shared.global [%0], [%1], 16;" \
                 :: "r"(dst), "l"(src))
#define CP_COMMIT() asm volatile("cp.async.commit_group;" ::: "memory")
#define CP_WAIT0()  asm volatile("cp.async.wait_group 0;" ::: "memory")

// split fp32 -> bf16 hi/lo
__device__ __forceinline__ void bf16_split(float v, unsigned short& h,
                                           unsigned short& l) {
    __nv_bfloat16 hb = __float2bfloat16(v);
    float hf = __bfloat162float(hb);
    __nv_bfloat16 lb = __float2bfloat16(v - hf);
    h = *(unsigned short*)&hb;
    l = *(unsigned short*)&lb;
}

// ---------------------------------------------------------------------------
// G1: zT_hi/lo = split(x @ w1)^T (coalesced via smem transpose),
//     u = x @ w2 + bias.  x:[B*N,128].
// ---------------------------------------------------------------------------
__global__ __launch_bounds__(256) void k_xw(
    const float* __restrict__ x, const float* __restrict__ w1,
    const float* __restrict__ w2, const float* __restrict__ bias,
    __nv_bfloat16* __restrict__ zhi, __nv_bfloat16* __restrict__ zlo,
    float* __restrict__ uout)
{
    __shared__ float ws[FDIM][68];   // 34816 B
    __shared__ float xt[64][36];     // 9216 B  (reused as z transpose stage)
    const int tid = threadIdx.x;
    const int m0  = blockIdx.x * 64;

#pragma unroll
    for (int i = 0; i < 4; i++) {
        int e = tid + 256 * i;
        int k = e >> 3, c4 = e & 7;
        *(float4*)&ws[k][c4 * 4]      = *(const float4*)&w1[k * HDIM + c4 * 4];
        *(float4*)&ws[k][32 + c4 * 4] = *(const float4*)&w2[k * HDIM + c4 * 4];
    }

    float acc[4][4];
#pragma unroll
    for (int i = 0; i < 4; i++)
#pragma unroll
        for (int j = 0; j < 4; j++) acc[i][j] = 0.f;

    const int tx = tid & 15, ty = tid >> 4;

    for (int k0 = 0; k0 < FDIM; k0 += 32) {
        __syncthreads();
#pragma unroll
        for (int i = 0; i < 2; i++) {
            int e = tid + 256 * i;
            int r = e >> 3, c4 = e & 7;
            *(float4*)&xt[r][c4 * 4] =
                *(const float4*)&x[(size_t)(m0 + r) * FDIM + k0 + c4 * 4];
        }
        __syncthreads();
#pragma unroll
        for (int kk = 0; kk < 32; kk++) {
            float4 wv = *(float4*)&ws[k0 + kk][tx * 4];
#pragma unroll
            for (int i = 0; i < 4; i++) {
                float xv = xt[ty * 4 + i][kk];
                acc[i][0] += xv * wv.x; acc[i][1] += xv * wv.y;
                acc[i][2] += xv * wv.z; acc[i][3] += xv * wv.w;
            }
        }
    }
    __syncthreads();   // xt reads done -> reuse as zts

    __nv_bfloat16* zts_h = (__nv_bfloat16*)xt;          // [32][72]
    __nv_bfloat16* zts_l = zts_h + 32 * 72;             // [32][72]

    if (tx < 8) {   // z half -> stage transposed split in smem
#pragma unroll
        for (int j = 0; j < 4; j++) {
            int col = tx * 4 + j;
#pragma unroll
            for (int i = 0; i < 4; i++) {
                unsigned short hp, lp;
                bf16_split(acc[i][j], hp, lp);
                zts_h[col * 72 + ty * 4 + i] = *(__nv_bfloat16*)&hp;
                zts_l[col * 72 + ty * 4 + i] = *(__nv_bfloat16*)&lp;
            }
        }
    } else {        // u half
        int c0 = tx * 4 - 32;
        float4 bv = *(const float4*)&bias[c0];
#pragma unroll
        for (int i = 0; i < 4; i++) {
            int gr = m0 + ty * 4 + i;
            *(float4*)&uout[(size_t)gr * HDIM + c0] =
                make_float4(acc[i][0] + bv.x, acc[i][1] + bv.y,
                            acc[i][2] + bv.z, acc[i][3] + bv.w);
        }
    }
    __syncthreads();
    {   // coalesced z store: 8 threads per column, 16B each
        int col = tid >> 3, seg = tid & 7;
        int b_ = m0 >> 9, r0 = m0 & (NNODE - 1);
        size_t gb = ((size_t)(b_ * HDIM + col)) * NNODE + r0 + seg * 8;
        *(uint4*)&zhi[gb] = *(uint4*)&zts_h[col * 72 + seg * 8];
        *(uint4*)&zlo[gb] = *(uint4*)&zts_l[col * 72 + seg * 8];
    }
}

// ---------------------------------------------------------------------------
// G3/G5: same but input is gate*h, h:[B*N,32].
// ---------------------------------------------------------------------------
__global__ __launch_bounds__(256) void k_gxw(
    const float* __restrict__ hfeat, const float* __restrict__ gate,
    const float* __restrict__ w1, const float* __restrict__ w2,
    const float* __restrict__ bias,
    __nv_bfloat16* __restrict__ zhi, __nv_bfloat16* __restrict__ zlo,
    float* __restrict__ uout)
{
    __shared__ float ws[HDIM][68];
    __shared__ float xt[64][36];
    __shared__ __nv_bfloat16 zts_h[32][72];
    __shared__ __nv_bfloat16 zts_l[32][72];
    const int tid = threadIdx.x;
    const int m0  = blockIdx.x * 64;

    {
        int k = tid >> 3, c4 = tid & 7;
        *(float4*)&ws[k][c4 * 4]      = *(const float4*)&w1[k * HDIM + c4 * 4];
        *(float4*)&ws[k][32 + c4 * 4] = *(const float4*)&w2[k * HDIM + c4 * 4];
    }
#pragma unroll
    for (int i = 0; i < 2; i++) {
        int e = tid + 256 * i;
        int r = e >> 3, c4 = e & 7;
        int gr = m0 + r;
        float g = gate[gr];
        float4 v = *(const float4*)&hfeat[(size_t)gr * HDIM + c4 * 4];
        v.x *= g; v.y *= g; v.z *= g; v.w *= g;
        *(float4*)&xt[r][c4 * 4] = v;
    }
    __syncthreads();

    float acc[4][4];
#pragma unroll
    for (int i = 0; i < 4; i++)
#pragma unroll
        for (int j = 0; j < 4; j++) acc[i][j] = 0.f;

    const int tx = tid & 15, ty = tid >> 4;
#pragma unroll
    for (int kk = 0; kk < HDIM; kk++) {
        float4 wv = *(float4*)&ws[kk][tx * 4];
#pragma unroll
        for (int i = 0; i < 4; i++) {
            float xv = xt[ty * 4 + i][kk];
            acc[i][0] += xv * wv.x; acc[i][1] += xv * wv.y;
            acc[i][2] += xv * wv.z; acc[i][3] += xv * wv.w;
        }
    }

    if (tx < 8) {
#pragma unroll
        for (int j = 0; j < 4; j++) {
            int col = tx * 4 + j;
#pragma unroll
            for (int i = 0; i < 4; i++) {
                unsigned short hp, lp;
                bf16_split(acc[i][j], hp, lp);
                zts_h[col][ty * 4 + i] = *(__nv_bfloat16*)&hp;
                zts_l[col][ty * 4 + i] = *(__nv_bfloat16*)&lp;
            }
        }
    } else {
        int c0 = tx * 4 - 32;
        float4 bv = *(const float4*)&bias[c0];
#pragma unroll
        for (int i = 0; i < 4; i++) {
            int gr = m0 + ty * 4 + i;
            *(float4*)&uout[(size_t)gr * HDIM + c0] =
                make_float4(acc[i][0] + bv.x, acc[i][1] + bv.y,
                            acc[i][2] + bv.z, acc[i][3] + bv.w);
        }
    }
    __syncthreads();
    {
        int col = tid >> 3, seg = tid & 7;
        int b_ = m0 >> 9, r0 = m0 & (NNODE - 1);
        size_t gb = ((size_t)(b_ * HDIM + col)) * NNODE + r0 + seg * 8;
        *(uint4*)&zhi[gb] = *(uint4*)&zts_h[col][seg * 8];
        *(uint4*)&zlo[gb] = *(uint4*)&zts_l[col][seg * 8];
    }
}

// ---------------------------------------------------------------------------
// HMMA a@z v2: z-resident in SMEM, cp.async double-buffered a chunks.
// out[rows] = relu( a[b,gidx(row),:] @ z[b] + u[b,gidx(row)] )
// Split-bf16 compensated: D = Ah*Bh + Ah*Bl + Al*Bh (fp32 accum).
// ---------------------------------------------------------------------------
#define ASTR   72       // a bf16 tile row stride (144B = 9*16B)
#define ZROW   520      // z resident row stride in bf16 (1040B = 65*16B)
#define OFF_ZL 33280    // sZh: [32][520] bf16 = 33280 B
#define OFF_AF 66560    // fp32 stage: 2 x 128*64*4 = 2 x 32768
#define OFF_AB 132096   // bf16 stage: 2 x (hi 18432 + lo 18432) = 2 x 36864
#define OFF_GIDX 205824
#define SMEM_AZ  206336

__global__ __launch_bounds__(256) void k_aZ_mma(
    const float* __restrict__ a, const __nv_bfloat16* __restrict__ zhi,
    const __nv_bfloat16* __restrict__ zlo, const float* __restrict__ u,
    float* __restrict__ out, const int* __restrict__ ridx,
    int rows_out, int out_compact)
{
    extern __shared__ char smem[];
    const uint32_t sb = smem_u32(smem);
    const int tid = threadIdx.x, wid = tid >> 5, lane = tid & 31;
    const int b  = blockIdx.y;
    const int m0 = blockIdx.x * 128;
    int* gidx = (int*)(smem + OFF_GIDX);

    if (tid < 128)
        gidx[tid] = ridx ? ridx[b * rows_out + m0 + tid] : (m0 + tid);
    __syncthreads();

    const float* ab = a + (size_t)b * NNODE * NNODE;
    const __nv_bfloat16* zhb = zhi + (size_t)b * HDIM * NNODE;
    const __nv_bfloat16* zlb = zlo + (size_t)b * HDIM * NNODE;

    // ---- z resident load (async): 2 arrays x 2048 x 16B ----
#pragma unroll
    for (int t = 0; t < 8; t++) {
        int i = tid + 256 * t;          // 0..2047
        int r = i >> 6, c = i & 63;
        uint32_t doff = r * (ZROW * 2) + c * 16;
        CP16(sb + doff,          zhb + (size_t)r * NNODE + c * 8);
        CP16(sb + OFF_ZL + doff, zlb + (size_t)r * NNODE + c * 8);
    }
    // ---- a chunk 0 (async) ----
#pragma unroll
    for (int t = 0; t < 8; t++) {
        int e = tid + 256 * t;
        int row = e >> 4, c16 = e & 15;
        CP16(sb + OFF_AF + row * 256 + c16 * 16,
             ab + (size_t)gidx[row] * NNODE + c16 * 4);
    }
    CP_COMMIT();
    CP_WAIT0();
    __syncthreads();

    // convert chunk 0
    {
        const float* src = (const float*)(smem + OFF_AF);
        __nv_bfloat16* dh = (__nv_bfloat16*)(smem + OFF_AB);
        __nv_bfloat16* dl = dh + 9216;
#pragma unroll
        for (int t = 0; t < 8; t++) {
            int e = tid + 256 * t;
            int row = e >> 4, c4 = (e & 15) * 4;
            float4 v = *(const float4*)&src[row * 64 + c4];
            unsigned short hp[4], lp[4];
            bf16_split(v.x, hp[0], lp[0]); bf16_split(v.y, hp[1], lp[1]);
            bf16_split(v.z, hp[2], lp[2]); bf16_split(v.w, hp[3], lp[3]);
            *(uint2*)&dh[row * ASTR + c4] = *(uint2*)hp;
            *(uint2*)&dl[row * ASTR + c4] = *(uint2*)lp;
        }
    }
    __syncthreads();

    float acc[4][4];
#pragma unroll
    for (int i = 0; i < 4; i++)
#pragma unroll
        for (int j = 0; j < 4; j++) acc[i][j] = 0.f;

    // ldmatrix per-lane addressing
    const int g8 = lane >> 3, r8 = lane & 7;
    const int a_row = wid * 16 + ((g8 & 1) ? 8 : 0) + r8;
    const int a_colB = ((g8 >= 2) ? 8 : 0) * 2;
    const uint32_t ah_off = (uint32_t)a_row * (ASTR * 2) + a_colB;
    const int b_rowoff = ((g8 >> 1) ? 8 : 0) + r8;
    const int b_colB   = ((g8 & 1) ? 8 : 0) * 2;
    const uint32_t bh0 = sb +          (uint32_t)b_rowoff * (ZROW * 2) + b_colB;
    const uint32_t bh1 = sb +          (uint32_t)(16 + b_rowoff) * (ZROW * 2) + b_colB;
    const uint32_t bl0 = sb + OFF_ZL + (uint32_t)b_rowoff * (ZROW * 2) + b_colB;
    const uint32_t bl1 = sb + OFF_ZL + (uint32_t)(16 + b_rowoff) * (ZROW * 2) + b_colB;

    for (int ch = 0; ch < 8; ch++) {
        // prefetch next a chunk while doing MMA on this one
        if (ch < 7) {
            const int s = (ch + 1) & 1;
            const int k0 = (ch + 1) * 64;
#pragma unroll
            for (int t = 0; t < 8; t++) {
                int e = tid + 256 * t;
                int row = e >> 4, c16 = e & 15;
                CP16(sb + OFF_AF + s * 32768 + row * 256 + c16 * 16,
                     ab + (size_t)gidx[row] * NNODE + k0 + c16 * 4);
            }
        }
        CP_COMMIT();

        const uint32_t ahb = sb + OFF_AB + (ch & 1) * 36864 + ah_off;
        const uint32_t alb = ahb + 18432;
#pragma unroll
        for (int ks = 0; ks < 4; ks++) {
            const uint32_t ka = (uint32_t)ks * 32;          // a tile k offset
            const uint32_t kz = (uint32_t)(ch * 128 + ks * 32);  // z k offset
            uint32_t ah[4], al[4], bh[8], bl[8];
            ldsm4(ah, ahb + ka);
            ldsm4(al, alb + ka);
            ldsm4(bh,     bh0 + kz);
            ldsm4(bh + 4, bh1 + kz);
            ldsm4(bl,     bl0 + kz);
            ldsm4(bl + 4, bl1 + kz);
#pragma unroll
            for (int nt = 0; nt < 4; nt++) {
                mma16816(acc[nt], ah, bh[nt * 2], bh[nt * 2 + 1]);
                mma16816(acc[nt], ah, bl[nt * 2], bl[nt * 2 + 1]);
                mma16816(acc[nt], al, bh[nt * 2], bh[nt * 2 + 1]);
            }
        }

        CP_WAIT0();
        __syncthreads();
        if (ch < 7) {
            const int s = (ch + 1) & 1;
            const float* src = (const float*)(smem + OFF_AF + s * 32768);
            __nv_bfloat16* dh = (__nv_bfloat16*)(smem + OFF_AB + s * 36864);
            __nv_bfloat16* dl = dh + 9216;
#pragma unroll
            for (int t = 0; t < 8; t++) {
                int e = tid + 256 * t;
                int row = e >> 4, c4 = (e & 15) * 4;
                float4 v = *(const float4*)&src[row * 64 + c4];
                unsigned short hp[4], lp[4];
                bf16_split(v.x, hp[0], lp[0]); bf16_split(v.y, hp[1], lp[1]);
                bf16_split(v.z, hp[2], lp[2]); bf16_split(v.w, hp[3], lp[3]);
                *(uint2*)&dh[row * ASTR + c4] = *(uint2*)hp;
                *(uint2*)&dl[row * ASTR + c4] = *(uint2*)lp;
            }
        }
        __syncthreads();
    }

    // ---- epilogue: D frag (g,t2),(g,t2+1),(g+8,t2),(g+8,t2+1) ----
    const int g  = lane >> 2, t2 = (lane & 3) * 2;
    const int lr0 = wid * 16 + g, lr1 = lr0 + 8;
    const int gm0 = gidx[lr0], gm1 = gidx[lr1];
    const float* u0 = &u[((size_t)b * NNODE + gm0) * HDIM];
    const float* u1 = &u[((size_t)b * NNODE + gm1) * HDIM];
    float* o0 = out + (out_compact
               ? ((size_t)b * rows_out + m0 + lr0) * HDIM
               : ((size_t)b * NNODE + gm0) * HDIM);
    float* o1 = out + (out_compact
               ? ((size_t)b * rows_out + m0 + lr1) * HDIM
               : ((size_t)b * NNODE + gm1) * HDIM);
#pragma unroll
    for (int nt = 0; nt < 4; nt++) {
        int c = nt * 8 + t2;
        float2 uv0 = *(const float2*)&u0[c];
        float2 uv1 = *(const float2*)&u1[c];
        float2 r0, r1;
        r0.x = fmaxf(acc[nt][0] + uv0.x, 0.f);
        r0.y = fmaxf(acc[nt][1] + uv0.y, 0.f);
        r1.x = fmaxf(acc[nt][2] + uv1.x, 0.f);
        r1.y = fmaxf(acc[nt][3] + uv1.y, 0.f);
        *(float2*)&o0[c] = r0;
        *(float2*)&o1[c] = r1;
    }
}

// ---------------------------------------------------------------------------
// TopK: exact jax.lax.top_k set semantics via rank counting.
// ---------------------------------------------------------------------------
__global__ __launch_bounds__(256) void k_topk(
    const float* __restrict__ hfeat, const float* __restrict__ p,
    const float* __restrict__ prevgate, float* __restrict__ gate_out,
    int* __restrict__ idx_out, int k)
{
    __shared__ float ysh[NNODE];
    __shared__ float pn[HDIM];
    __shared__ int sflag[NNODE];
    const int tid = threadIdx.x;
    const int b   = blockIdx.x;

    if (tid == 0) {
        float s = 0.f;
        for (int h = 0; h < HDIM; h++) s += p[h] * p[h];
        s = rsqrtf(s);
        for (int h = 0; h < HDIM; h++) pn[h] = p[h] * s;
    }
    __syncthreads();

    const int lane = tid & 31, w = tid >> 5;
    for (int r = w; r < NNODE; r += 8) {
        float v = hfeat[((size_t)b * NNODE + r) * HDIM + lane] * pn[lane];
#pragma unroll
        for (int s = 16; s > 0; s >>= 1) v += __shfl_xor_sync(0xffffffffu, v, s);
        if (lane == 0) {
            bool valid = (prevgate == nullptr) ||
                         (prevgate[(size_t)b * NNODE + r] > 0.f);
            ysh[r] = valid ? v : -1e30f;
        }
    }
    __syncthreads();

    for (int r = tid; r < NNODE; r += 256) {
        float yv = ysh[r];
        int rank = 0;
        for (int j = 0; j < NNODE; j++) {
            float yj = ysh[j];
            rank += (yj > yv) || (yj == yv && j < r);
        }
        int sel = (rank < k) ? 1 : 0;
        sflag[r] = sel;
        gate_out[(size_t)b * NNODE + r] =
            sel ? (1.f / (1.f + expf(-yv))) : 0.f;
    }
    __syncthreads();

    for (int r = tid; r < NNODE; r += 256) {
        if (sflag[r]) {
            int pos = 0;
            for (int j = 0; j < r; j++) pos += sflag[j];
            idx_out[b * k + pos] = r;
        }
    }
}

// ---------------------------------------------------------------------------
// Final: mean over 128 nodes -> dense [32,16] + bias -> softmax(16).
// ---------------------------------------------------------------------------
__global__ __launch_bounds__(128) void k_final(
    const float* __restrict__ h3, const float* __restrict__ wd,
    const float* __restrict__ bd, float* __restrict__ out)
{
    __shared__ float ps[4][HDIM];
    __shared__ float pooled[HDIM];
    __shared__ float logits[CDIM];
    const int tid = threadIdx.x;
    const int b   = blockIdx.x;
    const int c = tid & 31, seg = tid >> 5;

    float s = 0.f;
    for (int i = seg * 32; i < seg * 32 + 32; i++)
        s += h3[((size_t)b * KSEL2 + i) * HDIM + c];
    ps[seg][c] = s;
    __syncthreads();
    if (tid < HDIM)
        pooled[tid] = (ps[0][tid] + ps[1][tid] + ps[2][tid] + ps[3][tid]) *
                      (1.f / (float)KSEL2);
    __syncthreads();
    if (tid < CDIM) {
        float l = bd[tid];
        for (int h = 0; h < HDIM; h++) l += pooled[h] * wd[h * CDIM + tid];
        logits[tid] = l;
    }
    __syncthreads();
    if (tid < CDIM) {
        float mx = -1e30f;
        for (int j = 0; j < CDIM; j++) mx = fmaxf(mx, logits[j]);
        float den = 0.f;
        for (int j = 0; j < CDIM; j++) den += expf(logits[j] - mx);
        out[b * CDIM + tid] = expf(logits[tid] - mx) / den;
    }
}

// ---------------------------------------------------------------------------
extern "C" void kernel_launch(void* const* d_in, const int* in_sizes, int n_in,
                              void* d_out, int out_size)
{
    (void)in_sizes; (void)n_in; (void)out_size;
    const float* x    = (const float*)d_in[0];
    const float* a    = (const float*)d_in[1];
    const float* w1_1 = (const float*)d_in[2];
    const float* w2_1 = (const float*)d_in[3];
    const float* b1   = (const float*)d_in[4];
    const float* w1_2 = (const float*)d_in[5];
    const float* w2_2 = (const float*)d_in[6];
    const float* b2   = (const float*)d_in[7];
    const float* w1_3 = (const float*)d_in[8];
    const float* w2_3 = (const float*)d_in[9];
    const float* b3   = (const float*)d_in[10];
    const float* pp   = (const float*)d_in[11];
    const float* wd   = (const float*)d_in[12];
    const float* bd   = (const float*)d_in[13];
    float* out = (float*)d_out;

    __nv_bfloat16 *zhi, *zlo;
    float *u1, *u2, *u3, *h1, *h2, *h3, *gate1, *gate2;
    int *idx1, *idx2;
    cudaGetSymbolAddress((void**)&zhi, g_zhi);
    cudaGetSymbolAddress((void**)&zlo, g_zlo);
    cudaGetSymbolAddress((void**)&u1, g_u1);
    cudaGetSymbolAddress((void**)&u2, g_u2);
    cudaGetSymbolAddress((void**)&u3, g_u3);
    cudaGetSymbolAddress((void**)&h1, g_h1);
    cudaGetSymbolAddress((void**)&h2, g_h2);
    cudaGetSymbolAddress((void**)&h3, g_h3);
    cudaGetSymbolAddress((void**)&gate1, g_gate1);
    cudaGetSymbolAddress((void**)&gate2, g_gate2);
    cudaGetSymbolAddress((void**)&idx1, g_idx1);
    cudaGetSymbolAddress((void**)&idx2, g_idx2);

    cudaFuncSetAttribute(k_aZ_mma, cudaFuncAttributeMaxDynamicSharedMemorySize,
                         SMEM_AZ);

    // conv1
    k_xw<<<(BATCH * NNODE) / 64, 256>>>(x, w1_1, w2_1, b1, zhi, zlo, u1);
    k_aZ_mma<<<dim3(NNODE / 128, BATCH), 256, SMEM_AZ>>>(
        a, zhi, zlo, u1, h1, nullptr, NNODE, 0);
    // pool1
    k_topk<<<BATCH, 256>>>(h1, pp, nullptr, gate1, idx1, KSEL1);
    // conv2 (scatter-z / gather-rows: z rows are zero at dropped nodes)
    k_gxw<<<(BATCH * NNODE) / 64, 256>>>(h1, gate1, w1_2, w2_2, b2, zhi, zlo, u2);
    k_aZ_mma<<<dim3(KSEL1 / 128, BATCH), 256, SMEM_AZ>>>(
        a, zhi, zlo, u2, h2, idx1, KSEL1, 0);
    // pool2
    k_topk<<<BATCH, 256>>>(h2, pp, gate1, gate2, idx2, KSEL2);
    // conv3
    k_gxw<<<(BATCH * NNODE) / 64, 256>>>(h2, gate2, w1_3, w2_3, b3, zhi, zlo, u3);
    k_aZ_mma<<<dim3(KSEL2 / 128, BATCH), 256, SMEM_AZ>>>(
        a, zhi, zlo, u3, h3, idx2, KSEL2, 1);
    // global mean pool + dense + softmax
    k_final<<<BATCH, 128>>>(h3, wd, bd, out);
}

// round 7
// speedup vs baseline: 1.2947x; 1.0786x over previous
#include <cuda_runtime.h>
#include <cuda_bf16.h>
#include <math.h>
#include <stdint.h>

#define BATCH 256
#define NNODE 512
#define FDIM  128
#define HDIM  32
#define CDIM  16
#define KSEL1 256
#define KSEL2 128

// ---------------- scratch (device globals: no allocation allowed) ----------
__device__ __nv_bfloat16 g_zhi[BATCH * HDIM * NNODE];  // z^T split-hi [B][32][512]
__device__ __nv_bfloat16 g_zlo[BATCH * HDIM * NNODE];  // z^T split-lo
__device__ float g_u1[BATCH * NNODE * HDIM];
__device__ float g_u2[BATCH * NNODE * HDIM];
__device__ float g_u3[BATCH * NNODE * HDIM];
__device__ float g_h1[BATCH * NNODE * HDIM];
__device__ float g_h2[BATCH * NNODE * HDIM];
__device__ float g_h3[BATCH * KSEL2 * HDIM];
__device__ float g_gate1[BATCH * NNODE];
__device__ float g_gate2[BATCH * NNODE];
__device__ int   g_idx1[BATCH * KSEL1];
__device__ int   g_idx2[BATCH * KSEL2];

// ======================= warp-MMA helpers (generic PTX) =====================
__device__ __forceinline__ uint32_t smem_u32(const void* p) {
    uint32_t a;
    asm("{ .reg .u64 t; cvta.to.shared.u64 t, %1; cvt.u32.u64 %0, t; }"
        : "=r"(a) : "l"(p));
    return a;
}
__device__ __forceinline__ void ldsm4(uint32_t* r, uint32_t addr) {
    asm volatile(
        "ldmatrix.sync.aligned.m8n8.x4.shared.b16 {%0,%1,%2,%3}, [%4];"
        : "=r"(r[0]), "=r"(r[1]), "=r"(r[2]), "=r"(r[3]) : "r"(addr));
}
__device__ __forceinline__ void mma16816(float* c, const uint32_t* a,
                                         uint32_t b0, uint32_t b1) {
    asm volatile(
        "mma.sync.aligned.m16n8k16.row.col.f32.bf16.bf16.f32 "
        "{%0,%1,%2,%3}, {%4,%5,%6,%7}, {%8,%9}, {%0,%1,%2,%3};"
        : "+f"(c[0]), "+f"(c[1]), "+f"(c[2]), "+f"(c[3])
        : "r"(a[0]), "r"(a[1]), "r"(a[2]), "r"(a[3]), "r"(b0), "r"(b1));
}
#define CP16(dst, src) \
    asm volatile("cp.async.cg.shared.global [%0], [%1], 16;" \
                 :: "r"(dst), "l"(src))
#define CP_COMMIT() asm volatile("cp.async.commit_group;" ::: "memory")
#define CP_WAIT0()  asm volatile("cp.async.wait_group 0;" ::: "memory")

// split fp32 -> bf16 hi/lo
__device__ __forceinline__ void bsplit(float v, unsigned short& h,
                                       unsigned short& l) {
    __nv_bfloat16 hb = __float2bfloat16(v);
    float hf = __bfloat162float(hb);
    __nv_bfloat16 lb = __float2bfloat16(v - hf);
    h = *(unsigned short*)&hb;
    l = *(unsigned short*)&lb;
}

// ---------------------------------------------------------------------------
// G1: zT_hi/lo = split(x @ w1)^T (coalesced), u = x @ w2 + bias.
// Block 256 thr, tile 128 rows x 64 cols (w1|w2), thread tile 4x8.
// ---------------------------------------------------------------------------
__global__ __launch_bounds__(256) void k_xw(
    const float* __restrict__ x, const float* __restrict__ w1,
    const float* __restrict__ w2, const float* __restrict__ bias,
    __nv_bfloat16* __restrict__ zhi, __nv_bfloat16* __restrict__ zlo,
    float* __restrict__ uout)
{
    __shared__ __align__(16) float ws[FDIM][68];   // 34816 B (reused for zts)
    __shared__ __align__(16) float xt[128][36];    // 18432 B
    const int tid = threadIdx.x;
    const int m0  = blockIdx.x * 128;
    const int rg = tid >> 3, cg = tid & 7;

#pragma unroll
    for (int i = 0; i < 4; i++) {
        int e = tid + 256 * i;          // 0..1023
        int k = e >> 3, c4 = e & 7;
        *(float4*)&ws[k][c4 * 4]      = *(const float4*)&w1[k * HDIM + c4 * 4];
        *(float4*)&ws[k][32 + c4 * 4] = *(const float4*)&w2[k * HDIM + c4 * 4];
    }

    float acc[4][8];
#pragma unroll
    for (int i = 0; i < 4; i++)
#pragma unroll
        for (int j = 0; j < 8; j++) acc[i][j] = 0.f;

    for (int k0 = 0; k0 < FDIM; k0 += 32) {
        __syncthreads();
#pragma unroll
        for (int i = 0; i < 4; i++) {
            int e = tid + 256 * i;      // 1024 float4
            int r = e >> 3, c4 = e & 7;
            *(float4*)&xt[r][c4 * 4] =
                *(const float4*)&x[(size_t)(m0 + r) * FDIM + k0 + c4 * 4];
        }
        __syncthreads();
#pragma unroll
        for (int kk = 0; kk < 32; kk++) {
            float4 w0 = *(float4*)&ws[k0 + kk][cg * 8];
            float4 w1v = *(float4*)&ws[k0 + kk][cg * 8 + 4];
#pragma unroll
            for (int i = 0; i < 4; i++) {
                float xv = xt[rg * 4 + i][kk];
                acc[i][0] += xv * w0.x;  acc[i][1] += xv * w0.y;
                acc[i][2] += xv * w0.z;  acc[i][3] += xv * w0.w;
                acc[i][4] += xv * w1v.x; acc[i][5] += xv * w1v.y;
                acc[i][6] += xv * w1v.z; acc[i][7] += xv * w1v.w;
            }
        }
    }
    __syncthreads();   // ws/xt reads done -> reuse ws as z transpose stage

    __nv_bfloat16* zts_h = (__nv_bfloat16*)ws;     // [32][136]
    __nv_bfloat16* zts_l = zts_h + 32 * 136;

    if (cg < 4) {   // z half: cols cg*8..+8 of w1 output
#pragma unroll
        for (int j = 0; j < 8; j++) {
            int col = cg * 8 + j;
            unsigned short hp[4], lp[4];
#pragma unroll
            for (int i = 0; i < 4; i++) bsplit(acc[i][j], hp[i], lp[i]);
            *(uint2*)&zts_h[col * 136 + rg * 4] = *(uint2*)hp;
            *(uint2*)&zts_l[col * 136 + rg * 4] = *(uint2*)lp;
        }
    } else {        // u half
        int c0 = cg * 8 - 32;
        float4 bv0 = *(const float4*)&bias[c0];
        float4 bv1 = *(const float4*)&bias[c0 + 4];
#pragma unroll
        for (int i = 0; i < 4; i++) {
            int gr = m0 + rg * 4 + i;
            *(float4*)&uout[(size_t)gr * HDIM + c0] =
                make_float4(acc[i][0] + bv0.x, acc[i][1] + bv0.y,
                            acc[i][2] + bv0.z, acc[i][3] + bv0.w);
            *(float4*)&uout[(size_t)gr * HDIM + c0 + 4] =
                make_float4(acc[i][4] + bv1.x, acc[i][5] + bv1.y,
                            acc[i][6] + bv1.z, acc[i][7] + bv1.w);
        }
    }
    __syncthreads();
    {   // coalesced z store: 512 uint4 per array, 2 per thread
        int b_ = m0 >> 9, r0 = m0 & (NNODE - 1);
#pragma unroll
        for (int it = 0; it < 2; it++) {
            int e = tid + 256 * it;
            int col = e >> 4, seg = e & 15;
            size_t gb = ((size_t)(b_ * HDIM + col)) * NNODE + r0 + seg * 8;
            *(uint4*)&zhi[gb] = *(uint4*)&zts_h[col * 136 + seg * 8];
            *(uint4*)&zlo[gb] = *(uint4*)&zts_l[col * 136 + seg * 8];
        }
    }
}

// ---------------------------------------------------------------------------
// G3/G5: same but input is gate*h, h:[B*N,32]. Tile 128 rows x 64 cols.
// ---------------------------------------------------------------------------
__global__ __launch_bounds__(256) void k_gxw(
    const float* __restrict__ hfeat, const float* __restrict__ gate,
    const float* __restrict__ w1, const float* __restrict__ w2,
    const float* __restrict__ bias,
    __nv_bfloat16* __restrict__ zhi, __nv_bfloat16* __restrict__ zlo,
    float* __restrict__ uout)
{
    __shared__ __align__(16) float ws[HDIM][68];   // 8704 B
    __shared__ __align__(16) float xt[128][36];    // 18432 B (reused for zts)
    const int tid = threadIdx.x;
    const int m0  = blockIdx.x * 128;
    const int rg = tid >> 3, cg = tid & 7;

    {
        int k = tid >> 3, c4 = tid & 7;
        *(float4*)&ws[k][c4 * 4]      = *(const float4*)&w1[k * HDIM + c4 * 4];
        *(float4*)&ws[k][32 + c4 * 4] = *(const float4*)&w2[k * HDIM + c4 * 4];
    }
#pragma unroll
    for (int i = 0; i < 4; i++) {
        int e = tid + 256 * i;
        int r = e >> 3, c4 = e & 7;
        int gr = m0 + r;
        float g = gate[gr];
        float4 v = *(const float4*)&hfeat[(size_t)gr * HDIM + c4 * 4];
        v.x *= g; v.y *= g; v.z *= g; v.w *= g;
        *(float4*)&xt[r][c4 * 4] = v;
    }
    __syncthreads();

    float acc[4][8];
#pragma unroll
    for (int i = 0; i < 4; i++)
#pragma unroll
        for (int j = 0; j < 8; j++) acc[i][j] = 0.f;

#pragma unroll
    for (int kk = 0; kk < HDIM; kk++) {
        float4 w0 = *(float4*)&ws[kk][cg * 8];
        float4 w1v = *(float4*)&ws[kk][cg * 8 + 4];
#pragma unroll
        for (int i = 0; i < 4; i++) {
            float xv = xt[rg * 4 + i][kk];
            acc[i][0] += xv * w0.x;  acc[i][1] += xv * w0.y;
            acc[i][2] += xv * w0.z;  acc[i][3] += xv * w0.w;
            acc[i][4] += xv * w1v.x; acc[i][5] += xv * w1v.y;
            acc[i][6] += xv * w1v.z; acc[i][7] += xv * w1v.w;
        }
    }
    __syncthreads();   // xt reads done -> reuse as zts

    __nv_bfloat16* zts_h = (__nv_bfloat16*)xt;     // [32][136]
    __nv_bfloat16* zts_l = zts_h + 32 * 136;

    if (cg < 4) {
#pragma unroll
        for (int j = 0; j < 8; j++) {
            int col = cg * 8 + j;
            unsigned short hp[4], lp[4];
#pragma unroll
            for (int i = 0; i < 4; i++) bsplit(acc[i][j], hp[i], lp[i]);
            *(uint2*)&zts_h[col * 136 + rg * 4] = *(uint2*)hp;
            *(uint2*)&zts_l[col * 136 + rg * 4] = *(uint2*)lp;
        }
    } else {
        int c0 = cg * 8 - 32;
        float4 bv0 = *(const float4*)&bias[c0];
        float4 bv1 = *(const float4*)&bias[c0 + 4];
#pragma unroll
        for (int i = 0; i < 4; i++) {
            int gr = m0 + rg * 4 + i;
            *(float4*)&uout[(size_t)gr * HDIM + c0] =
                make_float4(acc[i][0] + bv0.x, acc[i][1] + bv0.y,
                            acc[i][2] + bv0.z, acc[i][3] + bv0.w);
            *(float4*)&uout[(size_t)gr * HDIM + c0 + 4] =
                make_float4(acc[i][4] + bv1.x, acc[i][5] + bv1.y,
                            acc[i][6] + bv1.z, acc[i][7] + bv1.w);
        }
    }
    __syncthreads();
    {
        int b_ = m0 >> 9, r0 = m0 & (NNODE - 1);
#pragma unroll
        for (int it = 0; it < 2; it++) {
            int e = tid + 256 * it;
            int col = e >> 4, seg = e & 15;
            size_t gb = ((size_t)(b_ * HDIM + col)) * NNODE + r0 + seg * 8;
            *(uint4*)&zhi[gb] = *(uint4*)&zts_h[col * 136 + seg * 8];
            *(uint4*)&zlo[gb] = *(uint4*)&zts_l[col * 136 + seg * 8];
        }
    }
}

// ---------------------------------------------------------------------------
// HMMA a@z v3: z-resident SMEM, register-prefetched a chunks, 2 CTAs/SM.
// out[rows] = relu( a[b,gidx(row),:] @ z[b] + u[b,gidx(row)] )
// Split-bf16 compensated: D = Ah*Bh + Ah*Bl + Al*Bh (fp32 accum).
// ---------------------------------------------------------------------------
#define ASTR   72       // a bf16 tile row stride (144B)
#define ZROW   520      // z resident row stride in bf16 (1040B)
#define OFF_ZL 33280    // sZh: [32][520] bf16 = 33280 B
#define OFF_AB 66560    // bf16 a tile: hi 18432 + lo 18432
#define OFF_GIDX 103424
#define SMEM_AZ  103936

__global__ __launch_bounds__(256, 2) void k_aZ_mma(
    const float* __restrict__ a, const __nv_bfloat16* __restrict__ zhi,
    const __nv_bfloat16* __restrict__ zlo, const float* __restrict__ u,
    float* __restrict__ out, const int* __restrict__ ridx,
    int rows_out, int out_compact)
{
    extern __shared__ char smem[];
    const uint32_t sb = smem_u32(smem);
    const int tid = threadIdx.x, wid = tid >> 5, lane = tid & 31;
    const int b  = blockIdx.y;
    const int m0 = blockIdx.x * 128;
    int* gidx = (int*)(smem + OFF_GIDX);

    if (tid < 128)
        gidx[tid] = ridx ? ridx[b * rows_out + m0 + tid] : (m0 + tid);
    __syncthreads();

    const float* ab = a + (size_t)b * NNODE * NNODE;
    const __nv_bfloat16* zhb = zhi + (size_t)b * HDIM * NNODE;
    const __nv_bfloat16* zlb = zlo + (size_t)b * HDIM * NNODE;

    // ---- z resident load (async) ----
#pragma unroll
    for (int t = 0; t < 8; t++) {
        int i = tid + 256 * t;          // 0..2047
        int r = i >> 6, c = i & 63;
        uint32_t doff = r * (ZROW * 2) + c * 16;
        CP16(sb + doff,          zhb + (size_t)r * NNODE + c * 8);
        CP16(sb + OFF_ZL + doff, zlb + (size_t)r * NNODE + c * 8);
    }
    CP_COMMIT();

    const int prow = tid >> 4;           // +16*t
    const int pc4  = (tid & 15) * 4;

    // ---- a chunk 0: LDG -> regs ----
    float4 pf[8];
#pragma unroll
    for (int t = 0; t < 8; t++)
        pf[t] = *(const float4*)&ab[(size_t)gidx[prow + 16 * t] * NNODE + pc4];

    // convert chunk 0 regs -> SMEM
    {
        __nv_bfloat16* dh = (__nv_bfloat16*)(smem + OFF_AB);
        __nv_bfloat16* dl = dh + 9216;
#pragma unroll
        for (int t = 0; t < 8; t++) {
            int row = prow + 16 * t;
            unsigned short hp[4], lp[4];
            bsplit(pf[t].x, hp[0], lp[0]); bsplit(pf[t].y, hp[1], lp[1]);
            bsplit(pf[t].z, hp[2], lp[2]); bsplit(pf[t].w, hp[3], lp[3]);
            *(uint2*)&dh[row * ASTR + pc4] = *(uint2*)hp;
            *(uint2*)&dl[row * ASTR + pc4] = *(uint2*)lp;
        }
    }
    CP_WAIT0();          // z resident ready
    __syncthreads();

    float acc[4][4];
#pragma unroll
    for (int i = 0; i < 4; i++)
#pragma unroll
        for (int j = 0; j < 4; j++) acc[i][j] = 0.f;

    // ldmatrix per-lane addressing
    const int g8 = lane >> 3, r8 = lane & 7;
    const int a_row = wid * 16 + ((g8 & 1) ? 8 : 0) + r8;
    const int a_colB = ((g8 >= 2) ? 8 : 0) * 2;
    const uint32_t ahb = sb + OFF_AB + (uint32_t)a_row * (ASTR * 2) + a_colB;
    const uint32_t alb = ahb + 18432;
    const int b_rowoff = ((g8 >> 1) ? 8 : 0) + r8;
    const int b_colB   = ((g8 & 1) ? 8 : 0) * 2;
    const uint32_t bh0 = sb +          (uint32_t)b_rowoff * (ZROW * 2) + b_colB;
    const uint32_t bh1 = sb +          (uint32_t)(16 + b_rowoff) * (ZROW * 2) + b_colB;
    const uint32_t bl0 = sb + OFF_ZL + (uint32_t)b_rowoff * (ZROW * 2) + b_colB;
    const uint32_t bl1 = sb + OFF_ZL + (uint32_t)(16 + b_rowoff) * (ZROW * 2) + b_colB;

    for (int ch = 0; ch < 8; ch++) {
        // prefetch next a chunk into regs (latency hidden by MMA below)
        if (ch < 7) {
            const int k0 = (ch + 1) * 64;
#pragma unroll
            for (int t = 0; t < 8; t++)
                pf[t] = *(const float4*)
                    &ab[(size_t)gidx[prow + 16 * t] * NNODE + k0 + pc4];
        }

#pragma unroll
        for (int ks = 0; ks < 4; ks++) {
            const uint32_t ka = (uint32_t)ks * 32;
            const uint32_t kz = (uint32_t)(ch * 128 + ks * 32);
            uint32_t ah[4], al[4], bh[8], bl[8];
            ldsm4(ah, ahb + ka);
            ldsm4(al, alb + ka);
            ldsm4(bh,     bh0 + kz);
            ldsm4(bh + 4, bh1 + kz);
            ldsm4(bl,     bl0 + kz);
            ldsm4(bl + 4, bl1 + kz);
#pragma unroll
            for (int nt = 0; nt < 4; nt++) {
                mma16816(acc[nt], ah, bh[nt * 2], bh[nt * 2 + 1]);
                mma16816(acc[nt], ah, bl[nt * 2], bl[nt * 2 + 1]);
                mma16816(acc[nt], al, bh[nt * 2], bh[nt * 2 + 1]);
            }
        }

        if (ch < 7) {
            __syncthreads();   // everyone done reading a tile
            __nv_bfloat16* dh = (__nv_bfloat16*)(smem + OFF_AB);
            __nv_bfloat16* dl = dh + 9216;
#pragma unroll
            for (int t = 0; t < 8; t++) {
                int row = prow + 16 * t;
                unsigned short hp[4], lp[4];
                bsplit(pf[t].x, hp[0], lp[0]); bsplit(pf[t].y, hp[1], lp[1]);
                bsplit(pf[t].z, hp[2], lp[2]); bsplit(pf[t].w, hp[3], lp[3]);
                *(uint2*)&dh[row * ASTR + pc4] = *(uint2*)hp;
                *(uint2*)&dl[row * ASTR + pc4] = *(uint2*)lp;
            }
            __syncthreads();   // a tile ready for next MMA round
        }
    }

    // ---- epilogue ----
    const int g  = lane >> 2, t2 = (lane & 3) * 2;
    const int lr0 = wid * 16 + g, lr1 = lr0 + 8;
    const int gm0 = gidx[lr0], gm1 = gidx[lr1];
    const float* u0 = &u[((size_t)b * NNODE + gm0) * HDIM];
    const float* u1 = &u[((size_t)b * NNODE + gm1) * HDIM];
    float* o0 = out + (out_compact
               ? ((size_t)b * rows_out + m0 + lr0) * HDIM
               : ((size_t)b * NNODE + gm0) * HDIM);
    float* o1 = out + (out_compact
               ? ((size_t)b * rows_out + m0 + lr1) * HDIM
               : ((size_t)b * NNODE + gm1) * HDIM);
#pragma unroll
    for (int nt = 0; nt < 4; nt++) {
        int c = nt * 8 + t2;
        float2 uv0 = *(const float2*)&u0[c];
        float2 uv1 = *(const float2*)&u1[c];
        float2 r0, r1;
        r0.x = fmaxf(acc[nt][0] + uv0.x, 0.f);
        r0.y = fmaxf(acc[nt][1] + uv0.y, 0.f);
        r1.x = fmaxf(acc[nt][2] + uv1.x, 0.f);
        r1.y = fmaxf(acc[nt][3] + uv1.y, 0.f);
        *(float2*)&o0[c] = r0;
        *(float2*)&o1[c] = r1;
    }
}

// ---------------------------------------------------------------------------
// TopK: exact jax.lax.top_k set semantics via rank counting.
// ---------------------------------------------------------------------------
__global__ __launch_bounds__(256) void k_topk(
    const float* __restrict__ hfeat, const float* __restrict__ p,
    const float* __restrict__ prevgate, float* __restrict__ gate_out,
    int* __restrict__ idx_out, int k)
{
    __shared__ float ysh[NNODE];
    __shared__ float pn[HDIM];
    __shared__ int sflag[NNODE];
    const int tid = threadIdx.x;
    const int b   = blockIdx.x;

    if (tid == 0) {
        float s = 0.f;
        for (int h = 0; h < HDIM; h++) s += p[h] * p[h];
        s = rsqrtf(s);
        for (int h = 0; h < HDIM; h++) pn[h] = p[h] * s;
    }
    __syncthreads();

    const int lane = tid & 31, w = tid >> 5;
    for (int r = w; r < NNODE; r += 8) {
        float v = hfeat[((size_t)b * NNODE + r) * HDIM + lane] * pn[lane];
#pragma unroll
        for (int s = 16; s > 0; s >>= 1) v += __shfl_xor_sync(0xffffffffu, v, s);
        if (lane == 0) {
            bool valid = (prevgate == nullptr) ||
                         (prevgate[(size_t)b * NNODE + r] > 0.f);
            ysh[r] = valid ? v : -1e30f;
        }
    }
    __syncthreads();

    for (int r = tid; r < NNODE; r += 256) {
        float yv = ysh[r];
        int rank = 0;
        for (int j = 0; j < NNODE; j++) {
            float yj = ysh[j];
            rank += (yj > yv) || (yj == yv && j < r);
        }
        int sel = (rank < k) ? 1 : 0;
        sflag[r] = sel;
        gate_out[(size_t)b * NNODE + r] =
            sel ? (1.f / (1.f + expf(-yv))) : 0.f;
    }
    __syncthreads();

    for (int r = tid; r < NNODE; r += 256) {
        if (sflag[r]) {
            int pos = 0;
            for (int j = 0; j < r; j++) pos += sflag[j];
            idx_out[b * k + pos] = r;
        }
    }
}

// ---------------------------------------------------------------------------
// Final: mean over 128 nodes -> dense [32,16] + bias -> softmax(16).
// ---------------------------------------------------------------------------
__global__ __launch_bounds__(128) void k_final(
    const float* __restrict__ h3, const float* __restrict__ wd,
    const float* __restrict__ bd, float* __restrict__ out)
{
    __shared__ float ps[4][HDIM];
    __shared__ float pooled[HDIM];
    __shared__ float logits[CDIM];
    const int tid = threadIdx.x;
    const int b   = blockIdx.x;
    const int c = tid & 31, seg = tid >> 5;

    float s = 0.f;
    for (int i = seg * 32; i < seg * 32 + 32; i++)
        s += h3[((size_t)b * KSEL2 + i) * HDIM + c];
    ps[seg][c] = s;
    __syncthreads();
    if (tid < HDIM)
        pooled[tid] = (ps[0][tid] + ps[1][tid] + ps[2][tid] + ps[3][tid]) *
                      (1.f / (float)KSEL2);
    __syncthreads();
    if (tid < CDIM) {
        float l = bd[tid];
        for (int h = 0; h < HDIM; h++) l += pooled[h] * wd[h * CDIM + tid];
        logits[tid] = l;
    }
    __syncthreads();
    if (tid < CDIM) {
        float mx = -1e30f;
        for (int j = 0; j < CDIM; j++) mx = fmaxf(mx, logits[j]);
        float den = 0.f;
        for (int j = 0; j < CDIM; j++) den += expf(logits[j] - mx);
        out[b * CDIM + tid] = expf(logits[tid] - mx) / den;
    }
}

// ---------------------------------------------------------------------------
extern "C" void kernel_launch(void* const* d_in, const int* in_sizes, int n_in,
                              void* d_out, int out_size)
{
    (void)in_sizes; (void)n_in; (void)out_size;
    const float* x    = (const float*)d_in[0];
    const float* a    = (const float*)d_in[1];
    const float* w1_1 = (const float*)d_in[2];
    const float* w2_1 = (const float*)d_in[3];
    const float* b1   = (const float*)d_in[4];
    const float* w1_2 = (const float*)d_in[5];
    const float* w2_2 = (const float*)d_in[6];
    const float* b2   = (const float*)d_in[7];
    const float* w1_3 = (const float*)d_in[8];
    const float* w2_3 = (const float*)d_in[9];
    const float* b3   = (const float*)d_in[10];
    const float* pp   = (const float*)d_in[11];
    const float* wd   = (const float*)d_in[12];
    const float* bd   = (const float*)d_in[13];
    float* out = (float*)d_out;

    __nv_bfloat16 *zhi, *zlo;
    float *u1, *u2, *u3, *h1, *h2, *h3, *gate1, *gate2;
    int *idx1, *idx2;
    cudaGetSymbolAddress((void**)&zhi, g_zhi);
    cudaGetSymbolAddress((void**)&zlo, g_zlo);
    cudaGetSymbolAddress((void**)&u1, g_u1);
    cudaGetSymbolAddress((void**)&u2, g_u2);
    cudaGetSymbolAddress((void**)&u3, g_u3);
    cudaGetSymbolAddress((void**)&h1, g_h1);
    cudaGetSymbolAddress((void**)&h2, g_h2);
    cudaGetSymbolAddress((void**)&h3, g_h3);
    cudaGetSymbolAddress((void**)&gate1, g_gate1);
    cudaGetSymbolAddress((void**)&gate2, g_gate2);
    cudaGetSymbolAddress((void**)&idx1, g_idx1);
    cudaGetSymbolAddress((void**)&idx2, g_idx2);

    cudaFuncSetAttribute(k_aZ_mma, cudaFuncAttributeMaxDynamicSharedMemorySize,
                         SMEM_AZ);

    // conv1
    k_xw<<<(BATCH * NNODE) / 128, 256>>>(x, w1_1, w2_1, b1, zhi, zlo, u1);
    k_aZ_mma<<<dim3(NNODE / 128, BATCH), 256, SMEM_AZ>>>(
        a, zhi, zlo, u1, h1, nullptr, NNODE, 0);
    // pool1
    k_topk<<<BATCH, 256>>>(h1, pp, nullptr, gate1, idx1, KSEL1);
    // conv2 (scatter-z / gather-rows: z rows are zero at dropped nodes)
    k_gxw<<<(BATCH * NNODE) / 128, 256>>>(h1, gate1, w1_2, w2_2, b2, zhi, zlo, u2);
    k_aZ_mma<<<dim3(KSEL1 / 128, BATCH), 256, SMEM_AZ>>>(
        a, zhi, zlo, u2, h2, idx1, KSEL1, 0);
    // pool2
    k_topk<<<BATCH, 256>>>(h2, pp, gate1, gate2, idx2, KSEL2);
    // conv3
    k_gxw<<<(BATCH * NNODE) / 128, 256>>>(h2, gate2, w1_3, w2_3, b3, zhi, zlo, u3);
    k_aZ_mma<<<dim3(KSEL2 / 128, BATCH), 256, SMEM_AZ>>>(
        a, zhi, zlo, u3, h3, idx2, KSEL2, 1);
    // global mean pool + dense + softmax
    k_final<<<BATCH, 128>>>(h3, wd, bd, out);
}

// round 9
// speedup vs baseline: 1.4065x; 1.0863x over previous
#include <cuda_runtime.h>
#include <cuda_fp16.h>
#include <math.h>
#include <stdint.h>

#define BATCH 256
#define NNODE 512
#define FDIM  128
#define HDIM  32
#define CDIM  16
#define KSEL1 256
#define KSEL2 128

// ---------------- scratch (device globals: no allocation allowed) ----------
__device__ __half g_zh[BATCH * HDIM * NNODE];   // z^T split-hi [B][32][512]
__device__ __half g_zl[BATCH * HDIM * NNODE];   // z^T split-lo
__device__ float g_u1[BATCH * NNODE * HDIM];
__device__ float g_u2[BATCH * NNODE * HDIM];
__device__ float g_u3[BATCH * NNODE * HDIM];
__device__ float g_h1[BATCH * NNODE * HDIM];
__device__ float g_h2[BATCH * NNODE * HDIM];
__device__ float g_h3[BATCH * KSEL2 * HDIM];
__device__ float g_gate1[BATCH * NNODE];
__device__ float g_gate2[BATCH * NNODE];
__device__ int   g_idx1[BATCH * KSEL1];
__device__ int   g_idx2[BATCH * KSEL2];

// ======================= warp-MMA helpers (generic PTX) =====================
__device__ __forceinline__ uint32_t smem_u32(const void* p) {
    uint32_t a;
    asm("{ .reg .u64 t; cvta.to.shared.u64 t, %1; cvt.u32.u64 %0, t; }"
        : "=r"(a) : "l"(p));
    return a;
}
__device__ __forceinline__ void ldsm4(uint32_t* r, uint32_t addr) {
    asm volatile(
        "ldmatrix.sync.aligned.m8n8.x4.shared.b16 {%0,%1,%2,%3}, [%4];"
        : "=r"(r[0]), "=r"(r[1]), "=r"(r[2]), "=r"(r[3]) : "r"(addr));
}
__device__ __forceinline__ void mma_f16(float* c, const uint32_t* a,
                                        uint32_t b0, uint32_t b1) {
    asm volatile(
        "mma.sync.aligned.m16n8k16.row.col.f32.f16.f16.f32 "
        "{%0,%1,%2,%3}, {%4,%5,%6,%7}, {%8,%9}, {%0,%1,%2,%3};"
        : "+f"(c[0]), "+f"(c[1]), "+f"(c[2]), "+f"(c[3])
        : "r"(a[0]), "r"(a[1]), "r"(a[2]), "r"(a[3]), "r"(b0), "r"(b1));
}
#define CP16(dst, src) \
    asm volatile("cp.async.cg.shared.global [%0], [%1], 16;" \
                 :: "r"(dst), "l"(src))
#define CP_COMMIT() asm volatile("cp.async.commit_group;" ::: "memory")
#define CP_WAIT0()  asm volatile("cp.async.wait_group 0;" ::: "memory")

// split fp32 -> fp16 hi/lo (hi+lo carries ~22 mantissa bits)
__device__ __forceinline__ void fsplit(float v, unsigned short& h,
                                       unsigned short& l) {
    __half hb = __float2half(v);
    float hf = __half2float(hb);
    __half lb = __float2half(v - hf);
    h = *(unsigned short*)&hb;
    l = *(unsigned short*)&lb;
}

// ---------------------------------------------------------------------------
// G1 (MMA): z = x @ w1, u = x @ w2 + bias, both via fp16 3-product
// (Xh*Wh + Xh*Wl + Xl*Wh; residual Xl*Wl ~2^-24). zT stored split fp16.
// Tile: 128 rows x 64 N (w1|w2), K=128. 8 warps, warp w: rows [16w,16w+16).
// ---------------------------------------------------------------------------
#define XW_XH   0        // Xh: [128][136] half = 34816
#define XW_XL   34816    // Xl: same
#define XW_WTH  69632    // WTh: [64][136] half = 17408
#define XW_WTL  87040    // WTl: same
#define XW_SMEM 104448

__global__ __launch_bounds__(256, 2) void k_xw(
    const float* __restrict__ x, const float* __restrict__ w1,
    const float* __restrict__ w2, const float* __restrict__ bias,
    __half* __restrict__ zh, __half* __restrict__ zl,
    float* __restrict__ uout)
{
    extern __shared__ char smem[];
    const uint32_t sb = smem_u32(smem);
    const int tid = threadIdx.x, wid = tid >> 5, lane = tid & 31;
    const int m0 = blockIdx.x * 128;
    __half* XH  = (__half*)(smem + XW_XH);
    __half* XL  = (__half*)(smem + XW_XL);
    __half* WTH = (__half*)(smem + XW_WTH);
    __half* WTL = (__half*)(smem + XW_WTL);

    // W^T split: [64 n][128 k]; w1 cols 0..31, w2 cols 32..63 (L2-hot)
#pragma unroll
    for (int t = 0; t < 32; t++) {
        int e = tid + 256 * t;          // 0..8191
        int n = e >> 7, k = e & 127;
        float w = (n < 32) ? w1[k * HDIM + n] : w2[k * HDIM + (n - 32)];
        unsigned short hh, ll;
        fsplit(w, hh, ll);
        WTH[n * 136 + k] = *(__half*)&hh;
        WTL[n * 136 + k] = *(__half*)&ll;
    }
    // x tile 128x128 -> fp16 hi/lo
#pragma unroll
    for (int t = 0; t < 16; t++) {
        int e = tid + 256 * t;          // 0..4095 float4 units
        int r = e >> 5, c4 = (e & 31) * 4;
        float4 v = *(const float4*)&x[(size_t)(m0 + r) * FDIM + c4];
        unsigned short hp[4], lp[4];
        fsplit(v.x, hp[0], lp[0]); fsplit(v.y, hp[1], lp[1]);
        fsplit(v.z, hp[2], lp[2]); fsplit(v.w, hp[3], lp[3]);
        *(uint2*)&XH[r * 136 + c4] = *(uint2*)hp;
        *(uint2*)&XL[r * 136 + c4] = *(uint2*)lp;
    }
    __syncthreads();

    float acc[8][4];
#pragma unroll
    for (int i = 0; i < 8; i++)
#pragma unroll
        for (int j = 0; j < 4; j++) acc[i][j] = 0.f;

    const int g8 = lane >> 3, r8 = lane & 7;
    const int a_row = wid * 16 + ((g8 & 1) ? 8 : 0) + r8;
    const uint32_t a_off = (uint32_t)a_row * 272 + ((g8 >= 2) ? 16 : 0);
    const uint32_t ah_base = sb + XW_XH + a_off;
    const uint32_t al_base = sb + XW_XL + a_off;
    const int b_rowoff = ((g8 >> 1) ? 8 : 0) + r8;
    const uint32_t b_off = (uint32_t)b_rowoff * 272 + ((g8 & 1) ? 16 : 0);
    const uint32_t bh_base = sb + XW_WTH + b_off;
    const uint32_t bl_base = sb + XW_WTL + b_off;

#pragma unroll
    for (int ks = 0; ks < 8; ks++) {
        const uint32_t ka = (uint32_t)ks * 32;
        uint32_t ah[4], al[4], bh[16], bl[16];
        ldsm4(ah, ah_base + ka);
        ldsm4(al, al_base + ka);
#pragma unroll
        for (int q = 0; q < 4; q++) {
            ldsm4(bh + 4 * q, bh_base + (uint32_t)q * 16 * 272 + ka);
            ldsm4(bl + 4 * q, bl_base + (uint32_t)q * 16 * 272 + ka);
        }
#pragma unroll
        for (int nt = 0; nt < 8; nt++) {
            mma_f16(acc[nt], ah, bh[nt * 2], bh[nt * 2 + 1]);
            mma_f16(acc[nt], ah, bl[nt * 2], bl[nt * 2 + 1]);
            mma_f16(acc[nt], al, bh[nt * 2], bh[nt * 2 + 1]);
        }
    }
    __syncthreads();   // all SMEM reads done -> reuse XH area for z staging

    __half* zts_h = (__half*)smem;              // [32 cols][136 rows]
    __half* zts_l = zts_h + 32 * 136;
    const int g = lane >> 2, t2 = (lane & 3) * 2;
    const int r0l = wid * 16 + g, r1l = r0l + 8;

#pragma unroll
    for (int nt = 0; nt < 4; nt++) {            // z half (cols 0..31)
        int c = nt * 8 + t2;
        unsigned short hh, ll;
        fsplit(acc[nt][0], hh, ll);
        zts_h[c * 136 + r0l] = *(__half*)&hh; zts_l[c * 136 + r0l] = *(__half*)&ll;
        fsplit(acc[nt][1], hh, ll);
        zts_h[(c + 1) * 136 + r0l] = *(__half*)&hh; zts_l[(c + 1) * 136 + r0l] = *(__half*)&ll;
        fsplit(acc[nt][2], hh, ll);
        zts_h[c * 136 + r1l] = *(__half*)&hh; zts_l[c * 136 + r1l] = *(__half*)&ll;
        fsplit(acc[nt][3], hh, ll);
        zts_h[(c + 1) * 136 + r1l] = *(__half*)&hh; zts_l[(c + 1) * 136 + r1l] = *(__half*)&ll;
    }
#pragma unroll
    for (int nt = 4; nt < 8; nt++) {            // u half (w2 cols 0..31)
        int c = (nt - 4) * 8 + t2;
        float2 bv = *(const float2*)&bias[c];
        int gr0 = m0 + r0l, gr1 = m0 + r1l;
        float2 v0 = make_float2(acc[nt][0] + bv.x, acc[nt][1] + bv.y);
        float2 v1 = make_float2(acc[nt][2] + bv.x, acc[nt][3] + bv.y);
        *(float2*)&uout[(size_t)gr0 * HDIM + c] = v0;
        *(float2*)&uout[(size_t)gr1 * HDIM + c] = v1;
    }
    __syncthreads();
    {   // coalesced transposed z store
        int b_ = m0 >> 9, r0g = m0 & (NNODE - 1);
#pragma unroll
        for (int it = 0; it < 2; it++) {
            int e = tid + 256 * it;
            int col = e >> 4, seg = e & 15;
            size_t gb = ((size_t)(b_ * HDIM + col)) * NNODE + r0g + seg * 8;
            *(uint4*)&zh[gb] = *(uint4*)&zts_h[col * 136 + seg * 8];
            *(uint4*)&zl[gb] = *(uint4*)&zts_l[col * 136 + seg * 8];
        }
    }
}

// ---------------------------------------------------------------------------
// G3/G5: z = (gate*h) @ w1 (split fp16 out), u = (gate*h) @ w2 + bias.
// SIMT fp32 (tiny FLOPs). Tile 128 rows.
// ---------------------------------------------------------------------------
__global__ __launch_bounds__(256) void k_gxw(
    const float* __restrict__ hfeat, const float* __restrict__ gate,
    const float* __restrict__ w1, const float* __restrict__ w2,
    const float* __restrict__ bias,
    __half* __restrict__ zh, __half* __restrict__ zl,
    float* __restrict__ uout)
{
    __shared__ __align__(16) float ws[HDIM][68];
    __shared__ __align__(16) float xt[128][36];     // reused for z staging
    const int tid = threadIdx.x;
    const int m0  = blockIdx.x * 128;
    const int rg = tid >> 3, cg = tid & 7;

    {
        int k = tid >> 3, c4 = tid & 7;
        *(float4*)&ws[k][c4 * 4]      = *(const float4*)&w1[k * HDIM + c4 * 4];
        *(float4*)&ws[k][32 + c4 * 4] = *(const float4*)&w2[k * HDIM + c4 * 4];
    }
#pragma unroll
    for (int i = 0; i < 4; i++) {
        int e = tid + 256 * i;
        int r = e >> 3, c4 = e & 7;
        int gr = m0 + r;
        float g = gate[gr];
        float4 v = *(const float4*)&hfeat[(size_t)gr * HDIM + c4 * 4];
        v.x *= g; v.y *= g; v.z *= g; v.w *= g;
        *(float4*)&xt[r][c4 * 4] = v;
    }
    __syncthreads();

    float acc[4][8];
#pragma unroll
    for (int i = 0; i < 4; i++)
#pragma unroll
        for (int j = 0; j < 8; j++) acc[i][j] = 0.f;

#pragma unroll
    for (int kk = 0; kk < HDIM; kk++) {
        float4 w0 = *(float4*)&ws[kk][cg * 8];
        float4 w1v = *(float4*)&ws[kk][cg * 8 + 4];
#pragma unroll
        for (int i = 0; i < 4; i++) {
            float xv = xt[rg * 4 + i][kk];
            acc[i][0] += xv * w0.x;  acc[i][1] += xv * w0.y;
            acc[i][2] += xv * w0.z;  acc[i][3] += xv * w0.w;
            acc[i][4] += xv * w1v.x; acc[i][5] += xv * w1v.y;
            acc[i][6] += xv * w1v.z; acc[i][7] += xv * w1v.w;
        }
    }
    __syncthreads();   // xt reads done -> reuse as z staging

    __half* zts_h = (__half*)xt;                 // [32][136]
    __half* zts_l = zts_h + 32 * 136;

    if (cg < 4) {
#pragma unroll
        for (int j = 0; j < 8; j++) {
            int col = cg * 8 + j;
#pragma unroll
            for (int i = 0; i < 4; i++) {
                unsigned short hh, ll;
                fsplit(acc[i][j], hh, ll);
                zts_h[col * 136 + rg * 4 + i] = *(__half*)&hh;
                zts_l[col * 136 + rg * 4 + i] = *(__half*)&ll;
            }
        }
    } else {
        int c0 = cg * 8 - 32;
        float4 bv0 = *(const float4*)&bias[c0];
        float4 bv1 = *(const float4*)&bias[c0 + 4];
#pragma unroll
        for (int i = 0; i < 4; i++) {
            int gr = m0 + rg * 4 + i;
            *(float4*)&uout[(size_t)gr * HDIM + c0] =
                make_float4(acc[i][0] + bv0.x, acc[i][1] + bv0.y,
                            acc[i][2] + bv0.z, acc[i][3] + bv0.w);
            *(float4*)&uout[(size_t)gr * HDIM + c0 + 4] =
                make_float4(acc[i][4] + bv1.x, acc[i][5] + bv1.y,
                            acc[i][6] + bv1.z, acc[i][7] + bv1.w);
        }
    }
    __syncthreads();
    {
        int b_ = m0 >> 9, r0 = m0 & (NNODE - 1);
#pragma unroll
        for (int it = 0; it < 2; it++) {
            int e = tid + 256 * it;
            int col = e >> 4, seg = e & 15;
            size_t gb = ((size_t)(b_ * HDIM + col)) * NNODE + r0 + seg * 8;
            *(uint4*)&zh[gb] = *(uint4*)&zts_h[col * 136 + seg * 8];
            *(uint4*)&zl[gb] = *(uint4*)&zts_l[col * 136 + seg * 8];
        }
    }
}

// ---------------------------------------------------------------------------
// fp16 MMA a@z: 3-product (Ah*Zh + Ah*Zl + Al*Zh; residual Al*Zl ~2^-24),
// z-resident SMEM, register-prefetched a chunks, 2 CTAs/SM.
// out[rows] = relu( a[b,gidx(row),:] @ z[b] + u[b,gidx(row)] )
// ---------------------------------------------------------------------------
#define ASTR   72       // a fp16 tile row stride (144B)
#define ZROW   520      // z resident row stride in halves (1040B)
#define OFF_ZL 33280    // ZH: [32][520] half = 33280 B
#define OFF_AH 66560    // Ah tile: [128][72] half = 18432 B
#define OFF_AL 84992    // Al tile: same
#define OFF_GIDX 103424
#define SMEM_AZ  103936

__global__ __launch_bounds__(256, 2) void k_aZ_mma(
    const float* __restrict__ a, const __half* __restrict__ zh,
    const __half* __restrict__ zl, const float* __restrict__ u,
    float* __restrict__ out, const int* __restrict__ ridx,
    int rows_out, int out_compact)
{
    extern __shared__ char smem[];
    const uint32_t sb = smem_u32(smem);
    const int tid = threadIdx.x, wid = tid >> 5, lane = tid & 31;
    const int b  = blockIdx.y;
    const int m0 = blockIdx.x * 128;
    int* gidx = (int*)(smem + OFF_GIDX);

    if (tid < 128)
        gidx[tid] = ridx ? ridx[b * rows_out + m0 + tid] : (m0 + tid);
    __syncthreads();

    const float* ab = a + (size_t)b * NNODE * NNODE;
    const __half* zhb = zh + (size_t)b * HDIM * NNODE;
    const __half* zlb = zl + (size_t)b * HDIM * NNODE;

    // ---- z resident load (async): 2 arrays x 2048 x 16B ----
#pragma unroll
    for (int t = 0; t < 8; t++) {
        int i = tid + 256 * t;          // 0..2047
        int r = i >> 6, c = i & 63;
        uint32_t doff = r * (ZROW * 2) + c * 16;
        CP16(sb + doff,          zhb + (size_t)r * NNODE + c * 8);
        CP16(sb + OFF_ZL + doff, zlb + (size_t)r * NNODE + c * 8);
    }
    CP_COMMIT();

    const int prow = tid >> 4;           // +16*t
    const int pc4  = (tid & 15) * 4;

    // ---- a chunk 0: LDG -> regs, split convert -> SMEM ----
    float4 pf[8];
#pragma unroll
    for (int t = 0; t < 8; t++)
        pf[t] = *(const float4*)&ab[(size_t)gidx[prow + 16 * t] * NNODE + pc4];
    {
        __half* dh = (__half*)(smem + OFF_AH);
        __half* dl = (__half*)(smem + OFF_AL);
#pragma unroll
        for (int t = 0; t < 8; t++) {
            int row = prow + 16 * t;
            unsigned short hp[4], lp[4];
            fsplit(pf[t].x, hp[0], lp[0]); fsplit(pf[t].y, hp[1], lp[1]);
            fsplit(pf[t].z, hp[2], lp[2]); fsplit(pf[t].w, hp[3], lp[3]);
            *(uint2*)&dh[row * ASTR + pc4] = *(uint2*)hp;
            *(uint2*)&dl[row * ASTR + pc4] = *(uint2*)lp;
        }
    }
    CP_WAIT0();          // z resident ready
    __syncthreads();

    float acc[4][4];
#pragma unroll
    for (int i = 0; i < 4; i++)
#pragma unroll
        for (int j = 0; j < 4; j++) acc[i][j] = 0.f;

    // ldmatrix per-lane addressing
    const int g8 = lane >> 3, r8 = lane & 7;
    const int a_row = wid * 16 + ((g8 & 1) ? 8 : 0) + r8;
    const uint32_t a_off = (uint32_t)a_row * (ASTR * 2) + ((g8 >= 2) ? 16 : 0);
    const uint32_t ahb = sb + OFF_AH + a_off;
    const uint32_t alb = sb + OFF_AL + a_off;
    const int b_rowoff = ((g8 >> 1) ? 8 : 0) + r8;
    const uint32_t b_colB = (g8 & 1) ? 16 : 0;
    const uint32_t bh0 = sb +          (uint32_t)b_rowoff * (ZROW * 2) + b_colB;
    const uint32_t bh1 = sb +          (uint32_t)(16 + b_rowoff) * (ZROW * 2) + b_colB;
    const uint32_t bl0 = sb + OFF_ZL + (uint32_t)b_rowoff * (ZROW * 2) + b_colB;
    const uint32_t bl1 = sb + OFF_ZL + (uint32_t)(16 + b_rowoff) * (ZROW * 2) + b_colB;

    for (int ch = 0; ch < 8; ch++) {
        // prefetch next a chunk into regs (hidden by MMA below)
        if (ch < 7) {
            const int k0 = (ch + 1) * 64;
#pragma unroll
            for (int t = 0; t < 8; t++)
                pf[t] = *(const float4*)
                    &ab[(size_t)gidx[prow + 16 * t] * NNODE + k0 + pc4];
        }

#pragma unroll
        for (int ks = 0; ks < 4; ks++) {
            const uint32_t ka = (uint32_t)ks * 32;
            const uint32_t kz = (uint32_t)(ch * 128 + ks * 32);
            uint32_t ah[4], al[4], bh[8], bl[8];
            ldsm4(ah, ahb + ka);
            ldsm4(al, alb + ka);
            ldsm4(bh,     bh0 + kz);
            ldsm4(bh + 4, bh1 + kz);
            ldsm4(bl,     bl0 + kz);
            ldsm4(bl + 4, bl1 + kz);
#pragma unroll
            for (int nt = 0; nt < 4; nt++) {
                mma_f16(acc[nt], ah, bh[nt * 2], bh[nt * 2 + 1]);
                mma_f16(acc[nt], ah, bl[nt * 2], bl[nt * 2 + 1]);
                mma_f16(acc[nt], al, bh[nt * 2], bh[nt * 2 + 1]);
            }
        }

        if (ch < 7) {
            __syncthreads();   // everyone done reading a tile
            __half* dh = (__half*)(smem + OFF_AH);
            __half* dl = (__half*)(smem + OFF_AL);
#pragma unroll
            for (int t = 0; t < 8; t++) {
                int row = prow + 16 * t;
                unsigned short hp[4], lp[4];
                fsplit(pf[t].x, hp[0], lp[0]); fsplit(pf[t].y, hp[1], lp[1]);
                fsplit(pf[t].z, hp[2], lp[2]); fsplit(pf[t].w, hp[3], lp[3]);
                *(uint2*)&dh[row * ASTR + pc4] = *(uint2*)hp;
                *(uint2*)&dl[row * ASTR + pc4] = *(uint2*)lp;
            }
            __syncthreads();   // a tile ready for next MMA round
        }
    }

    // ---- epilogue ----
    const int g  = lane >> 2, t2 = (lane & 3) * 2;
    const int lr0 = wid * 16 + g, lr1 = lr0 + 8;
    const int gm0 = gidx[lr0], gm1 = gidx[lr1];
    const float* u0 = &u[((size_t)b * NNODE + gm0) * HDIM];
    const float* u1 = &u[((size_t)b * NNODE + gm1) * HDIM];
    float* o0 = out + (out_compact
               ? ((size_t)b * rows_out + m0 + lr0) * HDIM
               : ((size_t)b * NNODE + gm0) * HDIM);
    float* o1 = out + (out_compact
               ? ((size_t)b * rows_out + m0 + lr1) * HDIM
               : ((size_t)b * NNODE + gm1) * HDIM);
#pragma unroll
    for (int nt = 0; nt < 4; nt++) {
        int c = nt * 8 + t2;
        float2 uv0 = *(const float2*)&u0[c];
        float2 uv1 = *(const float2*)&u1[c];
        float2 r0, r1;
        r0.x = fmaxf(acc[nt][0] + uv0.x, 0.f);
        r0.y = fmaxf(acc[nt][1] + uv0.y, 0.f);
        r1.x = fmaxf(acc[nt][2] + uv1.x, 0.f);
        r1.y = fmaxf(acc[nt][3] + uv1.y, 0.f);
        *(float2*)&o0[c] = r0;
        *(float2*)&o1[c] = r1;
    }
}

// ---------------------------------------------------------------------------
// TopK: exact jax.lax.top_k set semantics via rank counting.
// ---------------------------------------------------------------------------
__global__ __launch_bounds__(256) void k_topk(
    const float* __restrict__ hfeat, const float* __restrict__ p,
    const float* __restrict__ prevgate, float* __restrict__ gate_out,
    int* __restrict__ idx_out, int k)
{
    __shared__ float ysh[NNODE];
    __shared__ float pn[HDIM];
    __shared__ int sflag[NNODE];
    const int tid = threadIdx.x;
    const int b   = blockIdx.x;

    if (tid == 0) {
        float s = 0.f;
        for (int h = 0; h < HDIM; h++) s += p[h] * p[h];
        s = rsqrtf(s);
        for (int h = 0; h < HDIM; h++) pn[h] = p[h] * s;
    }
    __syncthreads();

    const int lane = tid & 31, w = tid >> 5;
    for (int r = w; r < NNODE; r += 8) {
        float v = hfeat[((size_t)b * NNODE + r) * HDIM + lane] * pn[lane];
#pragma unroll
        for (int s = 16; s > 0; s >>= 1) v += __shfl_xor_sync(0xffffffffu, v, s);
        if (lane == 0) {
            bool valid = (prevgate == nullptr) ||
                         (prevgate[(size_t)b * NNODE + r] > 0.f);
            ysh[r] = valid ? v : -1e30f;
        }
    }
    __syncthreads();

    for (int r = tid; r < NNODE; r += 256) {
        float yv = ysh[r];
        int rank = 0;
        for (int j = 0; j < NNODE; j++) {
            float yj = ysh[j];
            rank += (yj > yv) || (yj == yv && j < r);
        }
        int sel = (rank < k) ? 1 : 0;
        sflag[r] = sel;
        gate_out[(size_t)b * NNODE + r] =
            sel ? (1.f / (1.f + expf(-yv))) : 0.f;
    }
    __syncthreads();

    for (int r = tid; r < NNODE; r += 256) {
        if (sflag[r]) {
            int pos = 0;
            for (int j = 0; j < r; j++) pos += sflag[j];
            idx_out[b * k + pos] = r;
        }
    }
}

// ---------------------------------------------------------------------------
// Final: mean over 128 nodes -> dense [32,16] + bias -> softmax(16).
// ---------------------------------------------------------------------------
__global__ __launch_bounds__(128) void k_final(
    const float* __restrict__ h3, const float* __restrict__ wd,
    const float* __restrict__ bd, float* __restrict__ out)
{
    __shared__ float ps[4][HDIM];
    __shared__ float pooled[HDIM];
    __shared__ float logits[CDIM];
    const int tid = threadIdx.x;
    const int b   = blockIdx.x;
    const int c = tid & 31, seg = tid >> 5;

    float s = 0.f;
    for (int i = seg * 32; i < seg * 32 + 32; i++)
        s += h3[((size_t)b * KSEL2 + i) * HDIM + c];
    ps[seg][c] = s;
    __syncthreads();
    if (tid < HDIM)
        pooled[tid] = (ps[0][tid] + ps[1][tid] + ps[2][tid] + ps[3][tid]) *
                      (1.f / (float)KSEL2);
    __syncthreads();
    if (tid < CDIM) {
        float l = bd[tid];
        for (int h = 0; h < HDIM; h++) l += pooled[h] * wd[h * CDIM + tid];
        logits[tid] = l;
    }
    __syncthreads();
    if (tid < CDIM) {
        float mx = -1e30f;
        for (int j = 0; j < CDIM; j++) mx = fmaxf(mx, logits[j]);
        float den = 0.f;
        for (int j = 0; j < CDIM; j++) den += expf(logits[j] - mx);
        out[b * CDIM + tid] = expf(logits[tid] - mx) / den;
    }
}

// ---------------------------------------------------------------------------
extern "C" void kernel_launch(void* const* d_in, const int* in_sizes, int n_in,
                              void* d_out, int out_size)
{
    (void)in_sizes; (void)n_in; (void)out_size;
    const float* x    = (const float*)d_in[0];
    const float* a    = (const float*)d_in[1];
    const float* w1_1 = (const float*)d_in[2];
    const float* w2_1 = (const float*)d_in[3];
    const float* b1   = (const float*)d_in[4];
    const float* w1_2 = (const float*)d_in[5];
    const float* w2_2 = (const float*)d_in[6];
    const float* b2   = (const float*)d_in[7];
    const float* w1_3 = (const float*)d_in[8];
    const float* w2_3 = (const float*)d_in[9];
    const float* b3   = (const float*)d_in[10];
    const float* pp   = (const float*)d_in[11];
    const float* wd   = (const float*)d_in[12];
    const float* bd   = (const float*)d_in[13];
    float* out = (float*)d_out;

    __half *zh, *zl;
    float *u1, *u2, *u3, *h1, *h2, *h3, *gate1, *gate2;
    int *idx1, *idx2;
    cudaGetSymbolAddress((void**)&zh, g_zh);
    cudaGetSymbolAddress((void**)&zl, g_zl);
    cudaGetSymbolAddress((void**)&u1, g_u1);
    cudaGetSymbolAddress((void**)&u2, g_u2);
    cudaGetSymbolAddress((void**)&u3, g_u3);
    cudaGetSymbolAddress((void**)&h1, g_h1);
    cudaGetSymbolAddress((void**)&h2, g_h2);
    cudaGetSymbolAddress((void**)&h3, g_h3);
    cudaGetSymbolAddress((void**)&gate1, g_gate1);
    cudaGetSymbolAddress((void**)&gate2, g_gate2);
    cudaGetSymbolAddress((void**)&idx1, g_idx1);
    cudaGetSymbolAddress((void**)&idx2, g_idx2);

    cudaFuncSetAttribute(k_aZ_mma, cudaFuncAttributeMaxDynamicSharedMemorySize,
                         SMEM_AZ);
    cudaFuncSetAttribute(k_xw, cudaFuncAttributeMaxDynamicSharedMemorySize,
                         XW_SMEM);

    // conv1
    k_xw<<<(BATCH * NNODE) / 128, 256, XW_SMEM>>>(x, w1_1, w2_1, b1, zh, zl, u1);
    k_aZ_mma<<<dim3(NNODE / 128, BATCH), 256, SMEM_AZ>>>(
        a, zh, zl, u1, h1, nullptr, NNODE, 0);
    // pool1
    k_topk<<<BATCH, 256>>>(h1, pp, nullptr, gate1, idx1, KSEL1);
    // conv2 (scatter-z / gather-rows: z rows are zero at dropped nodes)
    k_gxw<<<(BATCH * NNODE) / 128, 256>>>(h1, gate1, w1_2, w2_2, b2, zh, zl, u2);
    k_aZ_mma<<<dim3(KSEL1 / 128, BATCH), 256, SMEM_AZ>>>(
        a, zh, zl, u2, h2, idx1, KSEL1, 0);
    // pool2
    k_topk<<<BATCH, 256>>>(h2, pp, gate1, gate2, idx2, KSEL2);
    // conv3
    k_gxw<<<(BATCH * NNODE) / 128, 256>>>(h2, gate2, w1_3, w2_3, b3, zh, zl, u3);
    k_aZ_mma<<<dim3(KSEL2 / 128, BATCH), 256, SMEM_AZ>>>(
        a, zh, zl, u3, h3, idx2, KSEL2, 1);
    // global mean pool + dense + softmax
    k_final<<<BATCH, 128>>>(h3, wd, bd, out);
}

// round 11
// speedup vs baseline: 1.5198x; 1.0806x over previous
#include <cuda_runtime.h>
#include <cuda_fp16.h>
#include <math.h>
#include <stdint.h>

#define BATCH 256
#define NNODE 512
#define FDIM  128
#define HDIM  32
#define CDIM  16
#define KSEL1 256
#define KSEL2 128

// ---------------- scratch (device globals: no allocation allowed) ----------
__device__ __half g_zh[BATCH * HDIM * NNODE];   // z^T split-hi [B][32][512]
__device__ __half g_zl[BATCH * HDIM * NNODE];   // z^T split-lo
__device__ float g_u1[BATCH * NNODE * HDIM];
__device__ float g_u2[BATCH * NNODE * HDIM];
__device__ float g_u3[BATCH * NNODE * HDIM];
__device__ float g_h1[BATCH * NNODE * HDIM];
__device__ float g_h2[BATCH * NNODE * HDIM];
__device__ float g_h3[BATCH * KSEL2 * HDIM];
__device__ float g_gate1[BATCH * NNODE];
__device__ float g_gate2[BATCH * NNODE];
__device__ int   g_idx1[BATCH * KSEL1];
__device__ int   g_idx2[BATCH * KSEL2];

// ======================= warp-MMA helpers (generic PTX) =====================
__device__ __forceinline__ uint32_t smem_u32(const void* p) {
    uint32_t a;
    asm("{ .reg .u64 t; cvta.to.shared.u64 t, %1; cvt.u32.u64 %0, t; }"
        : "=r"(a) : "l"(p));
    return a;
}
__device__ __forceinline__ void ldsm4(uint32_t* r, uint32_t addr) {
    asm volatile(
        "ldmatrix.sync.aligned.m8n8.x4.shared.b16 {%0,%1,%2,%3}, [%4];"
        : "=r"(r[0]), "=r"(r[1]), "=r"(r[2]), "=r"(r[3]) : "r"(addr));
}
__device__ __forceinline__ void mma_f16(float* c, const uint32_t* a,
                                        uint32_t b0, uint32_t b1) {
    asm volatile(
        "mma.sync.aligned.m16n8k16.row.col.f32.f16.f16.f32 "
        "{%0,%1,%2,%3}, {%4,%5,%6,%7}, {%8,%9}, {%0,%1,%2,%3};"
        : "+f"(c[0]), "+f"(c[1]), "+f"(c[2]), "+f"(c[3])
        : "r"(a[0]), "r"(a[1]), "r"(a[2]), "r"(a[3]), "r"(b0), "r"(b1));
}
#define CP16(dst, src) \
    asm volatile("cp.async.cg.shared.global [%0], [%1], 16;" \
                 :: "r"(dst), "l"(src))
#define CP_COMMIT() asm volatile("cp.async.commit_group;" ::: "memory")
#define CP_WAIT0()  asm volatile("cp.async.wait_group 0;" ::: "memory")

// split fp32 -> fp16 hi/lo (hi+lo carries ~22 mantissa bits)
__device__ __forceinline__ void fsplit(float v, unsigned short& h,
                                       unsigned short& l) {
    __half hb = __float2half(v);
    float hf = __half2float(hb);
    __half lb = __float2half(v - hf);
    h = *(unsigned short*)&hb;
    l = *(unsigned short*)&lb;
}

// ---------------------------------------------------------------------------
// G1 (MMA): z = x @ w1, u = x @ w2 + bias, both via fp16 3-product
// (Xh*Wh + Xh*Wl + Xl*Wh; residual Xl*Wl ~2^-24). zT stored split fp16.
// Tile: 128 rows x 64 N (w1|w2), K=128. 8 warps, warp w: rows [16w,16w+16).
// ---------------------------------------------------------------------------
#define XW_XH   0        // Xh: [128][136] half = 34816
#define XW_XL   34816    // Xl: same
#define XW_WTH  69632    // WTh: [64][136] half = 17408
#define XW_WTL  87040    // WTl: same
#define XW_SMEM 104448

__global__ __launch_bounds__(256, 2) void k_xw(
    const float* __restrict__ x, const float* __restrict__ w1,
    const float* __restrict__ w2, const float* __restrict__ bias,
    __half* __restrict__ zh, __half* __restrict__ zl,
    float* __restrict__ uout)
{
    extern __shared__ char smem[];
    const uint32_t sb = smem_u32(smem);
    const int tid = threadIdx.x, wid = tid >> 5, lane = tid & 31;
    const int m0 = blockIdx.x * 128;
    __half* XH  = (__half*)(smem + XW_XH);
    __half* XL  = (__half*)(smem + XW_XL);
    __half* WTH = (__half*)(smem + XW_WTH);
    __half* WTL = (__half*)(smem + XW_WTL);

    // W^T split: [64 n][128 k]; w1 cols 0..31, w2 cols 32..63 (L2-hot)
#pragma unroll
    for (int t = 0; t < 32; t++) {
        int e = tid + 256 * t;          // 0..8191
        int n = e >> 7, k = e & 127;
        float w = (n < 32) ? w1[k * HDIM + n] : w2[k * HDIM + (n - 32)];
        unsigned short hh, ll;
        fsplit(w, hh, ll);
        WTH[n * 136 + k] = *(__half*)&hh;
        WTL[n * 136 + k] = *(__half*)&ll;
    }
    // x tile 128x128 -> fp16 hi/lo
#pragma unroll
    for (int t = 0; t < 16; t++) {
        int e = tid + 256 * t;          // 0..4095 float4 units
        int r = e >> 5, c4 = (e & 31) * 4;
        float4 v = *(const float4*)&x[(size_t)(m0 + r) * FDIM + c4];
        unsigned short hp[4], lp[4];
        fsplit(v.x, hp[0], lp[0]); fsplit(v.y, hp[1], lp[1]);
        fsplit(v.z, hp[2], lp[2]); fsplit(v.w, hp[3], lp[3]);
        *(uint2*)&XH[r * 136 + c4] = *(uint2*)hp;
        *(uint2*)&XL[r * 136 + c4] = *(uint2*)lp;
    }
    __syncthreads();

    float acc[8][4];
#pragma unroll
    for (int i = 0; i < 8; i++)
#pragma unroll
        for (int j = 0; j < 4; j++) acc[i][j] = 0.f;

    const int g8 = lane >> 3, r8 = lane & 7;
    const int a_row = wid * 16 + ((g8 & 1) ? 8 : 0) + r8;
    const uint32_t a_off = (uint32_t)a_row * 272 + ((g8 >= 2) ? 16 : 0);
    const uint32_t ah_base = sb + XW_XH + a_off;
    const uint32_t al_base = sb + XW_XL + a_off;
    const int b_rowoff = ((g8 >> 1) ? 8 : 0) + r8;
    const uint32_t b_off = (uint32_t)b_rowoff * 272 + ((g8 & 1) ? 16 : 0);
    const uint32_t bh_base = sb + XW_WTH + b_off;
    const uint32_t bl_base = sb + XW_WTL + b_off;

#pragma unroll
    for (int ks = 0; ks < 8; ks++) {
        const uint32_t ka = (uint32_t)ks * 32;
        uint32_t ah[4], al[4], bh[16], bl[16];
        ldsm4(ah, ah_base + ka);
        ldsm4(al, al_base + ka);
#pragma unroll
        for (int q = 0; q < 4; q++) {
            ldsm4(bh + 4 * q, bh_base + (uint32_t)q * 16 * 272 + ka);
            ldsm4(bl + 4 * q, bl_base + (uint32_t)q * 16 * 272 + ka);
        }
#pragma unroll
        for (int nt = 0; nt < 8; nt++) {
            mma_f16(acc[nt], ah, bh[nt * 2], bh[nt * 2 + 1]);
            mma_f16(acc[nt], ah, bl[nt * 2], bl[nt * 2 + 1]);
            mma_f16(acc[nt], al, bh[nt * 2], bh[nt * 2 + 1]);
        }
    }
    __syncthreads();   // all SMEM reads done -> reuse XH area for z staging

    __half* zts_h = (__half*)smem;              // [32 cols][136 rows]
    __half* zts_l = zts_h + 32 * 136;
    const int g = lane >> 2, t2 = (lane & 3) * 2;
    const int r0l = wid * 16 + g, r1l = r0l + 8;

#pragma unroll
    for (int nt = 0; nt < 4; nt++) {            // z half (cols 0..31)
        int c = nt * 8 + t2;
        unsigned short hh, ll;
        fsplit(acc[nt][0], hh, ll);
        zts_h[c * 136 + r0l] = *(__half*)&hh; zts_l[c * 136 + r0l] = *(__half*)&ll;
        fsplit(acc[nt][1], hh, ll);
        zts_h[(c + 1) * 136 + r0l] = *(__half*)&hh; zts_l[(c + 1) * 136 + r0l] = *(__half*)&ll;
        fsplit(acc[nt][2], hh, ll);
        zts_h[c * 136 + r1l] = *(__half*)&hh; zts_l[c * 136 + r1l] = *(__half*)&ll;
        fsplit(acc[nt][3], hh, ll);
        zts_h[(c + 1) * 136 + r1l] = *(__half*)&hh; zts_l[(c + 1) * 136 + r1l] = *(__half*)&ll;
    }
#pragma unroll
    for (int nt = 4; nt < 8; nt++) {            // u half (w2 cols 0..31)
        int c = (nt - 4) * 8 + t2;
        float2 bv = *(const float2*)&bias[c];
        int gr0 = m0 + r0l, gr1 = m0 + r1l;
        float2 v0 = make_float2(acc[nt][0] + bv.x, acc[nt][1] + bv.y);
        float2 v1 = make_float2(acc[nt][2] + bv.x, acc[nt][3] + bv.y);
        *(float2*)&uout[(size_t)gr0 * HDIM + c] = v0;
        *(float2*)&uout[(size_t)gr1 * HDIM + c] = v1;
    }
    __syncthreads();
    {   // coalesced transposed z store
        int b_ = m0 >> 9, r0g = m0 & (NNODE - 1);
#pragma unroll
        for (int it = 0; it < 2; it++) {
            int e = tid + 256 * it;
            int col = e >> 4, seg = e & 15;
            size_t gb = ((size_t)(b_ * HDIM + col)) * NNODE + r0g + seg * 8;
            *(uint4*)&zh[gb] = *(uint4*)&zts_h[col * 136 + seg * 8];
            *(uint4*)&zl[gb] = *(uint4*)&zts_l[col * 136 + seg * 8];
        }
    }
}

// ---------------------------------------------------------------------------
// G3/G5 (MMA): z = (gate*h) @ w1, u = (gate*h) @ w2 + bias, fp16 3-product.
// Tile 128 rows x 64 N, K=32 (2 k-steps). Row stride 40 halves (80B,
// conflict-free ldmatrix). Static SMEM ~30KB.
// ---------------------------------------------------------------------------
#define GX_AH   0        // Ah: [128][40] half = 10240
#define GX_AL   10240
#define GX_WTH  20480    // WTh: [64][40] half = 5120
#define GX_WTL  25600
#define GX_SMEM 30720

__global__ __launch_bounds__(256) void k_gxw(
    const float* __restrict__ hfeat, const float* __restrict__ gate,
    const float* __restrict__ w1, const float* __restrict__ w2,
    const float* __restrict__ bias,
    __half* __restrict__ zh, __half* __restrict__ zl,
    float* __restrict__ uout)
{
    __shared__ __align__(16) char smem[GX_SMEM];
    const uint32_t sb = smem_u32(smem);
    const int tid = threadIdx.x, wid = tid >> 5, lane = tid & 31;
    const int m0 = blockIdx.x * 128;
    __half* AH  = (__half*)(smem + GX_AH);
    __half* AL  = (__half*)(smem + GX_AL);
    __half* WTH = (__half*)(smem + GX_WTH);
    __half* WTL = (__half*)(smem + GX_WTL);

    // W^T split: [64 n][32 k]
#pragma unroll
    for (int t = 0; t < 8; t++) {
        int e = tid + 256 * t;          // 0..2047
        int n = e >> 5, kk = e & 31;
        float w = (n < 32) ? w1[kk * HDIM + n] : w2[kk * HDIM + (n - 32)];
        unsigned short hh, ll;
        fsplit(w, hh, ll);
        WTH[n * 40 + kk] = *(__half*)&hh;
        WTL[n * 40 + kk] = *(__half*)&ll;
    }
    // gated h tile 128x32 -> fp16 hi/lo
#pragma unroll
    for (int t = 0; t < 4; t++) {
        int e = tid + 256 * t;          // 0..1023 float4 units
        int r = e >> 3, c4 = (e & 7) * 4;
        int gr = m0 + r;
        float g = gate[gr];
        float4 v = *(const float4*)&hfeat[(size_t)gr * HDIM + c4];
        v.x *= g; v.y *= g; v.z *= g; v.w *= g;
        unsigned short hp[4], lp[4];
        fsplit(v.x, hp[0], lp[0]); fsplit(v.y, hp[1], lp[1]);
        fsplit(v.z, hp[2], lp[2]); fsplit(v.w, hp[3], lp[3]);
        *(uint2*)&AH[r * 40 + c4] = *(uint2*)hp;
        *(uint2*)&AL[r * 40 + c4] = *(uint2*)lp;
    }
    __syncthreads();

    float acc[8][4];
#pragma unroll
    for (int i = 0; i < 8; i++)
#pragma unroll
        for (int j = 0; j < 4; j++) acc[i][j] = 0.f;

    const int g8 = lane >> 3, r8 = lane & 7;
    const int a_row = wid * 16 + ((g8 & 1) ? 8 : 0) + r8;
    const uint32_t a_off = (uint32_t)a_row * 80 + ((g8 >= 2) ? 16 : 0);
    const uint32_t ahb = sb + GX_AH + a_off;
    const uint32_t alb = sb + GX_AL + a_off;
    const int b_rowoff = ((g8 >> 1) ? 8 : 0) + r8;
    const uint32_t b_off = (uint32_t)b_rowoff * 80 + ((g8 & 1) ? 16 : 0);
    const uint32_t bhb = sb + GX_WTH + b_off;
    const uint32_t blb = sb + GX_WTL + b_off;

#pragma unroll
    for (int ks = 0; ks < 2; ks++) {
        const uint32_t ka = (uint32_t)ks * 32;
        uint32_t ah[4], al[4], bh[16], bl[16];
        ldsm4(ah, ahb + ka);
        ldsm4(al, alb + ka);
#pragma unroll
        for (int q = 0; q < 4; q++) {
            ldsm4(bh + 4 * q, bhb + (uint32_t)q * 16 * 80 + ka);
            ldsm4(bl + 4 * q, blb + (uint32_t)q * 16 * 80 + ka);
        }
#pragma unroll
        for (int nt = 0; nt < 8; nt++) {
            mma_f16(acc[nt], ah, bh[nt * 2], bh[nt * 2 + 1]);
            mma_f16(acc[nt], ah, bl[nt * 2], bl[nt * 2 + 1]);
            mma_f16(acc[nt], al, bh[nt * 2], bh[nt * 2 + 1]);
        }
    }
    __syncthreads();   // SMEM reads done -> reuse AH/AL area for z staging

    __half* zts_h = (__half*)smem;              // [32 cols][136 rows] = 17408B
    __half* zts_l = zts_h + 32 * 136;
    const int g = lane >> 2, t2 = (lane & 3) * 2;
    const int r0l = wid * 16 + g, r1l = r0l + 8;

#pragma unroll
    for (int nt = 0; nt < 4; nt++) {            // z half (w1 cols 0..31)
        int c = nt * 8 + t2;
        unsigned short hh, ll;
        fsplit(acc[nt][0], hh, ll);
        zts_h[c * 136 + r0l] = *(__half*)&hh; zts_l[c * 136 + r0l] = *(__half*)&ll;
        fsplit(acc[nt][1], hh, ll);
        zts_h[(c + 1) * 136 + r0l] = *(__half*)&hh; zts_l[(c + 1) * 136 + r0l] = *(__half*)&ll;
        fsplit(acc[nt][2], hh, ll);
        zts_h[c * 136 + r1l] = *(__half*)&hh; zts_l[c * 136 + r1l] = *(__half*)&ll;
        fsplit(acc[nt][3], hh, ll);
        zts_h[(c + 1) * 136 + r1l] = *(__half*)&hh; zts_l[(c + 1) * 136 + r1l] = *(__half*)&ll;
    }
#pragma unroll
    for (int nt = 4; nt < 8; nt++) {            // u half (w2 cols 0..31)
        int c = (nt - 4) * 8 + t2;
        float2 bv = *(const float2*)&bias[c];
        int gr0 = m0 + r0l, gr1 = m0 + r1l;
        float2 v0 = make_float2(acc[nt][0] + bv.x, acc[nt][1] + bv.y);
        float2 v1 = make_float2(acc[nt][2] + bv.x, acc[nt][3] + bv.y);
        *(float2*)&uout[(size_t)gr0 * HDIM + c] = v0;
        *(float2*)&uout[(size_t)gr1 * HDIM + c] = v1;
    }
    __syncthreads();
    {   // coalesced transposed z store
        int b_ = m0 >> 9, r0g = m0 & (NNODE - 1);
#pragma unroll
        for (int it = 0; it < 2; it++) {
            int e = tid + 256 * it;
            int col = e >> 4, seg = e & 15;
            size_t gb = ((size_t)(b_ * HDIM + col)) * NNODE + r0g + seg * 8;
            *(uint4*)&zh[gb] = *(uint4*)&zts_h[col * 136 + seg * 8];
            *(uint4*)&zl[gb] = *(uint4*)&zts_l[col * 136 + seg * 8];
        }
    }
}

// ---------------------------------------------------------------------------
// fp16 MMA a@z: 3-product (Ah*Zh + Ah*Zl + Al*Zh; residual Al*Zl ~2^-24),
// z-resident SMEM, register-prefetched a chunks, 2 CTAs/SM.
// out[rows] = relu( a[b,gidx(row),:] @ z[b] + u[b,gidx(row)] )
// ---------------------------------------------------------------------------
#define ASTR   72       // a fp16 tile row stride (144B)
#define ZROW   520      // z resident row stride in halves (1040B)
#define OFF_ZL 33280    // ZH: [32][520] half = 33280 B
#define OFF_AH 66560    // Ah tile: [128][72] half = 18432 B
#define OFF_AL 84992    // Al tile: same
#define OFF_GIDX 103424
#define SMEM_AZ  103936

__global__ __launch_bounds__(256, 2) void k_aZ_mma(
    const float* __restrict__ a, const __half* __restrict__ zh,
    const __half* __restrict__ zl, const float* __restrict__ u,
    float* __restrict__ out, const int* __restrict__ ridx,
    int rows_out, int out_compact)
{
    extern __shared__ char smem[];
    const uint32_t sb = smem_u32(smem);
    const int tid = threadIdx.x, wid = tid >> 5, lane = tid & 31;
    const int b  = blockIdx.y;
    const int m0 = blockIdx.x * 128;
    int* gidx = (int*)(smem + OFF_GIDX);

    if (tid < 128)
        gidx[tid] = ridx ? ridx[b * rows_out + m0 + tid] : (m0 + tid);
    __syncthreads();

    const float* ab = a + (size_t)b * NNODE * NNODE;
    const __half* zhb = zh + (size_t)b * HDIM * NNODE;
    const __half* zlb = zl + (size_t)b * HDIM * NNODE;

    // ---- z resident load (async): 2 arrays x 2048 x 16B ----
#pragma unroll
    for (int t = 0; t < 8; t++) {
        int i = tid + 256 * t;          // 0..2047
        int r = i >> 6, c = i & 63;
        uint32_t doff = r * (ZROW * 2) + c * 16;
        CP16(sb + doff,          zhb + (size_t)r * NNODE + c * 8);
        CP16(sb + OFF_ZL + doff, zlb + (size_t)r * NNODE + c * 8);
    }
    CP_COMMIT();

    const int prow = tid >> 4;           // +16*t
    const int pc4  = (tid & 15) * 4;

    // ---- a chunk 0: LDG -> regs, split convert -> SMEM ----
    float4 pf[8];
#pragma unroll
    for (int t = 0; t < 8; t++)
        pf[t] = *(const float4*)&ab[(size_t)gidx[prow + 16 * t] * NNODE + pc4];
    {
        __half* dh = (__half*)(smem + OFF_AH);
        __half* dl = (__half*)(smem + OFF_AL);
#pragma unroll
        for (int t = 0; t < 8; t++) {
            int row = prow + 16 * t;
            unsigned short hp[4], lp[4];
            fsplit(pf[t].x, hp[0], lp[0]); fsplit(pf[t].y, hp[1], lp[1]);
            fsplit(pf[t].z, hp[2], lp[2]); fsplit(pf[t].w, hp[3], lp[3]);
            *(uint2*)&dh[row * ASTR + pc4] = *(uint2*)hp;
            *(uint2*)&dl[row * ASTR + pc4] = *(uint2*)lp;
        }
    }
    CP_WAIT0();          // z resident ready
    __syncthreads();

    float acc[4][4];
#pragma unroll
    for (int i = 0; i < 4; i++)
#pragma unroll
        for (int j = 0; j < 4; j++) acc[i][j] = 0.f;

    // ldmatrix per-lane addressing
    const int g8 = lane >> 3, r8 = lane & 7;
    const int a_row = wid * 16 + ((g8 & 1) ? 8 : 0) + r8;
    const uint32_t a_off = (uint32_t)a_row * (ASTR * 2) + ((g8 >= 2) ? 16 : 0);
    const uint32_t ahb = sb + OFF_AH + a_off;
    const uint32_t alb = sb + OFF_AL + a_off;
    const int b_rowoff = ((g8 >> 1) ? 8 : 0) + r8;
    const uint32_t b_colB = (g8 & 1) ? 16 : 0;
    const uint32_t bh0 = sb +          (uint32_t)b_rowoff * (ZROW * 2) + b_colB;
    const uint32_t bh1 = sb +          (uint32_t)(16 + b_rowoff) * (ZROW * 2) + b_colB;
    const uint32_t bl0 = sb + OFF_ZL + (uint32_t)b_rowoff * (ZROW * 2) + b_colB;
    const uint32_t bl1 = sb + OFF_ZL + (uint32_t)(16 + b_rowoff) * (ZROW * 2) + b_colB;

    for (int ch = 0; ch < 8; ch++) {
        // prefetch next a chunk into regs (hidden by MMA below)
        if (ch < 7) {
            const int k0 = (ch + 1) * 64;
#pragma unroll
            for (int t = 0; t < 8; t++)
                pf[t] = *(const float4*)
                    &ab[(size_t)gidx[prow + 16 * t] * NNODE + k0 + pc4];
        }

#pragma unroll
        for (int ks = 0; ks < 4; ks++) {
            const uint32_t ka = (uint32_t)ks * 32;
            const uint32_t kz = (uint32_t)(ch * 128 + ks * 32);
            uint32_t ah[4], al[4], bh[8], bl[8];
            ldsm4(ah, ahb + ka);
            ldsm4(al, alb + ka);
            ldsm4(bh,     bh0 + kz);
            ldsm4(bh + 4, bh1 + kz);
            ldsm4(bl,     bl0 + kz);
            ldsm4(bl + 4, bl1 + kz);
#pragma unroll
            for (int nt = 0; nt < 4; nt++) {
                mma_f16(acc[nt], ah, bh[nt * 2], bh[nt * 2 + 1]);
                mma_f16(acc[nt], ah, bl[nt * 2], bl[nt * 2 + 1]);
                mma_f16(acc[nt], al, bh[nt * 2], bh[nt * 2 + 1]);
            }
        }

        if (ch < 7) {
            __syncthreads();   // everyone done reading a tile
            __half* dh = (__half*)(smem + OFF_AH);
            __half* dl = (__half*)(smem + OFF_AL);
#pragma unroll
            for (int t = 0; t < 8; t++) {
                int row = prow + 16 * t;
                unsigned short hp[4], lp[4];
                fsplit(pf[t].x, hp[0], lp[0]); fsplit(pf[t].y, hp[1], lp[1]);
                fsplit(pf[t].z, hp[2], lp[2]); fsplit(pf[t].w, hp[3], lp[3]);
                *(uint2*)&dh[row * ASTR + pc4] = *(uint2*)hp;
                *(uint2*)&dl[row * ASTR + pc4] = *(uint2*)lp;
            }
            __syncthreads();   // a tile ready for next MMA round
        }
    }

    // ---- epilogue ----
    const int g  = lane >> 2, t2 = (lane & 3) * 2;
    const int lr0 = wid * 16 + g, lr1 = lr0 + 8;
    const int gm0 = gidx[lr0], gm1 = gidx[lr1];
    const float* u0 = &u[((size_t)b * NNODE + gm0) * HDIM];
    const float* u1 = &u[((size_t)b * NNODE + gm1) * HDIM];
    float* o0 = out + (out_compact
               ? ((size_t)b * rows_out + m0 + lr0) * HDIM
               : ((size_t)b * NNODE + gm0) * HDIM);
    float* o1 = out + (out_compact
               ? ((size_t)b * rows_out + m0 + lr1) * HDIM
               : ((size_t)b * NNODE + gm1) * HDIM);
#pragma unroll
    for (int nt = 0; nt < 4; nt++) {
        int c = nt * 8 + t2;
        float2 uv0 = *(const float2*)&u0[c];
        float2 uv1 = *(const float2*)&u1[c];
        float2 r0, r1;
        r0.x = fmaxf(acc[nt][0] + uv0.x, 0.f);
        r0.y = fmaxf(acc[nt][1] + uv0.y, 0.f);
        r1.x = fmaxf(acc[nt][2] + uv1.x, 0.f);
        r1.y = fmaxf(acc[nt][3] + uv1.y, 0.f);
        *(float2*)&o0[c] = r0;
        *(float2*)&o1[c] = r1;
    }
}

// ---------------------------------------------------------------------------
// TopK: exact jax.lax.top_k set semantics via rank counting; ballot-based
// prefix compaction (deterministic ascending order).
// ---------------------------------------------------------------------------
__global__ __launch_bounds__(256) void k_topk(
    const float* __restrict__ hfeat, const float* __restrict__ p,
    const float* __restrict__ prevgate, float* __restrict__ gate_out,
    int* __restrict__ idx_out, int k)
{
    __shared__ float ysh[NNODE];
    __shared__ float pn[HDIM];
    __shared__ int wcnt[16], woff[16];
    const int tid = threadIdx.x;
    const int b   = blockIdx.x;
    const int lane = tid & 31, w = tid >> 5;

    if (tid == 0) {
        float s = 0.f;
        for (int h = 0; h < HDIM; h++) s += p[h] * p[h];
        s = rsqrtf(s);
        for (int h = 0; h < HDIM; h++) pn[h] = p[h] * s;
    }
    __syncthreads();

    for (int r = w; r < NNODE; r += 8) {
        float v = hfeat[((size_t)b * NNODE + r) * HDIM + lane] * pn[lane];
#pragma unroll
        for (int s = 16; s > 0; s >>= 1) v += __shfl_xor_sync(0xffffffffu, v, s);
        if (lane == 0) {
            bool valid = (prevgate == nullptr) ||
                         (prevgate[(size_t)b * NNODE + r] > 0.f);
            ysh[r] = valid ? v : -1e30f;
        }
    }
    __syncthreads();

    const int r0 = tid, r1 = tid + 256;
    float y0 = ysh[r0], y1 = ysh[r1];
    int rank0 = 0, rank1 = 0;
    for (int j = 0; j < NNODE; j++) {
        float yj = ysh[j];
        rank0 += (yj > y0) || (yj == y0 && j < r0);
        rank1 += (yj > y1) || (yj == y1 && j < r1);
    }
    int sel0 = rank0 < k, sel1 = rank1 < k;
    gate_out[(size_t)b * NNODE + r0] = sel0 ? (1.f / (1.f + expf(-y0))) : 0.f;
    gate_out[(size_t)b * NNODE + r1] = sel1 ? (1.f / (1.f + expf(-y1))) : 0.f;

    uint32_t m0 = __ballot_sync(0xffffffffu, sel0);
    uint32_t m1 = __ballot_sync(0xffffffffu, sel1);
    if (lane == 0) { wcnt[w] = __popc(m0); wcnt[8 + w] = __popc(m1); }
    __syncthreads();
    if (tid < 16) {
        int v = wcnt[tid];
        int x = v;
#pragma unroll
        for (int s = 1; s < 16; s <<= 1) {
            int t = __shfl_up_sync(0x0000ffffu, x, s);
            if (tid >= s) x += t;
        }
        woff[tid] = x - v;
    }
    __syncthreads();
    uint32_t lmask = (1u << lane) - 1u;
    if (sel0) idx_out[b * k + woff[w]     + __popc(m0 & lmask)] = r0;
    if (sel1) idx_out[b * k + woff[8 + w] + __popc(m1 & lmask)] = r1;
}

// ---------------------------------------------------------------------------
// Final: mean over 128 nodes -> dense [32,16] + bias -> softmax(16).
// ---------------------------------------------------------------------------
__global__ __launch_bounds__(128) void k_final(
    const float* __restrict__ h3, const float* __restrict__ wd,
    const float* __restrict__ bd, float* __restrict__ out)
{
    __shared__ float ps[4][HDIM];
    __shared__ float pooled[HDIM];
    __shared__ float logits[CDIM];
    const int tid = threadIdx.x;
    const int b   = blockIdx.x;
    const int c = tid & 31, seg = tid >> 5;

    float s = 0.f;
    for (int i = seg * 32; i < seg * 32 + 32; i++)
        s += h3[((size_t)b * KSEL2 + i) * HDIM + c];
    ps[seg][c] = s;
    __syncthreads();
    if (tid < HDIM)
        pooled[tid] = (ps[0][tid] + ps[1][tid] + ps[2][tid] + ps[3][tid]) *
                      (1.f / (float)KSEL2);
    __syncthreads();
    if (tid < CDIM) {
        float l = bd[tid];
        for (int h = 0; h < HDIM; h++) l += pooled[h] * wd[h * CDIM + tid];
        logits[tid] = l;
    }
    __syncthreads();
    if (tid < CDIM) {
        float mx = -1e30f;
        for (int j = 0; j < CDIM; j++) mx = fmaxf(mx, logits[j]);
        float den = 0.f;
        for (int j = 0; j < CDIM; j++) den += expf(logits[j] - mx);
        out[b * CDIM + tid] = expf(logits[tid] - mx) / den;
    }
}

// ---------------------------------------------------------------------------
extern "C" void kernel_launch(void* const* d_in, const int* in_sizes, int n_in,
                              void* d_out, int out_size)
{
    (void)in_sizes; (void)n_in; (void)out_size;
    const float* x    = (const float*)d_in[0];
    const float* a    = (const float*)d_in[1];
    const float* w1_1 = (const float*)d_in[2];
    const float* w2_1 = (const float*)d_in[3];
    const float* b1   = (const float*)d_in[4];
    const float* w1_2 = (const float*)d_in[5];
    const float* w2_2 = (const float*)d_in[6];
    const float* b2   = (const float*)d_in[7];
    const float* w1_3 = (const float*)d_in[8];
    const float* w2_3 = (const float*)d_in[9];
    const float* b3   = (const float*)d_in[10];
    const float* pp   = (const float*)d_in[11];
    const float* wd   = (const float*)d_in[12];
    const float* bd   = (const float*)d_in[13];
    float* out = (float*)d_out;

    __half *zh, *zl;
    float *u1, *u2, *u3, *h1, *h2, *h3, *gate1, *gate2;
    int *idx1, *idx2;
    cudaGetSymbolAddress((void**)&zh, g_zh);
    cudaGetSymbolAddress((void**)&zl, g_zl);
    cudaGetSymbolAddress((void**)&u1, g_u1);
    cudaGetSymbolAddress((void**)&u2, g_u2);
    cudaGetSymbolAddress((void**)&u3, g_u3);
    cudaGetSymbolAddress((void**)&h1, g_h1);
    cudaGetSymbolAddress((void**)&h2, g_h2);
    cudaGetSymbolAddress((void**)&h3, g_h3);
    cudaGetSymbolAddress((void**)&gate1, g_gate1);
    cudaGetSymbolAddress((void**)&gate2, g_gate2);
    cudaGetSymbolAddress((void**)&idx1, g_idx1);
    cudaGetSymbolAddress((void**)&idx2, g_idx2);

    cudaFuncSetAttribute(k_aZ_mma, cudaFuncAttributeMaxDynamicSharedMemorySize,
                         SMEM_AZ);
    cudaFuncSetAttribute(k_xw, cudaFuncAttributeMaxDynamicSharedMemorySize,
                         XW_SMEM);

    // conv1
    k_xw<<<(BATCH * NNODE) / 128, 256, XW_SMEM>>>(x, w1_1, w2_1, b1, zh, zl, u1);
    k_aZ_mma<<<dim3(NNODE / 128, BATCH), 256, SMEM_AZ>>>(
        a, zh, zl, u1, h1, nullptr, NNODE, 0);
    // pool1
    k_topk<<<BATCH, 256>>>(h1, pp, nullptr, gate1, idx1, KSEL1);
    // conv2 (scatter-z / gather-rows: z rows are zero at dropped nodes)
    k_gxw<<<(BATCH * NNODE) / 128, 256>>>(h1, gate1, w1_2, w2_2, b2, zh, zl, u2);
    k_aZ_mma<<<dim3(KSEL1 / 128, BATCH), 256, SMEM_AZ>>>(
        a, zh, zl, u2, h2, idx1, KSEL1, 0);
    // pool2
    k_topk<<<BATCH, 256>>>(h2, pp, gate1, gate2, idx2, KSEL2);
    // conv3
    k_gxw<<<(BATCH * NNODE) / 128, 256>>>(h2, gate2, w1_3, w2_3, b3, zh, zl, u3);
    k_aZ_mma<<<dim3(KSEL2 / 128, BATCH), 256, SMEM_AZ>>>(
        a, zh, zl, u3, h3, idx2, KSEL2, 1);
    // global mean pool + dense + softmax
    k_final<<<BATCH, 128>>>(h3, wd, bd, out);
}

// round 12
// speedup vs baseline: 1.7486x; 1.1505x over previous
#include <cuda_runtime.h>
#include <cuda_fp16.h>
#include <math.h>
#include <stdint.h>

#define BATCH 256
#define NNODE 512
#define FDIM  128
#define HDIM  32
#define CDIM  16
#define KSEL1 256
#define KSEL2 128

// ---------------- scratch (device globals: no allocation allowed) ----------
__device__ __half g_zh[BATCH * HDIM * NNODE];   // z^T hi; compact stride per stage
__device__ __half g_zl[BATCH * HDIM * NNODE];   // z^T lo
__device__ float g_u1[BATCH * NNODE * HDIM];
__device__ float g_u2[BATCH * NNODE * HDIM];
__device__ float g_u3[BATCH * NNODE * HDIM];
__device__ float g_h1[BATCH * NNODE * HDIM];
__device__ float g_h2[BATCH * NNODE * HDIM];
__device__ float g_h3[BATCH * KSEL2 * HDIM];
__device__ float g_gate1[BATCH * NNODE];
__device__ float g_gate2[BATCH * NNODE];
__device__ int   g_idx1[BATCH * KSEL1];
__device__ int   g_idx2[BATCH * KSEL2];

// ======================= warp-MMA helpers (generic PTX) =====================
__device__ __forceinline__ uint32_t smem_u32(const void* p) {
    uint32_t a;
    asm("{ .reg .u64 t; cvta.to.shared.u64 t, %1; cvt.u32.u64 %0, t; }"
        : "=r"(a) : "l"(p));
    return a;
}
__device__ __forceinline__ void ldsm4(uint32_t* r, uint32_t addr) {
    asm volatile(
        "ldmatrix.sync.aligned.m8n8.x4.shared.b16 {%0,%1,%2,%3}, [%4];"
        : "=r"(r[0]), "=r"(r[1]), "=r"(r[2]), "=r"(r[3]) : "r"(addr));
}
__device__ __forceinline__ void mma_f16(float* c, const uint32_t* a,
                                        uint32_t b0, uint32_t b1) {
    asm volatile(
        "mma.sync.aligned.m16n8k16.row.col.f32.f16.f16.f32 "
        "{%0,%1,%2,%3}, {%4,%5,%6,%7}, {%8,%9}, {%0,%1,%2,%3};"
        : "+f"(c[0]), "+f"(c[1]), "+f"(c[2]), "+f"(c[3])
        : "r"(a[0]), "r"(a[1]), "r"(a[2]), "r"(a[3]), "r"(b0), "r"(b1));
}
#define CP16(dst, src) \
    asm volatile("cp.async.cg.shared.global [%0], [%1], 16;" \
                 :: "r"(dst), "l"(src))
#define CP_COMMIT() asm volatile("cp.async.commit_group;" ::: "memory")
#define CP_WAIT0()  asm volatile("cp.async.wait_group 0;" ::: "memory")

// split fp32 -> fp16 hi/lo (hi+lo carries ~22 mantissa bits)
__device__ __forceinline__ void fsplit(float v, unsigned short& h,
                                       unsigned short& l) {
    __half hb = __float2half(v);
    float hf = __half2float(hb);
    __half lb = __float2half(v - hf);
    h = *(unsigned short*)&hb;
    l = *(unsigned short*)&lb;
}

// ---------------------------------------------------------------------------
// G1 (MMA): z = x @ w1, u = x @ w2 + bias, fp16 3-product.
// zT full-N stored split fp16 (stride NNODE). Tile 128 x 64, K=128.
// ---------------------------------------------------------------------------
#define XW_XH   0
#define XW_XL   34816
#define XW_WTH  69632
#define XW_WTL  87040
#define XW_SMEM 104448

__global__ __launch_bounds__(256, 2) void k_xw(
    const float* __restrict__ x, const float* __restrict__ w1,
    const float* __restrict__ w2, const float* __restrict__ bias,
    __half* __restrict__ zh, __half* __restrict__ zl,
    float* __restrict__ uout)
{
    extern __shared__ char smem[];
    const uint32_t sb = smem_u32(smem);
    const int tid = threadIdx.x, wid = tid >> 5, lane = tid & 31;
    const int m0 = blockIdx.x * 128;
    __half* XH  = (__half*)(smem + XW_XH);
    __half* XL  = (__half*)(smem + XW_XL);
    __half* WTH = (__half*)(smem + XW_WTH);
    __half* WTL = (__half*)(smem + XW_WTL);

#pragma unroll
    for (int t = 0; t < 32; t++) {
        int e = tid + 256 * t;
        int n = e >> 7, k = e & 127;
        float w = (n < 32) ? w1[k * HDIM + n] : w2[k * HDIM + (n - 32)];
        unsigned short hh, ll;
        fsplit(w, hh, ll);
        WTH[n * 136 + k] = *(__half*)&hh;
        WTL[n * 136 + k] = *(__half*)&ll;
    }
#pragma unroll
    for (int t = 0; t < 16; t++) {
        int e = tid + 256 * t;
        int r = e >> 5, c4 = (e & 31) * 4;
        float4 v = *(const float4*)&x[(size_t)(m0 + r) * FDIM + c4];
        unsigned short hp[4], lp[4];
        fsplit(v.x, hp[0], lp[0]); fsplit(v.y, hp[1], lp[1]);
        fsplit(v.z, hp[2], lp[2]); fsplit(v.w, hp[3], lp[3]);
        *(uint2*)&XH[r * 136 + c4] = *(uint2*)hp;
        *(uint2*)&XL[r * 136 + c4] = *(uint2*)lp;
    }
    __syncthreads();

    float acc[8][4];
#pragma unroll
    for (int i = 0; i < 8; i++)
#pragma unroll
        for (int j = 0; j < 4; j++) acc[i][j] = 0.f;

    const int g8 = lane >> 3, r8 = lane & 7;
    const int a_row = wid * 16 + ((g8 & 1) ? 8 : 0) + r8;
    const uint32_t a_off = (uint32_t)a_row * 272 + ((g8 >= 2) ? 16 : 0);
    const uint32_t ah_base = sb + XW_XH + a_off;
    const uint32_t al_base = sb + XW_XL + a_off;
    const int b_rowoff = ((g8 >> 1) ? 8 : 0) + r8;
    const uint32_t b_off = (uint32_t)b_rowoff * 272 + ((g8 & 1) ? 16 : 0);
    const uint32_t bh_base = sb + XW_WTH + b_off;
    const uint32_t bl_base = sb + XW_WTL + b_off;

#pragma unroll
    for (int ks = 0; ks < 8; ks++) {
        const uint32_t ka = (uint32_t)ks * 32;
        uint32_t ah[4], al[4], bh[16], bl[16];
        ldsm4(ah, ah_base + ka);
        ldsm4(al, al_base + ka);
#pragma unroll
        for (int q = 0; q < 4; q++) {
            ldsm4(bh + 4 * q, bh_base + (uint32_t)q * 16 * 272 + ka);
            ldsm4(bl + 4 * q, bl_base + (uint32_t)q * 16 * 272 + ka);
        }
#pragma unroll
        for (int nt = 0; nt < 8; nt++) {
            mma_f16(acc[nt], ah, bh[nt * 2], bh[nt * 2 + 1]);
            mma_f16(acc[nt], ah, bl[nt * 2], bl[nt * 2 + 1]);
            mma_f16(acc[nt], al, bh[nt * 2], bh[nt * 2 + 1]);
        }
    }
    __syncthreads();

    __half* zts_h = (__half*)smem;              // [32 cols][136 rows]
    __half* zts_l = zts_h + 32 * 136;
    const int g = lane >> 2, t2 = (lane & 3) * 2;
    const int r0l = wid * 16 + g, r1l = r0l + 8;

#pragma unroll
    for (int nt = 0; nt < 4; nt++) {
        int c = nt * 8 + t2;
        unsigned short hh, ll;
        fsplit(acc[nt][0], hh, ll);
        zts_h[c * 136 + r0l] = *(__half*)&hh; zts_l[c * 136 + r0l] = *(__half*)&ll;
        fsplit(acc[nt][1], hh, ll);
        zts_h[(c + 1) * 136 + r0l] = *(__half*)&hh; zts_l[(c + 1) * 136 + r0l] = *(__half*)&ll;
        fsplit(acc[nt][2], hh, ll);
        zts_h[c * 136 + r1l] = *(__half*)&hh; zts_l[c * 136 + r1l] = *(__half*)&ll;
        fsplit(acc[nt][3], hh, ll);
        zts_h[(c + 1) * 136 + r1l] = *(__half*)&hh; zts_l[(c + 1) * 136 + r1l] = *(__half*)&ll;
    }
#pragma unroll
    for (int nt = 4; nt < 8; nt++) {
        int c = (nt - 4) * 8 + t2;
        float2 bv = *(const float2*)&bias[c];
        int gr0 = m0 + r0l, gr1 = m0 + r1l;
        float2 v0 = make_float2(acc[nt][0] + bv.x, acc[nt][1] + bv.y);
        float2 v1 = make_float2(acc[nt][2] + bv.x, acc[nt][3] + bv.y);
        *(float2*)&uout[(size_t)gr0 * HDIM + c] = v0;
        *(float2*)&uout[(size_t)gr1 * HDIM + c] = v1;
    }
    __syncthreads();
    {
        int b_ = m0 >> 9, r0g = m0 & (NNODE - 1);
#pragma unroll
        for (int it = 0; it < 2; it++) {
            int e = tid + 256 * it;
            int col = e >> 4, seg = e & 15;
            size_t gb = ((size_t)(b_ * HDIM + col)) * NNODE + r0g + seg * 8;
            *(uint4*)&zh[gb] = *(uint4*)&zts_h[col * 136 + seg * 8];
            *(uint4*)&zl[gb] = *(uint4*)&zts_l[col * 136 + seg * 8];
        }
    }
}

// ---------------------------------------------------------------------------
// G3/G5 compact (MMA): processes 128 COMPACT rows (rid from idx list).
// z written compact transposed [B][32][ksel]; u written full-layout at
// selected rows. fp16 3-product.
// ---------------------------------------------------------------------------
#define GX_AH   0
#define GX_AL   10240
#define GX_WTH  20480
#define GX_WTL  25600
#define GX_RID  30720     // 128 ints
#define GX_SMEM 31232

__global__ __launch_bounds__(256) void k_gxw_c(
    const float* __restrict__ hfeat, const float* __restrict__ gate,
    const int* __restrict__ idx, int ksel, int kslog,
    const float* __restrict__ w1, const float* __restrict__ w2,
    const float* __restrict__ bias,
    __half* __restrict__ zh, __half* __restrict__ zl,
    float* __restrict__ uout)
{
    __shared__ __align__(16) char smem[GX_SMEM];
    const uint32_t sb = smem_u32(smem);
    const int tid = threadIdx.x, wid = tid >> 5, lane = tid & 31;
    const int jg = blockIdx.x * 128;
    const int b  = jg >> kslog;
    const int j0 = jg & (ksel - 1);
    __half* AH  = (__half*)(smem + GX_AH);
    __half* AL  = (__half*)(smem + GX_AL);
    __half* WTH = (__half*)(smem + GX_WTH);
    __half* WTL = (__half*)(smem + GX_WTL);
    int* rid = (int*)(smem + GX_RID);

    if (tid < 128) rid[tid] = idx[b * ksel + j0 + tid];
#pragma unroll
    for (int t = 0; t < 8; t++) {
        int e = tid + 256 * t;
        int n = e >> 5, kk = e & 31;
        float w = (n < 32) ? w1[kk * HDIM + n] : w2[kk * HDIM + (n - 32)];
        unsigned short hh, ll;
        fsplit(w, hh, ll);
        WTH[n * 40 + kk] = *(__half*)&hh;
        WTL[n * 40 + kk] = *(__half*)&ll;
    }
    __syncthreads();
#pragma unroll
    for (int t = 0; t < 4; t++) {
        int e = tid + 256 * t;
        int r = e >> 3, c4 = (e & 7) * 4;
        int gr = b * NNODE + rid[r];
        float g = gate[gr];
        float4 v = *(const float4*)&hfeat[(size_t)gr * HDIM + c4];
        v.x *= g; v.y *= g; v.z *= g; v.w *= g;
        unsigned short hp[4], lp[4];
        fsplit(v.x, hp[0], lp[0]); fsplit(v.y, hp[1], lp[1]);
        fsplit(v.z, hp[2], lp[2]); fsplit(v.w, hp[3], lp[3]);
        *(uint2*)&AH[r * 40 + c4] = *(uint2*)hp;
        *(uint2*)&AL[r * 40 + c4] = *(uint2*)lp;
    }
    __syncthreads();

    float acc[8][4];
#pragma unroll
    for (int i = 0; i < 8; i++)
#pragma unroll
        for (int j = 0; j < 4; j++) acc[i][j] = 0.f;

    const int g8 = lane >> 3, r8 = lane & 7;
    const int a_row = wid * 16 + ((g8 & 1) ? 8 : 0) + r8;
    const uint32_t a_off = (uint32_t)a_row * 80 + ((g8 >= 2) ? 16 : 0);
    const uint32_t ahb = sb + GX_AH + a_off;
    const uint32_t alb = sb + GX_AL + a_off;
    const int b_rowoff = ((g8 >> 1) ? 8 : 0) + r8;
    const uint32_t b_off = (uint32_t)b_rowoff * 80 + ((g8 & 1) ? 16 : 0);
    const uint32_t bhb = sb + GX_WTH + b_off;
    const uint32_t blb = sb + GX_WTL + b_off;

#pragma unroll
    for (int ks = 0; ks < 2; ks++) {
        const uint32_t ka = (uint32_t)ks * 32;
        uint32_t ah[4], al[4], bh[16], bl[16];
        ldsm4(ah, ahb + ka);
        ldsm4(al, alb + ka);
#pragma unroll
        for (int q = 0; q < 4; q++) {
            ldsm4(bh + 4 * q, bhb + (uint32_t)q * 16 * 80 + ka);
            ldsm4(bl + 4 * q, blb + (uint32_t)q * 16 * 80 + ka);
        }
#pragma unroll
        for (int nt = 0; nt < 8; nt++) {
            mma_f16(acc[nt], ah, bh[nt * 2], bh[nt * 2 + 1]);
            mma_f16(acc[nt], ah, bl[nt * 2], bl[nt * 2 + 1]);
            mma_f16(acc[nt], al, bh[nt * 2], bh[nt * 2 + 1]);
        }
    }
    __syncthreads();   // SMEM tile reads done -> reuse AH..WTL area for staging

    __half* zts_h = (__half*)smem;              // [32 cols][136 rows] 17408B
    __half* zts_l = zts_h + 32 * 136;           // (fits in first 30720B? 2*8704=17408... )
    const int g = lane >> 2, t2 = (lane & 3) * 2;
    const int r0l = wid * 16 + g, r1l = r0l + 8;

#pragma unroll
    for (int nt = 0; nt < 4; nt++) {
        int c = nt * 8 + t2;
        unsigned short hh, ll;
        fsplit(acc[nt][0], hh, ll);
        zts_h[c * 136 + r0l] = *(__half*)&hh; zts_l[c * 136 + r0l] = *(__half*)&ll;
        fsplit(acc[nt][1], hh, ll);
        zts_h[(c + 1) * 136 + r0l] = *(__half*)&hh; zts_l[(c + 1) * 136 + r0l] = *(__half*)&ll;
        fsplit(acc[nt][2], hh, ll);
        zts_h[c * 136 + r1l] = *(__half*)&hh; zts_l[c * 136 + r1l] = *(__half*)&ll;
        fsplit(acc[nt][3], hh, ll);
        zts_h[(c + 1) * 136 + r1l] = *(__half*)&hh; zts_l[(c + 1) * 136 + r1l] = *(__half*)&ll;
    }
#pragma unroll
    for (int nt = 4; nt < 8; nt++) {
        int c = (nt - 4) * 8 + t2;
        float2 bv = *(const float2*)&bias[c];
        int gr0 = b * NNODE + rid[r0l], gr1 = b * NNODE + rid[r1l];
        float2 v0 = make_float2(acc[nt][0] + bv.x, acc[nt][1] + bv.y);
        float2 v1 = make_float2(acc[nt][2] + bv.x, acc[nt][3] + bv.y);
        *(float2*)&uout[(size_t)gr0 * HDIM + c] = v0;
        *(float2*)&uout[(size_t)gr1 * HDIM + c] = v1;
    }
    __syncthreads();
    {   // compact transposed z store: stride ksel
#pragma unroll
        for (int it = 0; it < 2; it++) {
            int e = tid + 256 * it;
            int col = e >> 4, seg = e & 15;
            size_t gb = ((size_t)(b * HDIM + col)) * ksel + j0 + seg * 8;
            *(uint4*)&zh[gb] = *(uint4*)&zts_h[col * 136 + seg * 8];
            *(uint4*)&zl[gb] = *(uint4*)&zts_l[col * 136 + seg * 8];
        }
    }
}

// ---------------------------------------------------------------------------
// fp16 MMA a@z, runtime-K: 3-product, z-resident SMEM (stride klen+8),
// register-prefetched a chunks (contiguous or kid-gathered), 2 CTAs/SM.
// out[rows] = relu( a[b,gidx(row), kid(.)] @ zc[b] + u[b,gidx(row)] )
// ---------------------------------------------------------------------------
#define ASTR   72       // a fp16 tile row stride (144B)
#define AZ_SMEM_MAX 105984

__global__ __launch_bounds__(256, 2) void k_aZ_mma(
    const float* __restrict__ a, const __half* __restrict__ zh,
    const __half* __restrict__ zl, const float* __restrict__ u,
    float* __restrict__ out, const int* __restrict__ ridx,
    const int* __restrict__ kidx, int rows_out, int klen, int out_compact)
{
    extern __shared__ char smem[];
    const uint32_t sb = smem_u32(smem);
    const int tid = threadIdx.x, wid = tid >> 5, lane = tid & 31;
    const int b  = blockIdx.y;
    const int m0 = blockIdx.x * 128;

    const int zr = klen + 8;                 // halves
    const uint32_t zbytes = 64u * (uint32_t)zr;   // 32 rows * zr * 2B
    const uint32_t off_zl = zbytes;
    const uint32_t off_ah = 2u * zbytes;
    const uint32_t off_al = off_ah + 18432;
    const uint32_t off_gidx = off_al + 18432;
    const uint32_t off_kid  = off_gidx + 512;
    int* gidx = (int*)(smem + off_gidx);
    int* kid  = (int*)(smem + off_kid);

    if (tid < 128)
        gidx[tid] = ridx ? ridx[b * rows_out + m0 + tid] : (m0 + tid);
    if (kidx)
        for (int i = tid; i < klen; i += 256) kid[i] = kidx[b * klen + i];
    __syncthreads();

    const float* ab = a + (size_t)b * NNODE * NNODE;
    const __half* zhb = zh + (size_t)b * HDIM * klen;
    const __half* zlb = zl + (size_t)b * HDIM * klen;

    // ---- z resident load (async): 32 rows x klen halves, 16B units ----
    const int k8 = klen >> 3;                // 16B units per row
    const int kshift = 31 - __clz(k8);
    const int zit = klen >> 6;               // per-thread iterations
    for (int t = 0; t < zit; t++) {
        int i = tid + 256 * t;
        int r = i >> kshift, c = i & (k8 - 1);
        uint32_t doff = (uint32_t)r * (zr * 2) + c * 16;
        CP16(sb + doff,          zhb + (size_t)r * klen + c * 8);
        CP16(sb + off_zl + doff, zlb + (size_t)r * klen + c * 8);
    }
    CP_COMMIT();

    const int prow = tid >> 4;
    const int pc4  = (tid & 15) * 4;
    const int nch  = klen >> 6;

    // ---- a chunk 0: LDG (contig or gather) -> regs ----
    float4 pf[8];
#pragma unroll
    for (int t = 0; t < 8; t++) {
        const float* rp = ab + (size_t)gidx[prow + 16 * t] * NNODE;
        if (kidx) {
            pf[t].x = rp[kid[pc4 + 0]]; pf[t].y = rp[kid[pc4 + 1]];
            pf[t].z = rp[kid[pc4 + 2]]; pf[t].w = rp[kid[pc4 + 3]];
        } else {
            pf[t] = *(const float4*)&rp[pc4];
        }
    }
    {
        __half* dh = (__half*)(smem + off_ah);
        __half* dl = (__half*)(smem + off_al);
#pragma unroll
        for (int t = 0; t < 8; t++) {
            int row = prow + 16 * t;
            unsigned short hp[4], lp[4];
            fsplit(pf[t].x, hp[0], lp[0]); fsplit(pf[t].y, hp[1], lp[1]);
            fsplit(pf[t].z, hp[2], lp[2]); fsplit(pf[t].w, hp[3], lp[3]);
            *(uint2*)&dh[row * ASTR + pc4] = *(uint2*)hp;
            *(uint2*)&dl[row * ASTR + pc4] = *(uint2*)lp;
        }
    }
    CP_WAIT0();
    __syncthreads();

    float acc[4][4];
#pragma unroll
    for (int i = 0; i < 4; i++)
#pragma unroll
        for (int j = 0; j < 4; j++) acc[i][j] = 0.f;

    const int g8 = lane >> 3, r8 = lane & 7;
    const int a_row = wid * 16 + ((g8 & 1) ? 8 : 0) + r8;
    const uint32_t a_off = (uint32_t)a_row * (ASTR * 2) + ((g8 >= 2) ? 16 : 0);
    const uint32_t ahb = sb + off_ah + a_off;
    const uint32_t alb = sb + off_al + a_off;
    const int b_rowoff = ((g8 >> 1) ? 8 : 0) + r8;
    const uint32_t b_colB = (g8 & 1) ? 16 : 0;
    const uint32_t bh0 = sb +          (uint32_t)b_rowoff * (zr * 2) + b_colB;
    const uint32_t bh1 = sb +          (uint32_t)(16 + b_rowoff) * (zr * 2) + b_colB;
    const uint32_t bl0 = sb + off_zl + (uint32_t)b_rowoff * (zr * 2) + b_colB;
    const uint32_t bl1 = sb + off_zl + (uint32_t)(16 + b_rowoff) * (zr * 2) + b_colB;

    for (int ch = 0; ch < nch; ch++) {
        if (ch < nch - 1) {
            const int k0 = (ch + 1) * 64;
#pragma unroll
            for (int t = 0; t < 8; t++) {
                const float* rp = ab + (size_t)gidx[prow + 16 * t] * NNODE;
                if (kidx) {
                    pf[t].x = rp[kid[k0 + pc4 + 0]];
                    pf[t].y = rp[kid[k0 + pc4 + 1]];
                    pf[t].z = rp[kid[k0 + pc4 + 2]];
                    pf[t].w = rp[kid[k0 + pc4 + 3]];
                } else {
                    pf[t] = *(const float4*)&rp[k0 + pc4];
                }
            }
        }

#pragma unroll
        for (int ks = 0; ks < 4; ks++) {
            const uint32_t ka = (uint32_t)ks * 32;
            const uint32_t kz = (uint32_t)(ch * 128 + ks * 32);
            uint32_t ah[4], al[4], bh[8], bl[8];
            ldsm4(ah, ahb + ka);
            ldsm4(al, alb + ka);
            ldsm4(bh,     bh0 + kz);
            ldsm4(bh + 4, bh1 + kz);
            ldsm4(bl,     bl0 + kz);
            ldsm4(bl + 4, bl1 + kz);
#pragma unroll
            for (int nt = 0; nt < 4; nt++) {
                mma_f16(acc[nt], ah, bh[nt * 2], bh[nt * 2 + 1]);
                mma_f16(acc[nt], ah, bl[nt * 2], bl[nt * 2 + 1]);
                mma_f16(acc[nt], al, bh[nt * 2], bh[nt * 2 + 1]);
            }
        }

        if (ch < nch - 1) {
            __syncthreads();
            __half* dh = (__half*)(smem + off_ah);
            __half* dl = (__half*)(smem + off_al);
#pragma unroll
            for (int t = 0; t < 8; t++) {
                int row = prow + 16 * t;
                unsigned short hp[4], lp[4];
                fsplit(pf[t].x, hp[0], lp[0]); fsplit(pf[t].y, hp[1], lp[1]);
                fsplit(pf[t].z, hp[2], lp[2]); fsplit(pf[t].w, hp[3], lp[3]);
                *(uint2*)&dh[row * ASTR + pc4] = *(uint2*)hp;
                *(uint2*)&dl[row * ASTR + pc4] = *(uint2*)lp;
            }
            __syncthreads();
        }
    }

    // ---- epilogue ----
    const int g  = lane >> 2, t2 = (lane & 3) * 2;
    const int lr0 = wid * 16 + g, lr1 = lr0 + 8;
    const int gm0 = gidx[lr0], gm1 = gidx[lr1];
    const float* u0 = &u[((size_t)b * NNODE + gm0) * HDIM];
    const float* u1 = &u[((size_t)b * NNODE + gm1) * HDIM];
    float* o0 = out + (out_compact
               ? ((size_t)b * rows_out + m0 + lr0) * HDIM
               : ((size_t)b * NNODE + gm0) * HDIM);
    float* o1 = out + (out_compact
               ? ((size_t)b * rows_out + m0 + lr1) * HDIM
               : ((size_t)b * NNODE + gm1) * HDIM);
#pragma unroll
    for (int nt = 0; nt < 4; nt++) {
        int c = nt * 8 + t2;
        float2 uv0 = *(const float2*)&u0[c];
        float2 uv1 = *(const float2*)&u1[c];
        float2 r0, r1;
        r0.x = fmaxf(acc[nt][0] + uv0.x, 0.f);
        r0.y = fmaxf(acc[nt][1] + uv0.y, 0.f);
        r1.x = fmaxf(acc[nt][2] + uv1.x, 0.f);
        r1.y = fmaxf(acc[nt][3] + uv1.y, 0.f);
        *(float2*)&o0[c] = r0;
        *(float2*)&o1[c] = r1;
    }
}

// ---------------------------------------------------------------------------
// TopK: exact jax.lax.top_k set semantics via rank counting; ballot prefix.
// ---------------------------------------------------------------------------
__global__ __launch_bounds__(256) void k_topk(
    const float* __restrict__ hfeat, const float* __restrict__ p,
    const float* __restrict__ prevgate, float* __restrict__ gate_out,
    int* __restrict__ idx_out, int k)
{
    __shared__ float ysh[NNODE];
    __shared__ float pn[HDIM];
    __shared__ int wcnt[16], woff[16];
    const int tid = threadIdx.x;
    const int b   = blockIdx.x;
    const int lane = tid & 31, w = tid >> 5;

    if (tid == 0) {
        float s = 0.f;
        for (int h = 0; h < HDIM; h++) s += p[h] * p[h];
        s = rsqrtf(s);
        for (int h = 0; h < HDIM; h++) pn[h] = p[h] * s;
    }
    __syncthreads();

    for (int r = w; r < NNODE; r += 8) {
        float v = hfeat[((size_t)b * NNODE + r) * HDIM + lane] * pn[lane];
#pragma unroll
        for (int s = 16; s > 0; s >>= 1) v += __shfl_xor_sync(0xffffffffu, v, s);
        if (lane == 0) {
            bool valid = (prevgate == nullptr) ||
                         (prevgate[(size_t)b * NNODE + r] > 0.f);
            ysh[r] = valid ? v : -1e30f;
        }
    }
    __syncthreads();

    const int r0 = tid, r1 = tid + 256;
    float y0 = ysh[r0], y1 = ysh[r1];
    int rank0 = 0, rank1 = 0;
    for (int j = 0; j < NNODE; j++) {
        float yj = ysh[j];
        rank0 += (yj > y0) || (yj == y0 && j < r0);
        rank1 += (yj > y1) || (yj == y1 && j < r1);
    }
    int sel0 = rank0 < k, sel1 = rank1 < k;
    gate_out[(size_t)b * NNODE + r0] = sel0 ? (1.f / (1.f + expf(-y0))) : 0.f;
    gate_out[(size_t)b * NNODE + r1] = sel1 ? (1.f / (1.f + expf(-y1))) : 0.f;

    uint32_t m0 = __ballot_sync(0xffffffffu, sel0);
    uint32_t m1 = __ballot_sync(0xffffffffu, sel1);
    if (lane == 0) { wcnt[w] = __popc(m0); wcnt[8 + w] = __popc(m1); }
    __syncthreads();
    if (tid < 16) {
        int v = wcnt[tid];
        int x = v;
#pragma unroll
        for (int s = 1; s < 16; s <<= 1) {
            int t = __shfl_up_sync(0x0000ffffu, x, s);
            if (tid >= s) x += t;
        }
        woff[tid] = x - v;
    }
    __syncthreads();
    uint32_t lmask = (1u << lane) - 1u;
    if (sel0) idx_out[b * k + woff[w]     + __popc(m0 & lmask)] = r0;
    if (sel1) idx_out[b * k + woff[8 + w] + __popc(m1 & lmask)] = r1;
}

// ---------------------------------------------------------------------------
// Final: mean over 128 nodes -> dense [32,16] + bias -> softmax(16).
// ---------------------------------------------------------------------------
__global__ __launch_bounds__(128) void k_final(
    const float* __restrict__ h3, const float* __restrict__ wd,
    const float* __restrict__ bd, float* __restrict__ out)
{
    __shared__ float ps[4][HDIM];
    __shared__ float pooled[HDIM];
    __shared__ float logits[CDIM];
    const int tid = threadIdx.x;
    const int b   = blockIdx.x;
    const int c = tid & 31, seg = tid >> 5;

    float s = 0.f;
    for (int i = seg * 32; i < seg * 32 + 32; i++)
        s += h3[((size_t)b * KSEL2 + i) * HDIM + c];
    ps[seg][c] = s;
    __syncthreads();
    if (tid < HDIM)
        pooled[tid] = (ps[0][tid] + ps[1][tid] + ps[2][tid] + ps[3][tid]) *
                      (1.f / (float)KSEL2);
    __syncthreads();
    if (tid < CDIM) {
        float l = bd[tid];
        for (int h = 0; h < HDIM; h++) l += pooled[h] * wd[h * CDIM + tid];
        logits[tid] = l;
    }
    __syncthreads();
    if (tid < CDIM) {
        float mx = -1e30f;
        for (int j = 0; j < CDIM; j++) mx = fmaxf(mx, logits[j]);
        float den = 0.f;
        for (int j = 0; j < CDIM; j++) den += expf(logits[j] - mx);
        out[b * CDIM + tid] = expf(logits[tid] - mx) / den;
    }
}

// ---------------------------------------------------------------------------
extern "C" void kernel_launch(void* const* d_in, const int* in_sizes, int n_in,
                              void* d_out, int out_size)
{
    (void)in_sizes; (void)n_in; (void)out_size;
    const float* x    = (const float*)d_in[0];
    const float* a    = (const float*)d_in[1];
    const float* w1_1 = (const float*)d_in[2];
    const float* w2_1 = (const float*)d_in[3];
    const float* b1   = (const float*)d_in[4];
    const float* w1_2 = (const float*)d_in[5];
    const float* w2_2 = (const float*)d_in[6];
    const float* b2   = (const float*)d_in[7];
    const float* w1_3 = (const float*)d_in[8];
    const float* w2_3 = (const float*)d_in[9];
    const float* b3   = (const float*)d_in[10];
    const float* pp   = (const float*)d_in[11];
    const float* wd   = (const float*)d_in[12];
    const float* bd   = (const float*)d_in[13];
    float* out = (float*)d_out;

    __half *zh, *zl;
    float *u1, *u2, *u3, *h1, *h2, *h3, *gate1, *gate2;
    int *idx1, *idx2;
    cudaGetSymbolAddress((void**)&zh, g_zh);
    cudaGetSymbolAddress((void**)&zl, g_zl);
    cudaGetSymbolAddress((void**)&u1, g_u1);
    cudaGetSymbolAddress((void**)&u2, g_u2);
    cudaGetSymbolAddress((void**)&u3, g_u3);
    cudaGetSymbolAddress((void**)&h1, g_h1);
    cudaGetSymbolAddress((void**)&h2, g_h2);
    cudaGetSymbolAddress((void**)&h3, g_h3);
    cudaGetSymbolAddress((void**)&gate1, g_gate1);
    cudaGetSymbolAddress((void**)&gate2, g_gate2);
    cudaGetSymbolAddress((void**)&idx1, g_idx1);
    cudaGetSymbolAddress((void**)&idx2, g_idx2);

    cudaFuncSetAttribute(k_aZ_mma, cudaFuncAttributeMaxDynamicSharedMemorySize,
                         AZ_SMEM_MAX);
    cudaFuncSetAttribute(k_xw, cudaFuncAttributeMaxDynamicSharedMemorySize,
                         XW_SMEM);

    // smem sizes per aZ stage: 2*64*(klen+8) + 2*18432 + 512 + 2048
    const int az1 = 2 * 64 * (512 + 8) + 36864 + 2560;   // 105984
    const int az2 = 2 * 64 * (256 + 8) + 36864 + 2560;   // 73216
    const int az3 = 2 * 64 * (128 + 8) + 36864 + 2560;   // 56832

    // conv1 (full K=512)
    k_xw<<<(BATCH * NNODE) / 128, 256, XW_SMEM>>>(x, w1_1, w2_1, b1, zh, zl, u1);
    k_aZ_mma<<<dim3(NNODE / 128, BATCH), 256, az1>>>(
        a, zh, zl, u1, h1, nullptr, nullptr, NNODE, 512, 0);
    // pool1
    k_topk<<<BATCH, 256>>>(h1, pp, nullptr, gate1, idx1, KSEL1);
    // conv2 (compact rows + compact K = idx1)
    k_gxw_c<<<(BATCH * KSEL1) / 128, 256>>>(h1, gate1, idx1, KSEL1, 8,
                                            w1_2, w2_2, b2, zh, zl, u2);
    k_aZ_mma<<<dim3(KSEL1 / 128, BATCH), 256, az2>>>(
        a, zh, zl, u2, h2, idx1, idx1, KSEL1, KSEL1, 0);
    // pool2
    k_topk<<<BATCH, 256>>>(h2, pp, gate1, gate2, idx2, KSEL2);
    // conv3 (compact rows + compact K = idx2)
    k_gxw_c<<<(BATCH * KSEL2) / 128, 256>>>(h2, gate2, idx2, KSEL2, 7,
                                            w1_3, w2_3, b3, zh, zl, u3);
    k_aZ_mma<<<dim3(KSEL2 / 128, BATCH), 256, az3>>>(
        a, zh, zl, u3, h3, idx2, idx2, KSEL2, KSEL2, 1);
    // global mean pool + dense + softmax
    k_final<<<BATCH, 128>>>(h3, wd, bd, out);
}

// round 13
// speedup vs baseline: 2.1007x; 1.2014x over previous
#include <cuda_runtime.h>
#include <cuda_fp16.h>
#include <math.h>
#include <stdint.h>

#define BATCH 256
#define NNODE 512
#define FDIM  128
#define HDIM  32
#define CDIM  16
#define KSEL1 256
#define KSEL2 128

// ---------------- scratch (device globals: no allocation allowed) ----------
__device__ __half g_zh[BATCH * HDIM * NNODE];   // z^T hi; compact stride per stage
__device__ __half g_zl[BATCH * HDIM * NNODE];   // z^T lo
__device__ float g_u1[BATCH * NNODE * HDIM];
__device__ float g_u2[BATCH * NNODE * HDIM];
__device__ float g_u3[BATCH * NNODE * HDIM];
__device__ float g_h1[BATCH * NNODE * HDIM];
__device__ float g_h2[BATCH * NNODE * HDIM];
__device__ float g_h3[BATCH * KSEL2 * HDIM];
__device__ float g_gate1[BATCH * NNODE];
__device__ float g_gate2[BATCH * NNODE];
__device__ int   g_idx1[BATCH * KSEL1];
__device__ int   g_idx2[BATCH * KSEL2];
// pre-split transposed weights: [64 n][K k] fp16 hi/lo
__device__ __half g_wt1h[64 * 128];
__device__ __half g_wt1l[64 * 128];
__device__ __half g_wt2h[64 * 32];
__device__ __half g_wt2l[64 * 32];
__device__ __half g_wt3h[64 * 32];
__device__ __half g_wt3l[64 * 32];

// ======================= warp-MMA helpers (generic PTX) =====================
__device__ __forceinline__ uint32_t smem_u32(const void* p) {
    uint32_t a;
    asm("{ .reg .u64 t; cvta.to.shared.u64 t, %1; cvt.u32.u64 %0, t; }"
        : "=r"(a) : "l"(p));
    return a;
}
__device__ __forceinline__ void ldsm4(uint32_t* r, uint32_t addr) {
    asm volatile(
        "ldmatrix.sync.aligned.m8n8.x4.shared.b16 {%0,%1,%2,%3}, [%4];"
        : "=r"(r[0]), "=r"(r[1]), "=r"(r[2]), "=r"(r[3]) : "r"(addr));
}
__device__ __forceinline__ void mma_f16(float* c, const uint32_t* a,
                                        uint32_t b0, uint32_t b1) {
    asm volatile(
        "mma.sync.aligned.m16n8k16.row.col.f32.f16.f16.f32 "
        "{%0,%1,%2,%3}, {%4,%5,%6,%7}, {%8,%9}, {%0,%1,%2,%3};"
        : "+f"(c[0]), "+f"(c[1]), "+f"(c[2]), "+f"(c[3])
        : "r"(a[0]), "r"(a[1]), "r"(a[2]), "r"(a[3]), "r"(b0), "r"(b1));
}
#define CP16(dst, src) \
    asm volatile("cp.async.cg.shared.global [%0], [%1], 16;" \
                 :: "r"(dst), "l"(src))
#define CP_COMMIT() asm volatile("cp.async.commit_group;" ::: "memory")
#define CP_WAIT0()  asm volatile("cp.async.wait_group 0;" ::: "memory")

// split fp32 -> fp16 hi/lo (hi+lo carries ~22 mantissa bits)
__device__ __forceinline__ void fsplit(float v, unsigned short& h,
                                       unsigned short& l) {
    __half hb = __float2half(v);
    float hf = __half2float(hb);
    __half lb = __float2half(v - hf);
    h = *(unsigned short*)&hb;
    l = *(unsigned short*)&lb;
}

// ---------------------------------------------------------------------------
// W prep: split all three layers' W^T into global fp16 hi/lo once.
// Layout: row n in [0,64): n<32 -> w1 col n; n>=32 -> w2 col n-32.
// ---------------------------------------------------------------------------
__global__ __launch_bounds__(256) void k_wprep(
    const float* __restrict__ w11, const float* __restrict__ w21,
    const float* __restrict__ w12, const float* __restrict__ w22,
    const float* __restrict__ w13, const float* __restrict__ w23,
    __half* __restrict__ wt1h, __half* __restrict__ wt1l,
    __half* __restrict__ wt2h, __half* __restrict__ wt2l,
    __half* __restrict__ wt3h, __half* __restrict__ wt3l)
{
    int e = blockIdx.x * 256 + threadIdx.x;
    unsigned short hh, ll;
    if (e < 8192) {
        int n = e >> 7, k = e & 127;
        float w = (n < 32) ? w11[k * HDIM + n] : w21[k * HDIM + (n - 32)];
        fsplit(w, hh, ll);
        wt1h[n * 128 + k] = *(__half*)&hh;
        wt1l[n * 128 + k] = *(__half*)&ll;
    } else if (e < 10240) {
        int e2 = e - 8192;
        int n = e2 >> 5, k = e2 & 31;
        float w = (n < 32) ? w12[k * HDIM + n] : w22[k * HDIM + (n - 32)];
        fsplit(w, hh, ll);
        wt2h[n * 32 + k] = *(__half*)&hh;
        wt2l[n * 32 + k] = *(__half*)&ll;
    } else if (e < 12288) {
        int e2 = e - 10240;
        int n = e2 >> 5, k = e2 & 31;
        float w = (n < 32) ? w13[k * HDIM + n] : w23[k * HDIM + (n - 32)];
        fsplit(w, hh, ll);
        wt3h[n * 32 + k] = *(__half*)&hh;
        wt3l[n * 32 + k] = *(__half*)&ll;
    }
}

// ---------------------------------------------------------------------------
// G1 (MMA): z = x @ w1, u = x @ w2 + bias, fp16 3-product.
// zT full-N stored split fp16 (stride NNODE). Tile 128 x 64, K=128.
// ---------------------------------------------------------------------------
#define XW_XH   0
#define XW_XL   34816
#define XW_WTH  69632
#define XW_WTL  87040
#define XW_SMEM 104448

__global__ __launch_bounds__(256, 2) void k_xw(
    const float* __restrict__ x,
    const __half* __restrict__ wt1h, const __half* __restrict__ wt1l,
    const float* __restrict__ bias,
    __half* __restrict__ zh, __half* __restrict__ zl,
    float* __restrict__ uout)
{
    extern __shared__ char smem[];
    const uint32_t sb = smem_u32(smem);
    const int tid = threadIdx.x, wid = tid >> 5, lane = tid & 31;
    const int m0 = blockIdx.x * 128;
    __half* XH  = (__half*)(smem + XW_XH);
    __half* XL  = (__half*)(smem + XW_XL);
    __half* WTH = (__half*)(smem + XW_WTH);
    __half* WTL = (__half*)(smem + XW_WTL);

    // W^T hi/lo: 64 rows x 128 halves, vector copy
#pragma unroll
    for (int it = 0; it < 4; it++) {
        int e = tid + 256 * it;          // 0..1023
        int n = e >> 4, c = e & 15;
        *(uint4*)&WTH[n * 136 + c * 8] = *(const uint4*)&wt1h[n * 128 + c * 8];
        *(uint4*)&WTL[n * 136 + c * 8] = *(const uint4*)&wt1l[n * 128 + c * 8];
    }
    // x tile 128x128 -> fp16 hi/lo
#pragma unroll
    for (int t = 0; t < 16; t++) {
        int e = tid + 256 * t;
        int r = e >> 5, c4 = (e & 31) * 4;
        float4 v = *(const float4*)&x[(size_t)(m0 + r) * FDIM + c4];
        unsigned short hp[4], lp[4];
        fsplit(v.x, hp[0], lp[0]); fsplit(v.y, hp[1], lp[1]);
        fsplit(v.z, hp[2], lp[2]); fsplit(v.w, hp[3], lp[3]);
        *(uint2*)&XH[r * 136 + c4] = *(uint2*)hp;
        *(uint2*)&XL[r * 136 + c4] = *(uint2*)lp;
    }
    __syncthreads();

    float acc[8][4];
#pragma unroll
    for (int i = 0; i < 8; i++)
#pragma unroll
        for (int j = 0; j < 4; j++) acc[i][j] = 0.f;

    const int g8 = lane >> 3, r8 = lane & 7;
    const int a_row = wid * 16 + ((g8 & 1) ? 8 : 0) + r8;
    const uint32_t a_off = (uint32_t)a_row * 272 + ((g8 >= 2) ? 16 : 0);
    const uint32_t ah_base = sb + XW_XH + a_off;
    const uint32_t al_base = sb + XW_XL + a_off;
    const int b_rowoff = ((g8 >> 1) ? 8 : 0) + r8;
    const uint32_t b_off = (uint32_t)b_rowoff * 272 + ((g8 & 1) ? 16 : 0);
    const uint32_t bh_base = sb + XW_WTH + b_off;
    const uint32_t bl_base = sb + XW_WTL + b_off;

#pragma unroll
    for (int ks = 0; ks < 8; ks++) {
        const uint32_t ka = (uint32_t)ks * 32;
        uint32_t ah[4], al[4], bh[16], bl[16];
        ldsm4(ah, ah_base + ka);
        ldsm4(al, al_base + ka);
#pragma unroll
        for (int q = 0; q < 4; q++) {
            ldsm4(bh + 4 * q, bh_base + (uint32_t)q * 16 * 272 + ka);
            ldsm4(bl + 4 * q, bl_base + (uint32_t)q * 16 * 272 + ka);
        }
#pragma unroll
        for (int nt = 0; nt < 8; nt++) {
            mma_f16(acc[nt], ah, bh[nt * 2], bh[nt * 2 + 1]);
            mma_f16(acc[nt], ah, bl[nt * 2], bl[nt * 2 + 1]);
            mma_f16(acc[nt], al, bh[nt * 2], bh[nt * 2 + 1]);
        }
    }
    __syncthreads();

    __half* zts_h = (__half*)smem;              // [32 cols][136 rows]
    __half* zts_l = zts_h + 32 * 136;
    const int g = lane >> 2, t2 = (lane & 3) * 2;
    const int r0l = wid * 16 + g, r1l = r0l + 8;

#pragma unroll
    for (int nt = 0; nt < 4; nt++) {
        int c = nt * 8 + t2;
        unsigned short hh, ll;
        fsplit(acc[nt][0], hh, ll);
        zts_h[c * 136 + r0l] = *(__half*)&hh; zts_l[c * 136 + r0l] = *(__half*)&ll;
        fsplit(acc[nt][1], hh, ll);
        zts_h[(c + 1) * 136 + r0l] = *(__half*)&hh; zts_l[(c + 1) * 136 + r0l] = *(__half*)&ll;
        fsplit(acc[nt][2], hh, ll);
        zts_h[c * 136 + r1l] = *(__half*)&hh; zts_l[c * 136 + r1l] = *(__half*)&ll;
        fsplit(acc[nt][3], hh, ll);
        zts_h[(c + 1) * 136 + r1l] = *(__half*)&hh; zts_l[(c + 1) * 136 + r1l] = *(__half*)&ll;
    }
#pragma unroll
    for (int nt = 4; nt < 8; nt++) {
        int c = (nt - 4) * 8 + t2;
        float2 bv = *(const float2*)&bias[c];
        int gr0 = m0 + r0l, gr1 = m0 + r1l;
        float2 v0 = make_float2(acc[nt][0] + bv.x, acc[nt][1] + bv.y);
        float2 v1 = make_float2(acc[nt][2] + bv.x, acc[nt][3] + bv.y);
        *(float2*)&uout[(size_t)gr0 * HDIM + c] = v0;
        *(float2*)&uout[(size_t)gr1 * HDIM + c] = v1;
    }
    __syncthreads();
    {
        int b_ = m0 >> 9, r0g = m0 & (NNODE - 1);
#pragma unroll
        for (int it = 0; it < 2; it++) {
            int e = tid + 256 * it;
            int col = e >> 4, seg = e & 15;
            size_t gb = ((size_t)(b_ * HDIM + col)) * NNODE + r0g + seg * 8;
            *(uint4*)&zh[gb] = *(uint4*)&zts_h[col * 136 + seg * 8];
            *(uint4*)&zl[gb] = *(uint4*)&zts_l[col * 136 + seg * 8];
        }
    }
}

// ---------------------------------------------------------------------------
// G3/G5 compact (MMA): 128 COMPACT rows (rid from idx). z compact transposed
// [B][32][ksel]; u full-layout at selected rows. fp16 3-product.
// ---------------------------------------------------------------------------
#define GX_AH   0
#define GX_AL   10240
#define GX_WTH  20480
#define GX_WTL  25600
#define GX_RID  30720     // 128 ints
#define GX_SMEM 31232

__global__ __launch_bounds__(256) void k_gxw_c(
    const float* __restrict__ hfeat, const float* __restrict__ gate,
    const int* __restrict__ idx, int ksel, int kslog,
    const __half* __restrict__ wth, const __half* __restrict__ wtl,
    const float* __restrict__ bias,
    __half* __restrict__ zh, __half* __restrict__ zl,
    float* __restrict__ uout)
{
    __shared__ __align__(16) char smem[GX_SMEM];
    const uint32_t sb = smem_u32(smem);
    const int tid = threadIdx.x, wid = tid >> 5, lane = tid & 31;
    const int jg = blockIdx.x * 128;
    const int b  = jg >> kslog;
    const int j0 = jg & (ksel - 1);
    __half* AH  = (__half*)(smem + GX_AH);
    __half* AL  = (__half*)(smem + GX_AL);
    __half* WTH = (__half*)(smem + GX_WTH);
    __half* WTL = (__half*)(smem + GX_WTL);
    int* rid = (int*)(smem + GX_RID);

    if (tid < 128) rid[tid] = idx[b * ksel + j0 + tid];
    {   // W^T hi/lo: 64 rows x 32 halves = 256 uint4, one per thread
        int n = tid >> 2, c = tid & 3;
        *(uint4*)&WTH[n * 40 + c * 8] = *(const uint4*)&wth[n * 32 + c * 8];
        *(uint4*)&WTL[n * 40 + c * 8] = *(const uint4*)&wtl[n * 32 + c * 8];
    }
    __syncthreads();
#pragma unroll
    for (int t = 0; t < 4; t++) {
        int e = tid + 256 * t;
        int r = e >> 3, c4 = (e & 7) * 4;
        int gr = b * NNODE + rid[r];
        float g = gate[gr];
        float4 v = *(const float4*)&hfeat[(size_t)gr * HDIM + c4];
        v.x *= g; v.y *= g; v.z *= g; v.w *= g;
        unsigned short hp[4], lp[4];
        fsplit(v.x, hp[0], lp[0]); fsplit(v.y, hp[1], lp[1]);
        fsplit(v.z, hp[2], lp[2]); fsplit(v.w, hp[3], lp[3]);
        *(uint2*)&AH[r * 40 + c4] = *(uint2*)hp;
        *(uint2*)&AL[r * 40 + c4] = *(uint2*)lp;
    }
    __syncthreads();

    float acc[8][4];
#pragma unroll
    for (int i = 0; i < 8; i++)
#pragma unroll
        for (int j = 0; j < 4; j++) acc[i][j] = 0.f;

    const int g8 = lane >> 3, r8 = lane & 7;
    const int a_row = wid * 16 + ((g8 & 1) ? 8 : 0) + r8;
    const uint32_t a_off = (uint32_t)a_row * 80 + ((g8 >= 2) ? 16 : 0);
    const uint32_t ahb = sb + GX_AH + a_off;
    const uint32_t alb = sb + GX_AL + a_off;
    const int b_rowoff = ((g8 >> 1) ? 8 : 0) + r8;
    const uint32_t b_off = (uint32_t)b_rowoff * 80 + ((g8 & 1) ? 16 : 0);
    const uint32_t bhb = sb + GX_WTH + b_off;
    const uint32_t blb = sb + GX_WTL + b_off;

#pragma unroll
    for (int ks = 0; ks < 2; ks++) {
        const uint32_t ka = (uint32_t)ks * 32;
        uint32_t ah[4], al[4], bh[16], bl[16];
        ldsm4(ah, ahb + ka);
        ldsm4(al, alb + ka);
#pragma unroll
        for (int q = 0; q < 4; q++) {
            ldsm4(bh + 4 * q, bhb + (uint32_t)q * 16 * 80 + ka);
            ldsm4(bl + 4 * q, blb + (uint32_t)q * 16 * 80 + ka);
        }
#pragma unroll
        for (int nt = 0; nt < 8; nt++) {
            mma_f16(acc[nt], ah, bh[nt * 2], bh[nt * 2 + 1]);
            mma_f16(acc[nt], ah, bl[nt * 2], bl[nt * 2 + 1]);
            mma_f16(acc[nt], al, bh[nt * 2], bh[nt * 2 + 1]);
        }
    }
    __syncthreads();

    __half* zts_h = (__half*)smem;              // [32 cols][136 rows]
    __half* zts_l = zts_h + 32 * 136;
    const int g = lane >> 2, t2 = (lane & 3) * 2;
    const int r0l = wid * 16 + g, r1l = r0l + 8;

#pragma unroll
    for (int nt = 0; nt < 4; nt++) {
        int c = nt * 8 + t2;
        unsigned short hh, ll;
        fsplit(acc[nt][0], hh, ll);
        zts_h[c * 136 + r0l] = *(__half*)&hh; zts_l[c * 136 + r0l] = *(__half*)&ll;
        fsplit(acc[nt][1], hh, ll);
        zts_h[(c + 1) * 136 + r0l] = *(__half*)&hh; zts_l[(c + 1) * 136 + r0l] = *(__half*)&ll;
        fsplit(acc[nt][2], hh, ll);
        zts_h[c * 136 + r1l] = *(__half*)&hh; zts_l[c * 136 + r1l] = *(__half*)&ll;
        fsplit(acc[nt][3], hh, ll);
        zts_h[(c + 1) * 136 + r1l] = *(__half*)&hh; zts_l[(c + 1) * 136 + r1l] = *(__half*)&ll;
    }
#pragma unroll
    for (int nt = 4; nt < 8; nt++) {
        int c = (nt - 4) * 8 + t2;
        float2 bv = *(const float2*)&bias[c];
        int gr0 = b * NNODE + rid[r0l], gr1 = b * NNODE + rid[r1l];
        float2 v0 = make_float2(acc[nt][0] + bv.x, acc[nt][1] + bv.y);
        float2 v1 = make_float2(acc[nt][2] + bv.x, acc[nt][3] + bv.y);
        *(float2*)&uout[(size_t)gr0 * HDIM + c] = v0;
        *(float2*)&uout[(size_t)gr1 * HDIM + c] = v1;
    }
    __syncthreads();
    {
#pragma unroll
        for (int it = 0; it < 2; it++) {
            int e = tid + 256 * it;
            int col = e >> 4, seg = e & 15;
            size_t gb = ((size_t)(b * HDIM + col)) * ksel + j0 + seg * 8;
            *(uint4*)&zh[gb] = *(uint4*)&zts_h[col * 136 + seg * 8];
            *(uint4*)&zl[gb] = *(uint4*)&zts_l[col * 136 + seg * 8];
        }
    }
}

// ---------------------------------------------------------------------------
// fp16 MMA a@z v5: per-chunk cp.async z staging (double-buffered, fixed
// 144B stride), register-prefetched a chunks, 2 CTAs/SM (57.9KB SMEM).
// out[rows] = relu( a[b,gidx(row), kid(.)] @ zc[b] + u[b,gidx(row)] )
// ---------------------------------------------------------------------------
#define ASTR     72        // a fp16 tile row stride (144B)
#define AZ_ZST   9216      // per-stage z bytes: zh[32][72] + zl[32][72]
#define AZ_ZL    4608      // zl offset within stage
#define AZ_AH    18432     // A hi tile [128][72]
#define AZ_AL    36864
#define AZ_GIDX  55296
#define AZ_KID   55808
#define AZ_SMEM  57856

__global__ __launch_bounds__(256, 2) void k_aZ_mma(
    const float* __restrict__ a, const __half* __restrict__ zh,
    const __half* __restrict__ zl, const float* __restrict__ u,
    float* __restrict__ out, const int* __restrict__ ridx,
    const int* __restrict__ kidx, int rows_out, int klen, int out_compact)
{
    extern __shared__ char smem[];
    const uint32_t sb = smem_u32(smem);
    const int tid = threadIdx.x, wid = tid >> 5, lane = tid & 31;
    const int b  = blockIdx.y;
    const int m0 = blockIdx.x * 128;
    int* gidx = (int*)(smem + AZ_GIDX);
    int* kid  = (int*)(smem + AZ_KID);

    if (tid < 128)
        gidx[tid] = ridx ? ridx[b * rows_out + m0 + tid] : (m0 + tid);
    if (kidx)
        for (int i = tid; i < klen; i += 256) kid[i] = kidx[b * klen + i];
    __syncthreads();

    const float* ab = a + (size_t)b * NNODE * NNODE;
    const __half* zhb = zh + (size_t)b * HDIM * klen;
    const __half* zlb = zl + (size_t)b * HDIM * klen;
    const int nch = klen >> 6;

    // z chunk loader: 32 rows x 64 halves per array; one 16B unit per thread
    const int zrow = tid >> 3, zc = tid & 7;
    // ---- z chunk 0 (async) -> stage 0 ----
    {
        uint32_t dst = sb + zrow * 144 + zc * 16;
        CP16(dst,         zhb + (size_t)zrow * klen + zc * 8);
        CP16(dst + AZ_ZL, zlb + (size_t)zrow * klen + zc * 8);
    }
    CP_COMMIT();

    const int prow = tid >> 4;
    const int pc4  = (tid & 15) * 4;

    // ---- a chunk 0: LDG (contig or gather) -> regs, convert -> SMEM ----
    float4 pf[8];
#pragma unroll
    for (int t = 0; t < 8; t++) {
        const float* rp = ab + (size_t)gidx[prow + 16 * t] * NNODE;
        if (kidx) {
            pf[t].x = rp[kid[pc4 + 0]]; pf[t].y = rp[kid[pc4 + 1]];
            pf[t].z = rp[kid[pc4 + 2]]; pf[t].w = rp[kid[pc4 + 3]];
        } else {
            pf[t] = *(const float4*)&rp[pc4];
        }
    }
    {
        __half* dh = (__half*)(smem + AZ_AH);
        __half* dl = (__half*)(smem + AZ_AL);
#pragma unroll
        for (int t = 0; t < 8; t++) {
            int row = prow + 16 * t;
            unsigned short hp[4], lp[4];
            fsplit(pf[t].x, hp[0], lp[0]); fsplit(pf[t].y, hp[1], lp[1]);
            fsplit(pf[t].z, hp[2], lp[2]); fsplit(pf[t].w, hp[3], lp[3]);
            *(uint2*)&dh[row * ASTR + pc4] = *(uint2*)hp;
            *(uint2*)&dl[row * ASTR + pc4] = *(uint2*)lp;
        }
    }
    CP_WAIT0();
    __syncthreads();

    float acc[4][4];
#pragma unroll
    for (int i = 0; i < 4; i++)
#pragma unroll
        for (int j = 0; j < 4; j++) acc[i][j] = 0.f;

    const int g8 = lane >> 3, r8 = lane & 7;
    const int a_row = wid * 16 + ((g8 & 1) ? 8 : 0) + r8;
    const uint32_t a_off = (uint32_t)a_row * (ASTR * 2) + ((g8 >= 2) ? 16 : 0);
    const uint32_t ahb = sb + AZ_AH + a_off;
    const uint32_t alb = sb + AZ_AL + a_off;
    const int b_rowoff = ((g8 >> 1) ? 8 : 0) + r8;
    const uint32_t b_colB = (g8 & 1) ? 16 : 0;
    const uint32_t bh0 = sb +         (uint32_t)b_rowoff * 144 + b_colB;
    const uint32_t bh1 = sb +         (uint32_t)(16 + b_rowoff) * 144 + b_colB;
    const uint32_t bl0 = sb + AZ_ZL + (uint32_t)b_rowoff * 144 + b_colB;
    const uint32_t bl1 = sb + AZ_ZL + (uint32_t)(16 + b_rowoff) * 144 + b_colB;

    for (int ch = 0; ch < nch; ch++) {
        const uint32_t sB = (uint32_t)(ch & 1) * AZ_ZST;
        if (ch < nch - 1) {
            // issue z(ch+1) -> other stage
            const int zk = (ch + 1) * 64;
            const uint32_t sN = (uint32_t)((ch + 1) & 1) * AZ_ZST;
            uint32_t dst = sb + sN + zrow * 144 + zc * 16;
            CP16(dst,         zhb + (size_t)zrow * klen + zk + zc * 8);
            CP16(dst + AZ_ZL, zlb + (size_t)zrow * klen + zk + zc * 8);
            CP_COMMIT();
            // prefetch a(ch+1) -> regs
            const int k0 = (ch + 1) * 64;
#pragma unroll
            for (int t = 0; t < 8; t++) {
                const float* rp = ab + (size_t)gidx[prow + 16 * t] * NNODE;
                if (kidx) {
                    pf[t].x = rp[kid[k0 + pc4 + 0]];
                    pf[t].y = rp[kid[k0 + pc4 + 1]];
                    pf[t].z = rp[kid[k0 + pc4 + 2]];
                    pf[t].w = rp[kid[k0 + pc4 + 3]];
                } else {
                    pf[t] = *(const float4*)&rp[k0 + pc4];
                }
            }
        }

#pragma unroll
        for (int ks = 0; ks < 4; ks++) {
            const uint32_t ka = (uint32_t)ks * 32;
            uint32_t ah[4], al[4], bh[8], bl[8];
            ldsm4(ah, ahb + ka);
            ldsm4(al, alb + ka);
            ldsm4(bh,     bh0 + sB + ka);
            ldsm4(bh + 4, bh1 + sB + ka);
            ldsm4(bl,     bl0 + sB + ka);
            ldsm4(bl + 4, bl1 + sB + ka);
#pragma unroll
            for (int nt = 0; nt < 4; nt++) {
                mma_f16(acc[nt], ah, bh[nt * 2], bh[nt * 2 + 1]);
                mma_f16(acc[nt], ah, bl[nt * 2], bl[nt * 2 + 1]);
                mma_f16(acc[nt], al, bh[nt * 2], bh[nt * 2 + 1]);
            }
        }

        if (ch < nch - 1) {
            __syncthreads();      // A-tile readers done
            __half* dh = (__half*)(smem + AZ_AH);
            __half* dl = (__half*)(smem + AZ_AL);
#pragma unroll
            for (int t = 0; t < 8; t++) {
                int row = prow + 16 * t;
                unsigned short hp[4], lp[4];
                fsplit(pf[t].x, hp[0], lp[0]); fsplit(pf[t].y, hp[1], lp[1]);
                fsplit(pf[t].z, hp[2], lp[2]); fsplit(pf[t].w, hp[3], lp[3]);
                *(uint2*)&dh[row * ASTR + pc4] = *(uint2*)hp;
                *(uint2*)&dl[row * ASTR + pc4] = *(uint2*)lp;
            }
            CP_WAIT0();           // z(ch+1) landed
            __syncthreads();      // publish A + z
        }
    }

    // ---- epilogue ----
    const int g  = lane >> 2, t2 = (lane & 3) * 2;
    const int lr0 = wid * 16 + g, lr1 = lr0 + 8;
    const int gm0 = gidx[lr0], gm1 = gidx[lr1];
    const float* u0 = &u[((size_t)b * NNODE + gm0) * HDIM];
    const float* u1 = &u[((size_t)b * NNODE + gm1) * HDIM];
    float* o0 = out + (out_compact
               ? ((size_t)b * rows_out + m0 + lr0) * HDIM
               : ((size_t)b * NNODE + gm0) * HDIM);
    float* o1 = out + (out_compact
               ? ((size_t)b * rows_out + m0 + lr1) * HDIM
               : ((size_t)b * NNODE + gm1) * HDIM);
#pragma unroll
    for (int nt = 0; nt < 4; nt++) {
        int c = nt * 8 + t2;
        float2 uv0 = *(const float2*)&u0[c];
        float2 uv1 = *(const float2*)&u1[c];
        float2 r0, r1;
        r0.x = fmaxf(acc[nt][0] + uv0.x, 0.f);
        r0.y = fmaxf(acc[nt][1] + uv0.y, 0.f);
        r1.x = fmaxf(acc[nt][2] + uv1.x, 0.f);
        r1.y = fmaxf(acc[nt][3] + uv1.y, 0.f);
        *(float2*)&o0[c] = r0;
        *(float2*)&o1[c] = r1;
    }
}

// ---------------------------------------------------------------------------
// TopK: exact jax.lax.top_k set semantics via rank counting; ballot prefix.
// ---------------------------------------------------------------------------
__global__ __launch_bounds__(256) void k_topk(
    const float* __restrict__ hfeat, const float* __restrict__ p,
    const float* __restrict__ prevgate, float* __restrict__ gate_out,
    int* __restrict__ idx_out, int k)
{
    __shared__ float ysh[NNODE];
    __shared__ float pn[HDIM];
    __shared__ int wcnt[16], woff[16];
    const int tid = threadIdx.x;
    const int b   = blockIdx.x;
    const int lane = tid & 31, w = tid >> 5;

    if (tid == 0) {
        float s = 0.f;
        for (int h = 0; h < HDIM; h++) s += p[h] * p[h];
        s = rsqrtf(s);
        for (int h = 0; h < HDIM; h++) pn[h] = p[h] * s;
    }
    __syncthreads();

    for (int r = w; r < NNODE; r += 8) {
        float v = hfeat[((size_t)b * NNODE + r) * HDIM + lane] * pn[lane];
#pragma unroll
        for (int s = 16; s > 0; s >>= 1) v += __shfl_xor_sync(0xffffffffu, v, s);
        if (lane == 0) {
            bool valid = (prevgate == nullptr) ||
                         (prevgate[(size_t)b * NNODE + r] > 0.f);
            ysh[r] = valid ? v : -1e30f;
        }
    }
    __syncthreads();

    const int r0 = tid, r1 = tid + 256;
    float y0 = ysh[r0], y1 = ysh[r1];
    int rank0 = 0, rank1 = 0;
    for (int j = 0; j < NNODE; j++) {
        float yj = ysh[j];
        rank0 += (yj > y0) || (yj == y0 && j < r0);
        rank1 += (yj > y1) || (yj == y1 && j < r1);
    }
    int sel0 = rank0 < k, sel1 = rank1 < k;
    gate_out[(size_t)b * NNODE + r0] = sel0 ? (1.f / (1.f + expf(-y0))) : 0.f;
    gate_out[(size_t)b * NNODE + r1] = sel1 ? (1.f / (1.f + expf(-y1))) : 0.f;

    uint32_t m0 = __ballot_sync(0xffffffffu, sel0);
    uint32_t m1 = __ballot_sync(0xffffffffu, sel1);
    if (lane == 0) { wcnt[w] = __popc(m0); wcnt[8 + w] = __popc(m1); }
    __syncthreads();
    if (tid < 16) {
        int v = wcnt[tid];
        int x = v;
#pragma unroll
        for (int s = 1; s < 16; s <<= 1) {
            int t = __shfl_up_sync(0x0000ffffu, x, s);
            if (tid >= s) x += t;
        }
        woff[tid] = x - v;
    }
    __syncthreads();
    uint32_t lmask = (1u << lane) - 1u;
    if (sel0) idx_out[b * k + woff[w]     + __popc(m0 & lmask)] = r0;
    if (sel1) idx_out[b * k + woff[8 + w] + __popc(m1 & lmask)] = r1;
}

// ---------------------------------------------------------------------------
// Final: mean over 128 nodes -> dense [32,16] + bias -> softmax(16).
// ---------------------------------------------------------------------------
__global__ __launch_bounds__(128) void k_final(
    const float* __restrict__ h3, const float* __restrict__ wd,
    const float* __restrict__ bd, float* __restrict__ out)
{
    __shared__ float ps[4][HDIM];
    __shared__ float pooled[HDIM];
    __shared__ float logits[CDIM];
    const int tid = threadIdx.x;
    const int b   = blockIdx.x;
    const int c = tid & 31, seg = tid >> 5;

    float s = 0.f;
    for (int i = seg * 32; i < seg * 32 + 32; i++)
        s += h3[((size_t)b * KSEL2 + i) * HDIM + c];
    ps[seg][c] = s;
    __syncthreads();
    if (tid < HDIM)
        pooled[tid] = (ps[0][tid] + ps[1][tid] + ps[2][tid] + ps[3][tid]) *
                      (1.f / (float)KSEL2);
    __syncthreads();
    if (tid < CDIM) {
        float l = bd[tid];
        for (int h = 0; h < HDIM; h++) l += pooled[h] * wd[h * CDIM + tid];
        logits[tid] = l;
    }
    __syncthreads();
    if (tid < CDIM) {
        float mx = -1e30f;
        for (int j = 0; j < CDIM; j++) mx = fmaxf(mx, logits[j]);
        float den = 0.f;
        for (int j = 0; j < CDIM; j++) den += expf(logits[j] - mx);
        out[b * CDIM + tid] = expf(logits[tid] - mx) / den;
    }
}

// ---------------------------------------------------------------------------
extern "C" void kernel_launch(void* const* d_in, const int* in_sizes, int n_in,
                              void* d_out, int out_size)
{
    (void)in_sizes; (void)n_in; (void)out_size;
    const float* x    = (const float*)d_in[0];
    const float* a    = (const float*)d_in[1];
    const float* w1_1 = (const float*)d_in[2];
    const float* w2_1 = (const float*)d_in[3];
    const float* b1   = (const float*)d_in[4];
    const float* w1_2 = (const float*)d_in[5];
    const float* w2_2 = (const float*)d_in[6];
    const float* b2   = (const float*)d_in[7];
    const float* w1_3 = (const float*)d_in[8];
    const float* w2_3 = (const float*)d_in[9];
    const float* b3   = (const float*)d_in[10];
    const float* pp   = (const float*)d_in[11];
    const float* wd   = (const float*)d_in[12];
    const float* bd   = (const float*)d_in[13];
    float* out = (float*)d_out;

    __half *zh, *zl, *wt1h, *wt1l, *wt2h, *wt2l, *wt3h, *wt3l;
    float *u1, *u2, *u3, *h1, *h2, *h3, *gate1, *gate2;
    int *idx1, *idx2;
    cudaGetSymbolAddress((void**)&zh, g_zh);
    cudaGetSymbolAddress((void**)&zl, g_zl);
    cudaGetSymbolAddress((void**)&wt1h, g_wt1h);
    cudaGetSymbolAddress((void**)&wt1l, g_wt1l);
    cudaGetSymbolAddress((void**)&wt2h, g_wt2h);
    cudaGetSymbolAddress((void**)&wt2l, g_wt2l);
    cudaGetSymbolAddress((void**)&wt3h, g_wt3h);
    cudaGetSymbolAddress((void**)&wt3l, g_wt3l);
    cudaGetSymbolAddress((void**)&u1, g_u1);
    cudaGetSymbolAddress((void**)&u2, g_u2);
    cudaGetSymbolAddress((void**)&u3, g_u3);
    cudaGetSymbolAddress((void**)&h1, g_h1);
    cudaGetSymbolAddress((void**)&h2, g_h2);
    cudaGetSymbolAddress((void**)&h3, g_h3);
    cudaGetSymbolAddress((void**)&gate1, g_gate1);
    cudaGetSymbolAddress((void**)&gate2, g_gate2);
    cudaGetSymbolAddress((void**)&idx1, g_idx1);
    cudaGetSymbolAddress((void**)&idx2, g_idx2);

    cudaFuncSetAttribute(k_aZ_mma, cudaFuncAttributeMaxDynamicSharedMemorySize,
                         AZ_SMEM);
    cudaFuncSetAttribute(k_xw, cudaFuncAttributeMaxDynamicSharedMemorySize,
                         XW_SMEM);

    // one-shot weight split (all 3 layers)
    k_wprep<<<48, 256>>>(w1_1, w2_1, w1_2, w2_2, w1_3, w2_3,
                         wt1h, wt1l, wt2h, wt2l, wt3h, wt3l);

    // conv1 (full K=512)
    k_xw<<<(BATCH * NNODE) / 128, 256, XW_SMEM>>>(x, wt1h, wt1l, b1, zh, zl, u1);
    k_aZ_mma<<<dim3(NNODE / 128, BATCH), 256, AZ_SMEM>>>(
        a, zh, zl, u1, h1, nullptr, nullptr, NNODE, 512, 0);
    // pool1
    k_topk<<<BATCH, 256>>>(h1, pp, nullptr, gate1, idx1, KSEL1);
    // conv2 (compact rows + compact K = idx1)
    k_gxw_c<<<(BATCH * KSEL1) / 128, 256>>>(h1, gate1, idx1, KSEL1, 8,
                                            wt2h, wt2l, b2, zh, zl, u2);
    k_aZ_mma<<<dim3(KSEL1 / 128, BATCH), 256, AZ_SMEM>>>(
        a, zh, zl, u2, h2, idx1, idx1, KSEL1, KSEL1, 0);
    // pool2
    k_topk<<<BATCH, 256>>>(h2, pp, gate1, gate2, idx2, KSEL2);
    // conv3 (compact rows + compact K = idx2)
    k_gxw_c<<<(BATCH * KSEL2) / 128, 256>>>(h2, gate2, idx2, KSEL2, 7,
                                            wt3h, wt3l, b3, zh, zl, u3);
    k_aZ_mma<<<dim3(KSEL2 / 128, BATCH), 256, AZ_SMEM>>>(
        a, zh, zl, u3, h3, idx2, idx2, KSEL2, KSEL2, 1);
    // global mean pool + dense + softmax
    k_final<<<BATCH, 128>>>(h3, wd, bd, out);
}

// round 16
// speedup vs baseline: 2.2310x; 1.0620x over previous
#include <cuda_runtime.h>
#include <cuda_fp16.h>
#include <math.h>
#include <stdint.h>

#define BATCH 256
#define NNODE 512
#define FDIM  128
#define HDIM  32
#define CDIM  16
#define KSEL1 256
#define KSEL2 128

// ---------------- scratch (device globals: no allocation allowed) ----------
__device__ __half g_zh[BATCH * HDIM * NNODE];   // z^T hi; compact stride per stage
__device__ __half g_zl[BATCH * HDIM * NNODE];   // z^T lo
__device__ float g_u1[BATCH * NNODE * HDIM];
__device__ float g_u2[BATCH * NNODE * HDIM];
__device__ float g_u3[BATCH * NNODE * HDIM];
__device__ float g_h1[BATCH * NNODE * HDIM];
__device__ float g_h2[BATCH * NNODE * HDIM];
__device__ float g_h3[BATCH * KSEL2 * HDIM];
__device__ float g_gate1[BATCH * NNODE];
__device__ float g_gate2[BATCH * NNODE];
__device__ int   g_idx1[BATCH * KSEL1];
__device__ int   g_idx2[BATCH * KSEL2];
// pre-split transposed weights: [64 n][K k] fp16 hi/lo
__device__ __half g_wt1h[64 * 128];
__device__ __half g_wt1l[64 * 128];
__device__ __half g_wt2h[64 * 32];
__device__ __half g_wt2l[64 * 32];
__device__ __half g_wt3h[64 * 32];
__device__ __half g_wt3l[64 * 32];

// ======================= warp-MMA helpers (generic PTX) =====================
__device__ __forceinline__ uint32_t smem_u32(const void* p) {
    uint32_t a;
    asm("{ .reg .u64 t; cvta.to.shared.u64 t, %1; cvt.u32.u64 %0, t; }"
        : "=r"(a) : "l"(p));
    return a;
}
__device__ __forceinline__ void ldsm4(uint32_t* r, uint32_t addr) {
    asm volatile(
        "ldmatrix.sync.aligned.m8n8.x4.shared.b16 {%0,%1,%2,%3}, [%4];"
        : "=r"(r[0]), "=r"(r[1]), "=r"(r[2]), "=r"(r[3]) : "r"(addr));
}
__device__ __forceinline__ void mma_f16(float* c, const uint32_t* a,
                                        uint32_t b0, uint32_t b1) {
    asm volatile(
        "mma.sync.aligned.m16n8k16.row.col.f32.f16.f16.f32 "
        "{%0,%1,%2,%3}, {%4,%5,%6,%7}, {%8,%9}, {%0,%1,%2,%3};"
        : "+f"(c[0]), "+f"(c[1]), "+f"(c[2]), "+f"(c[3])
        : "r"(a[0]), "r"(a[1]), "r"(a[2]), "r"(a[3]), "r"(b0), "r"(b1));
}
#define CP16(dst, src) \
    asm volatile("cp.async.cg.shared.global [%0], [%1], 16;" \
                 :: "r"(dst), "l"(src))
#define CP_COMMIT() asm volatile("cp.async.commit_group;" ::: "memory")
#define CP_WAIT0()  asm volatile("cp.async.wait_group 0;" ::: "memory")

// split fp32 -> fp16 hi/lo (hi+lo carries ~22 mantissa bits)
__device__ __forceinline__ void fsplit(float v, unsigned short& h,
                                       unsigned short& l) {
    __half hb = __float2half(v);
    float hf = __half2float(hb);
    __half lb = __float2half(v - hf);
    h = *(unsigned short*)&hb;
    l = *(unsigned short*)&lb;
}

// ---------------------------------------------------------------------------
// W prep: split all three layers' W^T into global fp16 hi/lo once.
// ---------------------------------------------------------------------------
__global__ __launch_bounds__(256) void k_wprep(
    const float* __restrict__ w11, const float* __restrict__ w21,
    const float* __restrict__ w12, const float* __restrict__ w22,
    const float* __restrict__ w13, const float* __restrict__ w23,
    __half* __restrict__ wt1h, __half* __restrict__ wt1l,
    __half* __restrict__ wt2h, __half* __restrict__ wt2l,
    __half* __restrict__ wt3h, __half* __restrict__ wt3l)
{
    int e = blockIdx.x * 256 + threadIdx.x;
    unsigned short hh, ll;
    if (e < 8192) {
        int n = e >> 7, k = e & 127;
        float w = (n < 32) ? w11[k * HDIM + n] : w21[k * HDIM + (n - 32)];
        fsplit(w, hh, ll);
        wt1h[n * 128 + k] = *(__half*)&hh;
        wt1l[n * 128 + k] = *(__half*)&ll;
    } else if (e < 10240) {
        int e2 = e - 8192;
        int n = e2 >> 5, k = e2 & 31;
        float w = (n < 32) ? w12[k * HDIM + n] : w22[k * HDIM + (n - 32)];
        fsplit(w, hh, ll);
        wt2h[n * 32 + k] = *(__half*)&hh;
        wt2l[n * 32 + k] = *(__half*)&ll;
    } else if (e < 12288) {
        int e2 = e - 10240;
        int n = e2 >> 5, k = e2 & 31;
        float w = (n < 32) ? w13[k * HDIM + n] : w23[k * HDIM + (n - 32)];
        fsplit(w, hh, ll);
        wt3h[n * 32 + k] = *(__half*)&hh;
        wt3l[n * 32 + k] = *(__half*)&ll;
    }
}

// ---------------------------------------------------------------------------
// G1 (MMA): z = x @ w1, u = x @ w2 + bias, fp16 3-product.
// ---------------------------------------------------------------------------
#define XW_XH   0
#define XW_XL   34816
#define XW_WTH  69632
#define XW_WTL  87040
#define XW_SMEM 104448

__global__ __launch_bounds__(256, 2) void k_xw(
    const float* __restrict__ x,
    const __half* __restrict__ wt1h, const __half* __restrict__ wt1l,
    const float* __restrict__ bias,
    __half* __restrict__ zh, __half* __restrict__ zl,
    float* __restrict__ uout)
{
    extern __shared__ char smem[];
    const uint32_t sb = smem_u32(smem);
    const int tid = threadIdx.x, wid = tid >> 5, lane = tid & 31;
    const int m0 = blockIdx.x * 128;
    __half* XH  = (__half*)(smem + XW_XH);
    __half* XL  = (__half*)(smem + XW_XL);
    __half* WTH = (__half*)(smem + XW_WTH);
    __half* WTL = (__half*)(smem + XW_WTL);

#pragma unroll
    for (int it = 0; it < 4; it++) {
        int e = tid + 256 * it;
        int n = e >> 4, c = e & 15;
        *(uint4*)&WTH[n * 136 + c * 8] = *(const uint4*)&wt1h[n * 128 + c * 8];
        *(uint4*)&WTL[n * 136 + c * 8] = *(const uint4*)&wt1l[n * 128 + c * 8];
    }
#pragma unroll
    for (int t = 0; t < 16; t++) {
        int e = tid + 256 * t;
        int r = e >> 5, c4 = (e & 31) * 4;
        float4 v = *(const float4*)&x[(size_t)(m0 + r) * FDIM + c4];
        unsigned short hp[4], lp[4];
        fsplit(v.x, hp[0], lp[0]); fsplit(v.y, hp[1], lp[1]);
        fsplit(v.z, hp[2], lp[2]); fsplit(v.w, hp[3], lp[3]);
        *(uint2*)&XH[r * 136 + c4] = *(uint2*)hp;
        *(uint2*)&XL[r * 136 + c4] = *(uint2*)lp;
    }
    __syncthreads();

    float acc[8][4];
#pragma unroll
    for (int i = 0; i < 8; i++)
#pragma unroll
        for (int j = 0; j < 4; j++) acc[i][j] = 0.f;

    const int g8 = lane >> 3, r8 = lane & 7;
    const int a_row = wid * 16 + ((g8 & 1) ? 8 : 0) + r8;
    const uint32_t a_off = (uint32_t)a_row * 272 + ((g8 >= 2) ? 16 : 0);
    const uint32_t ah_base = sb + XW_XH + a_off;
    const uint32_t al_base = sb + XW_XL + a_off;
    const int b_rowoff = ((g8 >> 1) ? 8 : 0) + r8;
    const uint32_t b_off = (uint32_t)b_rowoff * 272 + ((g8 & 1) ? 16 : 0);
    const uint32_t bh_base = sb + XW_WTH + b_off;
    const uint32_t bl_base = sb + XW_WTL + b_off;

#pragma unroll
    for (int ks = 0; ks < 8; ks++) {
        const uint32_t ka = (uint32_t)ks * 32;
        uint32_t ah[4], al[4], bh[16], bl[16];
        ldsm4(ah, ah_base + ka);
        ldsm4(al, al_base + ka);
#pragma unroll
        for (int q = 0; q < 4; q++) {
            ldsm4(bh + 4 * q, bh_base + (uint32_t)q * 16 * 272 + ka);
            ldsm4(bl + 4 * q, bl_base + (uint32_t)q * 16 * 272 + ka);
        }
#pragma unroll
        for (int nt = 0; nt < 8; nt++) {
            mma_f16(acc[nt], ah, bh[nt * 2], bh[nt * 2 + 1]);
            mma_f16(acc[nt], ah, bl[nt * 2], bl[nt * 2 + 1]);
            mma_f16(acc[nt], al, bh[nt * 2], bh[nt * 2 + 1]);
        }
    }
    __syncthreads();

    __half* zts_h = (__half*)smem;              // [32 cols][136 rows]
    __half* zts_l = zts_h + 32 * 136;
    const int g = lane >> 2, t2 = (lane & 3) * 2;
    const int r0l = wid * 16 + g, r1l = r0l + 8;

#pragma unroll
    for (int nt = 0; nt < 4; nt++) {
        int c = nt * 8 + t2;
        unsigned short hh, ll;
        fsplit(acc[nt][0], hh, ll);
        zts_h[c * 136 + r0l] = *(__half*)&hh; zts_l[c * 136 + r0l] = *(__half*)&ll;
        fsplit(acc[nt][1], hh, ll);
        zts_h[(c + 1) * 136 + r0l] = *(__half*)&hh; zts_l[(c + 1) * 136 + r0l] = *(__half*)&ll;
        fsplit(acc[nt][2], hh, ll);
        zts_h[c * 136 + r1l] = *(__half*)&hh; zts_l[c * 136 + r1l] = *(__half*)&ll;
        fsplit(acc[nt][3], hh, ll);
        zts_h[(c + 1) * 136 + r1l] = *(__half*)&hh; zts_l[(c + 1) * 136 + r1l] = *(__half*)&ll;
    }
#pragma unroll
    for (int nt = 4; nt < 8; nt++) {
        int c = (nt - 4) * 8 + t2;
        float2 bv = *(const float2*)&bias[c];
        int gr0 = m0 + r0l, gr1 = m0 + r1l;
        float2 v0 = make_float2(acc[nt][0] + bv.x, acc[nt][1] + bv.y);
        float2 v1 = make_float2(acc[nt][2] + bv.x, acc[nt][3] + bv.y);
        *(float2*)&uout[(size_t)gr0 * HDIM + c] = v0;
        *(float2*)&uout[(size_t)gr1 * HDIM + c] = v1;
    }
    __syncthreads();
    {
        int b_ = m0 >> 9, r0g = m0 & (NNODE - 1);
#pragma unroll
        for (int it = 0; it < 2; it++) {
            int e = tid + 256 * it;
            int col = e >> 4, seg = e & 15;
            size_t gb = ((size_t)(b_ * HDIM + col)) * NNODE + r0g + seg * 8;
            *(uint4*)&zh[gb] = *(uint4*)&zts_h[col * 136 + seg * 8];
            *(uint4*)&zl[gb] = *(uint4*)&zts_l[col * 136 + seg * 8];
        }
    }
}

// ---------------------------------------------------------------------------
// G3/G5 compact (MMA): 128 COMPACT rows; z compact transposed; u full-layout.
// ---------------------------------------------------------------------------
#define GX_AH   0
#define GX_AL   10240
#define GX_WTH  20480
#define GX_WTL  25600
#define GX_RID  30720
#define GX_SMEM 31232

__global__ __launch_bounds__(256) void k_gxw_c(
    const float* __restrict__ hfeat, const float* __restrict__ gate,
    const int* __restrict__ idx, int ksel, int kslog,
    const __half* __restrict__ wth, const __half* __restrict__ wtl,
    const float* __restrict__ bias,
    __half* __restrict__ zh, __half* __restrict__ zl,
    float* __restrict__ uout)
{
    __shared__ __align__(16) char smem[GX_SMEM];
    const uint32_t sb = smem_u32(smem);
    const int tid = threadIdx.x, wid = tid >> 5, lane = tid & 31;
    const int jg = blockIdx.x * 128;
    const int b  = jg >> kslog;
    const int j0 = jg & (ksel - 1);
    __half* AH  = (__half*)(smem + GX_AH);
    __half* AL  = (__half*)(smem + GX_AL);
    __half* WTH = (__half*)(smem + GX_WTH);
    __half* WTL = (__half*)(smem + GX_WTL);
    int* rid = (int*)(smem + GX_RID);

    if (tid < 128) rid[tid] = idx[b * ksel + j0 + tid];
    {
        int n = tid >> 2, c = tid & 3;
        *(uint4*)&WTH[n * 40 + c * 8] = *(const uint4*)&wth[n * 32 + c * 8];
        *(uint4*)&WTL[n * 40 + c * 8] = *(const uint4*)&wtl[n * 32 + c * 8];
    }
    __syncthreads();
#pragma unroll
    for (int t = 0; t < 4; t++) {
        int e = tid + 256 * t;
        int r = e >> 3, c4 = (e & 7) * 4;
        int gr = b * NNODE + rid[r];
        float g = gate[gr];
        float4 v = *(const float4*)&hfeat[(size_t)gr * HDIM + c4];
        v.x *= g; v.y *= g; v.z *= g; v.w *= g;
        unsigned short hp[4], lp[4];
        fsplit(v.x, hp[0], lp[0]); fsplit(v.y, hp[1], lp[1]);
        fsplit(v.z, hp[2], lp[2]); fsplit(v.w, hp[3], lp[3]);
        *(uint2*)&AH[r * 40 + c4] = *(uint2*)hp;
        *(uint2*)&AL[r * 40 + c4] = *(uint2*)lp;
    }
    __syncthreads();

    float acc[8][4];
#pragma unroll
    for (int i = 0; i < 8; i++)
#pragma unroll
        for (int j = 0; j < 4; j++) acc[i][j] = 0.f;

    const int g8 = lane >> 3, r8 = lane & 7;
    const int a_row = wid * 16 + ((g8 & 1) ? 8 : 0) + r8;
    const uint32_t a_off = (uint32_t)a_row * 80 + ((g8 >= 2) ? 16 : 0);
    const uint32_t ahb = sb + GX_AH + a_off;
    const uint32_t alb = sb + GX_AL + a_off;
    const int b_rowoff = ((g8 >> 1) ? 8 : 0) + r8;
    const uint32_t b_off = (uint32_t)b_rowoff * 80 + ((g8 & 1) ? 16 : 0);
    const uint32_t bhb = sb + GX_WTH + b_off;
    const uint32_t blb = sb + GX_WTL + b_off;

#pragma unroll
    for (int ks = 0; ks < 2; ks++) {
        const uint32_t ka = (uint32_t)ks * 32;
        uint32_t ah[4], al[4], bh[16], bl[16];
        ldsm4(ah, ahb + ka);
        ldsm4(al, alb + ka);
#pragma unroll
        for (int q = 0; q < 4; q++) {
            ldsm4(bh + 4 * q, bhb + (uint32_t)q * 16 * 80 + ka);
            ldsm4(bl + 4 * q, blb + (uint32_t)q * 16 * 80 + ka);
        }
#pragma unroll
        for (int nt = 0; nt < 8; nt++) {
            mma_f16(acc[nt], ah, bh[nt * 2], bh[nt * 2 + 1]);
            mma_f16(acc[nt], ah, bl[nt * 2], bl[nt * 2 + 1]);
            mma_f16(acc[nt], al, bh[nt * 2], bh[nt * 2 + 1]);
        }
    }
    __syncthreads();

    __half* zts_h = (__half*)smem;              // [32 cols][136 rows]
    __half* zts_l = zts_h + 32 * 136;
    const int g = lane >> 2, t2 = (lane & 3) * 2;
    const int r0l = wid * 16 + g, r1l = r0l + 8;

#pragma unroll
    for (int nt = 0; nt < 4; nt++) {
        int c = nt * 8 + t2;
        unsigned short hh, ll;
        fsplit(acc[nt][0], hh, ll);
        zts_h[c * 136 + r0l] = *(__half*)&hh; zts_l[c * 136 + r0l] = *(__half*)&ll;
        fsplit(acc[nt][1], hh, ll);
        zts_h[(c + 1) * 136 + r0l] = *(__half*)&hh; zts_l[(c + 1) * 136 + r0l] = *(__half*)&ll;
        fsplit(acc[nt][2], hh, ll);
        zts_h[c * 136 + r1l] = *(__half*)&hh; zts_l[c * 136 + r1l] = *(__half*)&ll;
        fsplit(acc[nt][3], hh, ll);
        zts_h[(c + 1) * 136 + r1l] = *(__half*)&hh; zts_l[(c + 1) * 136 + r1l] = *(__half*)&ll;
    }
#pragma unroll
    for (int nt = 4; nt < 8; nt++) {
        int c = (nt - 4) * 8 + t2;
        float2 bv = *(const float2*)&bias[c];
        int gr0 = b * NNODE + rid[r0l], gr1 = b * NNODE + rid[r1l];
        float2 v0 = make_float2(acc[nt][0] + bv.x, acc[nt][1] + bv.y);
        float2 v1 = make_float2(acc[nt][2] + bv.x, acc[nt][3] + bv.y);
        *(float2*)&uout[(size_t)gr0 * HDIM + c] = v0;
        *(float2*)&uout[(size_t)gr1 * HDIM + c] = v1;
    }
    __syncthreads();
    {
#pragma unroll
        for (int it = 0; it < 2; it++) {
            int e = tid + 256 * it;
            int col = e >> 4, seg = e & 15;
            size_t gb = ((size_t)(b * HDIM + col)) * ksel + j0 + seg * 8;
            *(uint4*)&zh[gb] = *(uint4*)&zts_h[col * 136 + seg * 8];
            *(uint4*)&zl[gb] = *(uint4*)&zts_l[col * 136 + seg * 8];
        }
    }
}

// ---------------------------------------------------------------------------
// fp16 MMA a@z v5: per-chunk cp.async z staging, reg-prefetched a, 2 CTAs/SM.
// ---------------------------------------------------------------------------
#define ASTR     72
#define AZ_ZST   9216
#define AZ_ZL    4608
#define AZ_AH    18432
#define AZ_AL    36864
#define AZ_GIDX  55296
#define AZ_KID   55808
#define AZ_SMEM  57856

__global__ __launch_bounds__(256, 2) void k_aZ_mma(
    const float* __restrict__ a, const __half* __restrict__ zh,
    const __half* __restrict__ zl, const float* __restrict__ u,
    float* __restrict__ out, const int* __restrict__ ridx,
    const int* __restrict__ kidx, int rows_out, int klen, int out_compact)
{
    extern __shared__ char smem[];
    const uint32_t sb = smem_u32(smem);
    const int tid = threadIdx.x, wid = tid >> 5, lane = tid & 31;
    const int b  = blockIdx.y;
    const int m0 = blockIdx.x * 128;
    int* gidx = (int*)(smem + AZ_GIDX);
    int* kid  = (int*)(smem + AZ_KID);

    if (tid < 128)
        gidx[tid] = ridx ? ridx[b * rows_out + m0 + tid] : (m0 + tid);
    if (kidx)
        for (int i = tid; i < klen; i += 256) kid[i] = kidx[b * klen + i];
    __syncthreads();

    const float* ab = a + (size_t)b * NNODE * NNODE;
    const __half* zhb = zh + (size_t)b * HDIM * klen;
    const __half* zlb = zl + (size_t)b * HDIM * klen;
    const int nch = klen >> 6;

    const int zrow = tid >> 3, zc = tid & 7;
    {
        uint32_t dst = sb + zrow * 144 + zc * 16;
        CP16(dst,         zhb + (size_t)zrow * klen + zc * 8);
        CP16(dst + AZ_ZL, zlb + (size_t)zrow * klen + zc * 8);
    }
    CP_COMMIT();

    const int prow = tid >> 4;
    const int pc4  = (tid & 15) * 4;

    float4 pf[8];
#pragma unroll
    for (int t = 0; t < 8; t++) {
        const float* rp = ab + (size_t)gidx[prow + 16 * t] * NNODE;
        if (kidx) {
            pf[t].x = rp[kid[pc4 + 0]]; pf[t].y = rp[kid[pc4 + 1]];
            pf[t].z = rp[kid[pc4 + 2]]; pf[t].w = rp[kid[pc4 + 3]];
        } else {
            pf[t] = *(const float4*)&rp[pc4];
        }
    }
    {
        __half* dh = (__half*)(smem + AZ_AH);
        __half* dl = (__half*)(smem + AZ_AL);
#pragma unroll
        for (int t = 0; t < 8; t++) {
            int row = prow + 16 * t;
            unsigned short hp[4], lp[4];
            fsplit(pf[t].x, hp[0], lp[0]); fsplit(pf[t].y, hp[1], lp[1]);
            fsplit(pf[t].z, hp[2], lp[2]); fsplit(pf[t].w, hp[3], lp[3]);
            *(uint2*)&dh[row * ASTR + pc4] = *(uint2*)hp;
            *(uint2*)&dl[row * ASTR + pc4] = *(uint2*)lp;
        }
    }
    CP_WAIT0();
    __syncthreads();

    float acc[4][4];
#pragma unroll
    for (int i = 0; i < 4; i++)
#pragma unroll
        for (int j = 0; j < 4; j++) acc[i][j] = 0.f;

    const int g8 = lane >> 3, r8 = lane & 7;
    const int a_row = wid * 16 + ((g8 & 1) ? 8 : 0) + r8;
    const uint32_t a_off = (uint32_t)a_row * (ASTR * 2) + ((g8 >= 2) ? 16 : 0);
    const uint32_t ahb = sb + AZ_AH + a_off;
    const uint32_t alb = sb + AZ_AL + a_off;
    const int b_rowoff = ((g8 >> 1) ? 8 : 0) + r8;
    const uint32_t b_colB = (g8 & 1) ? 16 : 0;
    const uint32_t bh0 = sb +         (uint32_t)b_rowoff * 144 + b_colB;
    const uint32_t bh1 = sb +         (uint32_t)(16 + b_rowoff) * 144 + b_colB;
    const uint32_t bl0 = sb + AZ_ZL + (uint32_t)b_rowoff * 144 + b_colB;
    const uint32_t bl1 = sb + AZ_ZL + (uint32_t)(16 + b_rowoff) * 144 + b_colB;

    for (int ch = 0; ch < nch; ch++) {
        const uint32_t sB = (uint32_t)(ch & 1) * AZ_ZST;
        if (ch < nch - 1) {
            const int zk = (ch + 1) * 64;
            const uint32_t sN = (uint32_t)((ch + 1) & 1) * AZ_ZST;
            uint32_t dst = sb + sN + zrow * 144 + zc * 16;
            CP16(dst,         zhb + (size_t)zrow * klen + zk + zc * 8);
            CP16(dst + AZ_ZL, zlb + (size_t)zrow * klen + zk + zc * 8);
            CP_COMMIT();
            const int k0 = (ch + 1) * 64;
#pragma unroll
            for (int t = 0; t < 8; t++) {
                const float* rp = ab + (size_t)gidx[prow + 16 * t] * NNODE;
                if (kidx) {
                    pf[t].x = rp[kid[k0 + pc4 + 0]];
                    pf[t].y = rp[kid[k0 + pc4 + 1]];
                    pf[t].z = rp[kid[k0 + pc4 + 2]];
                    pf[t].w = rp[kid[k0 + pc4 + 3]];
                } else {
                    pf[t] = *(const float4*)&rp[k0 + pc4];
                }
            }
        }

#pragma unroll
        for (int ks = 0; ks < 4; ks++) {
            const uint32_t ka = (uint32_t)ks * 32;
            uint32_t ah[4], al[4], bh[8], bl[8];
            ldsm4(ah, ahb + ka);
            ldsm4(al, alb + ka);
            ldsm4(bh,     bh0 + sB + ka);
            ldsm4(bh + 4, bh1 + sB + ka);
            ldsm4(bl,     bl0 + sB + ka);
            ldsm4(bl + 4, bl1 + sB + ka);
#pragma unroll
            for (int nt = 0; nt < 4; nt++) {
                mma_f16(acc[nt], ah, bh[nt * 2], bh[nt * 2 + 1]);
                mma_f16(acc[nt], ah, bl[nt * 2], bl[nt * 2 + 1]);
                mma_f16(acc[nt], al, bh[nt * 2], bh[nt * 2 + 1]);
            }
        }

        if (ch < nch - 1) {
            __syncthreads();
            __half* dh = (__half*)(smem + AZ_AH);
            __half* dl = (__half*)(smem + AZ_AL);
#pragma unroll
            for (int t = 0; t < 8; t++) {
                int row = prow + 16 * t;
                unsigned short hp[4], lp[4];
                fsplit(pf[t].x, hp[0], lp[0]); fsplit(pf[t].y, hp[1], lp[1]);
                fsplit(pf[t].z, hp[2], lp[2]); fsplit(pf[t].w, hp[3], lp[3]);
                *(uint2*)&dh[row * ASTR + pc4] = *(uint2*)hp;
                *(uint2*)&dl[row * ASTR + pc4] = *(uint2*)lp;
            }
            CP_WAIT0();
            __syncthreads();
        }
    }

    const int g  = lane >> 2, t2 = (lane & 3) * 2;
    const int lr0 = wid * 16 + g, lr1 = lr0 + 8;
    const int gm0 = gidx[lr0], gm1 = gidx[lr1];
    const float* u0 = &u[((size_t)b * NNODE + gm0) * HDIM];
    const float* u1 = &u[((size_t)b * NNODE + gm1) * HDIM];
    float* o0 = out + (out_compact
               ? ((size_t)b * rows_out + m0 + lr0) * HDIM
               : ((size_t)b * NNODE + gm0) * HDIM);
    float* o1 = out + (out_compact
               ? ((size_t)b * rows_out + m0 + lr1) * HDIM
               : ((size_t)b * NNODE + gm1) * HDIM);
#pragma unroll
    for (int nt = 0; nt < 4; nt++) {
        int c = nt * 8 + t2;
        float2 uv0 = *(const float2*)&u0[c];
        float2 uv1 = *(const float2*)&u1[c];
        float2 r0, r1;
        r0.x = fmaxf(acc[nt][0] + uv0.x, 0.f);
        r0.y = fmaxf(acc[nt][1] + uv0.y, 0.f);
        r1.x = fmaxf(acc[nt][2] + uv1.x, 0.f);
        r1.y = fmaxf(acc[nt][3] + uv1.y, 0.f);
        *(float2*)&o0[c] = r0;
        *(float2*)&o1[c] = r1;
    }
}

// ---------------------------------------------------------------------------
// TopK v2: exact top-k via 32-pass MSB radix select on order-preserving
// uint keys + index-ordered tie fill. Identical set to jax.lax.top_k.
// ---------------------------------------------------------------------------
__global__ __launch_bounds__(256) void k_topk(
    const float* __restrict__ hfeat, const float* __restrict__ p,
    const float* __restrict__ prevgate, float* __restrict__ gate_out,
    int* __restrict__ idx_out, int k)
{
    __shared__ float ysh[NNODE];
    __shared__ float pn[HDIM];
    __shared__ int wcnt[16], woff[16];
    __shared__ int scnt;
    const int tid = threadIdx.x;
    const int b   = blockIdx.x;
    const int lane = tid & 31, w = tid >> 5;

    if (tid == 0) {
        float s = 0.f;
        for (int h = 0; h < HDIM; h++) s += p[h] * p[h];
        s = rsqrtf(s);
        for (int h = 0; h < HDIM; h++) pn[h] = p[h] * s;
    }
    __syncthreads();

    for (int r = w; r < NNODE; r += 8) {
        float v = hfeat[((size_t)b * NNODE + r) * HDIM + lane] * pn[lane];
#pragma unroll
        for (int s = 16; s > 0; s >>= 1) v += __shfl_xor_sync(0xffffffffu, v, s);
        if (lane == 0) {
            bool valid = (prevgate == nullptr) ||
                         (prevgate[(size_t)b * NNODE + r] > 0.f);
            ysh[r] = valid ? v : -1e30f;
        }
    }
    __syncthreads();

    const int r0 = tid, r1 = tid + 256;
    float y0 = ysh[r0], y1 = ysh[r1];
    uint32_t u0b = __float_as_uint(y0), u1b = __float_as_uint(y1);
    uint32_t key0 = u0b ^ ((u0b >> 31) ? 0xFFFFFFFFu : 0x80000000u);
    uint32_t key1 = u1b ^ ((u1b >> 31) ? 0xFFFFFFFFu : 0x80000000u);

    // ---- radix select: T = key of k-th largest ----
    uint32_t prefix = 0;
    int remaining = k;
#pragma unroll
    for (int bp = 31; bp >= 0; bp--) {
        uint32_t cand = prefix | (1u << bp);
        int p0 = ((key0 >> bp) == (cand >> bp));
        int p1 = ((key1 >> bp) == (cand >> bp));
        uint32_t b0 = __ballot_sync(0xffffffffu, p0);
        uint32_t b1 = __ballot_sync(0xffffffffu, p1);
        if (lane == 0) wcnt[w] = __popc(b0) + __popc(b1);
        __syncthreads();
        if (tid < 8) {
            int v = wcnt[tid];
#pragma unroll
            for (int s = 1; s < 8; s <<= 1)
                v += __shfl_xor_sync(0x000000ffu, v, s);
            if (tid == 0) scnt = v;
        }
        __syncthreads();
        int c = scnt;
        if (c >= remaining) prefix = cand;
        else remaining -= c;
    }
    const uint32_t T = prefix;

    // ---- selection: key>T always; ties ==T filled in index order ----
    int gt0 = key0 > T, gt1 = key1 > T;
    int tie0 = key0 == T, tie1 = key1 == T;
    uint32_t gb0 = __ballot_sync(0xffffffffu, gt0);
    uint32_t gb1 = __ballot_sync(0xffffffffu, gt1);
    uint32_t tb0 = __ballot_sync(0xffffffffu, tie0);
    uint32_t tb1 = __ballot_sync(0xffffffffu, tie1);
    if (lane == 0) {
        scnt = 0;   // reset via race-free: single write below instead
    }
    __syncthreads();
    if (lane == 0) wcnt[w] = __popc(gb0) + __popc(gb1);
    __syncthreads();
    if (tid < 8) {
        int v = wcnt[tid];
#pragma unroll
        for (int s = 1; s < 8; s <<= 1)
            v += __shfl_xor_sync(0x000000ffu, v, s);
        if (tid == 0) scnt = v;
    }
    __syncthreads();
    const int cnt_gt = scnt;
    const int quota = k - cnt_gt;
    __syncthreads();
    // ordered tie prefix (indices 0..255 by warps 0..7, 256..511 by 8..15)
    if (lane == 0) { wcnt[w] = __popc(tb0); wcnt[8 + w] = __popc(tb1); }
    __syncthreads();
    if (tid < 16) {
        int v = wcnt[tid];
        int x = v;
#pragma unroll
        for (int s = 1; s < 16; s <<= 1) {
            int t = __shfl_up_sync(0x0000ffffu, x, s);
            if (tid >= s) x += t;
        }
        woff[tid] = x - v;
    }
    __syncthreads();
    uint32_t lmask = (1u << lane) - 1u;
    int tpos0 = woff[w]     + __popc(tb0 & lmask);
    int tpos1 = woff[8 + w] + __popc(tb1 & lmask);
    int sel0 = gt0 || (tie0 && tpos0 < quota);
    int sel1 = gt1 || (tie1 && tpos1 < quota);

    gate_out[(size_t)b * NNODE + r0] = sel0 ? (1.f / (1.f + expf(-y0))) : 0.f;
    gate_out[(size_t)b * NNODE + r1] = sel1 ? (1.f / (1.f + expf(-y1))) : 0.f;

    // ---- index compaction (deterministic ascending) ----
    uint32_t m0 = __ballot_sync(0xffffffffu, sel0);
    uint32_t m1 = __ballot_sync(0xffffffffu, sel1);
    __syncthreads();
    if (lane == 0) { wcnt[w] = __popc(m0); wcnt[8 + w] = __popc(m1); }
    __syncthreads();
    if (tid < 16) {
        int v = wcnt[tid];
        int x = v;
#pragma unroll
        for (int s = 1; s < 16; s <<= 1) {
            int t = __shfl_up_sync(0x0000ffffu, x, s);
            if (tid >= s) x += t;
        }
        woff[tid] = x - v;
    }
    __syncthreads();
    if (sel0) idx_out[b * k + woff[w]     + __popc(m0 & lmask)] = r0;
    if (sel1) idx_out[b * k + woff[8 + w] + __popc(m1 & lmask)] = r1;
}

// ---------------------------------------------------------------------------
// Final: mean over 128 nodes -> dense [32,16] + bias -> softmax(16).
// ---------------------------------------------------------------------------
__global__ __launch_bounds__(128) void k_final(
    const float* __restrict__ h3, const float* __restrict__ wd,
    const float* __restrict__ bd, float* __restrict__ out)
{
    __shared__ float ps[4][HDIM];
    __shared__ float pooled[HDIM];
    __shared__ float logits[CDIM];
    const int tid = threadIdx.x;
    const int b   = blockIdx.x;
    const int c = tid & 31, seg = tid >> 5;

    float s = 0.f;
    for (int i = seg * 32; i < seg * 32 + 32; i++)
        s += h3[((size_t)b * KSEL2 + i) * HDIM + c];
    ps[seg][c] = s;
    __syncthreads();
    if (tid < HDIM)
        pooled[tid] = (ps[0][tid] + ps[1][tid] + ps[2][tid] + ps[3][tid]) *
                      (1.f / (float)KSEL2);
    __syncthreads();
    if (tid < CDIM) {
        float l = bd[tid];
        for (int h = 0; h < HDIM; h++) l += pooled[h] * wd[h * CDIM + tid];
        logits[tid] = l;
    }
    __syncthreads();
    if (tid < CDIM) {
        float mx = -1e30f;
        for (int j = 0; j < CDIM; j++) mx = fmaxf(mx, logits[j]);
        float den = 0.f;
        for (int j = 0; j < CDIM; j++) den += expf(logits[j] - mx);
        out[b * CDIM + tid] = expf(logits[tid] - mx) / den;
    }
}

// ---------------------------------------------------------------------------
extern "C" void kernel_launch(void* const* d_in, const int* in_sizes, int n_in,
                              void* d_out, int out_size)
{
    (void)in_sizes; (void)n_in; (void)out_size;
    const float* x    = (const float*)d_in[0];
    const float* a    = (const float*)d_in[1];
    const float* w1_1 = (const float*)d_in[2];
    const float* w2_1 = (const float*)d_in[3];
    const float* b1   = (const float*)d_in[4];
    const float* w1_2 = (const float*)d_in[5];
    const float* w2_2 = (const float*)d_in[6];
    const float* b2   = (const float*)d_in[7];
    const float* w1_3 = (const float*)d_in[8];
    const float* w2_3 = (const float*)d_in[9];
    const float* b3   = (const float*)d_in[10];
    const float* pp   = (const float*)d_in[11];
    const float* wd   = (const float*)d_in[12];
    const float* bd   = (const float*)d_in[13];
    float* out = (float*)d_out;

    __half *zh, *zl, *wt1h, *wt1l, *wt2h, *wt2l, *wt3h, *wt3l;
    float *u1, *u2, *u3, *h1, *h2, *h3, *gate1, *gate2;
    int *idx1, *idx2;
    cudaGetSymbolAddress((void**)&zh, g_zh);
    cudaGetSymbolAddress((void**)&zl, g_zl);
    cudaGetSymbolAddress((void**)&wt1h, g_wt1h);
    cudaGetSymbolAddress((void**)&wt1l, g_wt1l);
    cudaGetSymbolAddress((void**)&wt2h, g_wt2h);
    cudaGetSymbolAddress((void**)&wt2l, g_wt2l);
    cudaGetSymbolAddress((void**)&wt3h, g_wt3h);
    cudaGetSymbolAddress((void**)&wt3l, g_wt3l);
    cudaGetSymbolAddress((void**)&u1, g_u1);
    cudaGetSymbolAddress((void**)&u2, g_u2);
    cudaGetSymbolAddress((void**)&u3, g_u3);
    cudaGetSymbolAddress((void**)&h1, g_h1);
    cudaGetSymbolAddress((void**)&h2, g_h2);
    cudaGetSymbolAddress((void**)&h3, g_h3);
    cudaGetSymbolAddress((void**)&gate1, g_gate1);
    cudaGetSymbolAddress((void**)&gate2, g_gate2);
    cudaGetSymbolAddress((void**)&idx1, g_idx1);
    cudaGetSymbolAddress((void**)&idx2, g_idx2);

    cudaFuncSetAttribute(k_aZ_mma, cudaFuncAttributeMaxDynamicSharedMemorySize,
                         AZ_SMEM);
    cudaFuncSetAttribute(k_xw, cudaFuncAttributeMaxDynamicSharedMemorySize,
                         XW_SMEM);

    // one-shot weight split (all 3 layers)
    k_wprep<<<48, 256>>>(w1_1, w2_1, w1_2, w2_2, w1_3, w2_3,
                         wt1h, wt1l, wt2h, wt2l, wt3h, wt3l);

    // conv1 (full K=512)
    k_xw<<<(BATCH * NNODE) / 128, 256, XW_SMEM>>>(x, wt1h, wt1l, b1, zh, zl, u1);
    k_aZ_mma<<<dim3(NNODE / 128, BATCH), 256, AZ_SMEM>>>(
        a, zh, zl, u1, h1, nullptr, nullptr, NNODE, 512, 0);
    // pool1
    k_topk<<<BATCH, 256>>>(h1, pp, nullptr, gate1, idx1, KSEL1);
    // conv2 (compact rows + compact K = idx1)
    k_gxw_c<<<(BATCH * KSEL1) / 128, 256>>>(h1, gate1, idx1, KSEL1, 8,
                                            wt2h, wt2l, b2, zh, zl, u2);
    k_aZ_mma<<<dim3(KSEL1 / 128, BATCH), 256, AZ_SMEM>>>(
        a, zh, zl, u2, h2, idx1, idx1, KSEL1, KSEL1, 0);
    // pool2
    k_topk<<<BATCH, 256>>>(h2, pp, gate1, gate2, idx2, KSEL2);
    // conv3 (compact rows + compact K = idx2)
    k_gxw_c<<<(BATCH * KSEL2) / 128, 256>>>(h2, gate2, idx2, KSEL2, 7,
                                            wt3h, wt3l, b3, zh, zl, u3);
    k_aZ_mma<<<dim3(KSEL2 / 128, BATCH), 256, AZ_SMEM>>>(
        a, zh, zl, u3, h3, idx2, idx2, KSEL2, KSEL2, 1);
    // global mean pool + dense + softmax
    k_final<<<BATCH, 128>>>(h3, wd, bd, out);
}